// round 1
// baseline (speedup 1.0000x reference)
#include <cuda_runtime.h>
#include <math.h>

#define B_TOT 16384
#define TX 30
#define TY 10
#define NA 32
#define NS 64
#define HV 128
#define MV 64
#define GE 128   // 4*NA
#define GP 256   // 4*NS

// scratch: concat bidirectional hidden states a[B][TX][64]
__device__ float g_a[(size_t)B_TOT * TX * (2 * NA)];

__device__ __forceinline__ float fsigmoid(float x) {
    return __fdividef(1.0f, 1.0f + __expf(-x));
}
__device__ __forceinline__ float ftanh(float x) {
    x = fminf(15.0f, fmaxf(-15.0f, x));
    float e = __expf(2.0f * x);
    return __fdividef(e - 1.0f, e + 1.0f);
}

// ============================================================================
// Encoder: one block = 32 batch elems, one direction. Persistent over TX steps.
// smem: W_ihT[128][128], W_hhT[32][128], b[128], xs[32][128], hs[32][32], cs[32][32]
// GEMM: 256 threads, each computes a 4-elem x 4-gate register tile.
// ============================================================================
#define EBE 32
#define ENC_THREADS 256
#define ENC_SMEM_FLOATS (HV*GE + NA*GE + GE + EBE*HV + EBE*NA + EBE*NA)

__global__ __launch_bounds__(ENC_THREADS, 2)
void encoder_kernel(const float* __restrict__ X,
                    const float* __restrict__ W_ih_f, const float* __restrict__ W_hh_f,
                    const float* __restrict__ b_f,
                    const float* __restrict__ W_ih_r, const float* __restrict__ W_hh_r,
                    const float* __restrict__ b_r)
{
    const int dir = blockIdx.y;
    const int b0  = blockIdx.x * EBE;
    const float* W_ih = dir ? W_ih_r : W_ih_f;
    const float* W_hh = dir ? W_hh_r : W_hh_f;
    const float* bias = dir ? b_r    : b_f;

    extern __shared__ float sm[];
    float* Wx = sm;                 // [HV][GE]  Wx[k*GE+g] = W_ih[g][k]
    float* Wh = Wx + HV * GE;       // [NA][GE]
    float* bs = Wh + NA * GE;       // [GE]
    float* xs = bs + GE;            // [EBE][HV]  (aliased as zs[EBE][GE] after GEMM)
    float* hs = xs + EBE * HV;      // [EBE][NA]
    float* cs = hs + EBE * NA;      // [EBE][NA]
    float* zs = xs;                 // alias (same size: EBE*HV == EBE*GE)

    const int tid = threadIdx.x;

    // stage weights (coalesced global reads; one-time transposed smem stores)
    for (int i = tid; i < GE * HV; i += ENC_THREADS) {
        int g = i / HV, k = i % HV;
        Wx[k * GE + g] = W_ih[i];
    }
    for (int i = tid; i < GE * NA; i += ENC_THREADS) {
        int g = i / NA, k = i % NA;
        Wh[k * GE + g] = W_hh[i];
    }
    for (int i = tid; i < GE; i += ENC_THREADS) bs[i] = bias[i];
    for (int i = tid; i < EBE * NA; i += ENC_THREADS) { hs[i] = 0.0f; cs[i] = 0.0f; }
    __syncthreads();

    const int gg = tid & 31;        // gate group: g0 = 4*gg (lane within warp)
    const int ee = tid >> 5;        // elem group: e0 = 4*ee (warp id)
    const int g0 = gg * 4;
    const int e0 = ee * 4;

    for (int t = 0; t < TX; t++) {
        const int tt = dir ? (TX - 1 - t) : t;

        // load x_t tile (coalesced float4)
        for (int i = tid; i < EBE * (HV / 4); i += ENC_THREADS) {
            int e = i >> 5, k4 = i & 31;   // HV/4 = 32
            ((float4*)xs)[i] = *(const float4*)(X + ((size_t)(b0 + e) * TX + tt) * HV + k4 * 4);
        }
        __syncthreads();

        float acc[4][4];
        #pragma unroll
        for (int i = 0; i < 4; i++)
            #pragma unroll
            for (int j = 0; j < 4; j++) acc[i][j] = 0.0f;

        // z += x @ W_ihT
        #pragma unroll 4
        for (int k = 0; k < HV; k++) {
            float4 w = *(const float4*)&Wx[k * GE + g0];
            #pragma unroll
            for (int i = 0; i < 4; i++) {
                float xv = xs[(e0 + i) * HV + k];
                acc[i][0] += xv * w.x; acc[i][1] += xv * w.y;
                acc[i][2] += xv * w.z; acc[i][3] += xv * w.w;
            }
        }
        // z += h @ W_hhT
        #pragma unroll 4
        for (int k = 0; k < NA; k++) {
            float4 w = *(const float4*)&Wh[k * GE + g0];
            #pragma unroll
            for (int i = 0; i < 4; i++) {
                float hv = hs[(e0 + i) * NA + k];
                acc[i][0] += hv * w.x; acc[i][1] += hv * w.y;
                acc[i][2] += hv * w.z; acc[i][3] += hv * w.w;
            }
        }
        __syncthreads();  // xs reads done; zs (alias) can be written

        float4 bv = *(const float4*)&bs[g0];
        #pragma unroll
        for (int i = 0; i < 4; i++) {
            float4 z4;
            z4.x = acc[i][0] + bv.x; z4.y = acc[i][1] + bv.y;
            z4.z = acc[i][2] + bv.z; z4.w = acc[i][3] + bv.w;
            *(float4*)&zs[(e0 + i) * GE + g0] = z4;
        }
        __syncthreads();

        // LSTM cell (gate order i,f,g,o)
        for (int idx = tid; idx < EBE * NA; idx += ENC_THREADS) {
            int e = idx >> 5, n = idx & 31;   // NA = 32
            float zi = zs[e * GE + n];
            float zf = zs[e * GE + NA + n];
            float zg = zs[e * GE + 2 * NA + n];
            float zo = zs[e * GE + 3 * NA + n];
            float c = fsigmoid(zf) * cs[idx] + fsigmoid(zi) * ftanh(zg);
            float h = fsigmoid(zo) * ftanh(c);
            cs[idx] = c; hs[idx] = h;
            g_a[((size_t)(b0 + e) * TX + tt) * (2 * NA) + dir * NA + n] = h;
        }
        __syncthreads();
    }
}

// ============================================================================
// Decoder: one block = 8 batch elems, persistent over TY steps.
// a-tile + Ea + all LSTM/attention weights resident in smem (1 block/SM).
// Wo cached per-thread in registers (k-split by 4, smem reduce via zsd buffer).
// ============================================================================
#define DBE 8
#define DEC_THREADS 256
#define SA_STRIDE 68   // padded row (64 data + 4 pad) to break bank conflicts

#define NF_WP   (HV * GP)            // 32768
#define NF_SA   (DBE * TX * SA_STRIDE)   // 16320
#define NF_EA   (DBE * TX * 10)      // 2400
#define DEC_SMEM_FLOATS (NF_WP + NF_SA + NF_EA + 640 + 640 + 16 + 16 + GP + MV \
                         + DBE*NS + DBE*NS + DBE*HV + DBE*GP + DBE*32 + DBE*10)

__global__ __launch_bounds__(DEC_THREADS, 1)
void decoder_kernel(const float* __restrict__ W1, const float* __restrict__ b1,
                    const float* __restrict__ W2, const float* __restrict__ b2,
                    const float* __restrict__ W_ih_p, const float* __restrict__ W_hh_p,
                    const float* __restrict__ b_p,
                    const float* __restrict__ Wo, const float* __restrict__ bo,
                    float* __restrict__ out)
{
    const int b0 = blockIdx.x * DBE;
    const int tid = threadIdx.x;

    extern __shared__ float sm[];
    float* Wp   = sm;                  // [128][256]: Wp[k*256+g] = [W_ih_p | W_hh_p]^T
    float* sa   = Wp + NF_WP;          // [8][30][SA_STRIDE]
    float* ea   = sa + NF_SA;          // [8][30][10]
    float* W1a  = ea + NF_EA;          // [10][64]
    float* W1s  = W1a + 640;           // [10][64]
    float* b1s  = W1s + 640;           // [16]
    float* W2s  = b1s + 16;            // [16]
    float* bps  = W2s + 16;            // [256]
    float* bos  = bps + GP;            // [64]
    float* ss   = bos + MV;            // [8][64]  s state
    float* cc   = ss + DBE * NS;       // [8][64]  c state
    float* ins  = cc + DBE * NS;       // [8][128] (ctx | s)
    float* zsd  = ins + DBE * HV;      // [8][256] gates (reused as out-reduce buffer)
    float* alph = zsd + DBE * GP;      // [8][32]
    float* esm  = alph + DBE * 32;     // [8][10]

    // ---- stage weights ----
    for (int i = tid; i < NS * GP; i += DEC_THREADS) {  // i = g*64 + k
        int g = i / NS, k = i % NS;
        Wp[k * GP + g]        = W_ih_p[i];
        Wp[(k + NS) * GP + g] = W_hh_p[i];
    }
    for (int i = tid; i < 640; i += DEC_THREADS) {
        int j = i / 64, d = i % 64;
        W1a[i] = W1[j * 128 + d];
        W1s[i] = W1[j * 128 + 64 + d];
    }
    if (tid < 10) { b1s[tid] = b1[tid]; W2s[tid] = W2[tid]; }
    for (int i = tid; i < GP; i += DEC_THREADS) bps[i] = b_p[i];
    if (tid < MV) bos[tid] = bo[tid];
    for (int i = tid; i < DBE * NS; i += DEC_THREADS) { ss[i] = 0.0f; cc[i] = 0.0f; }
    const float b2v = b2[0];

    // per-thread Wo register cache: thread owns (m = tid&63, k-chunk kh = tid>>6)
    const int wm = tid & 63, wkh = tid >> 6;
    float wreg[16];
    #pragma unroll
    for (int kk = 0; kk < 16; kk++) wreg[kk] = Wo[wm * 64 + wkh * 16 + kk];

    // ---- load a tile (coalesced float4 from g_a) ----
    for (int i = tid; i < DBE * TX * (NS / 4); i += DEC_THREADS) {
        int e = i / (TX * 16);
        int r = i % (TX * 16);
        int tx = r / 16, d4 = r % 16;
        float4 v = *(const float4*)(g_a + ((size_t)(b0 + e) * TX + tx) * (2 * NA) + d4 * 4);
        *(float4*)&sa[(e * TX + tx) * SA_STRIDE + d4 * 4] = v;
    }
    __syncthreads();

    // ---- precompute Ea[e][tx][j] = sum_d a * W1a[j][d]  (step-invariant) ----
    if (tid < DBE * TX) {
        int e = tid / TX, tx = tid % TX;
        const float* arow = &sa[(e * TX + tx) * SA_STRIDE];
        float acc[10];
        #pragma unroll
        for (int j = 0; j < 10; j++) acc[j] = 0.0f;
        for (int d = 0; d < 64; d++) {
            float av = arow[d];
            #pragma unroll
            for (int j = 0; j < 10; j++) acc[j] += av * W1a[j * 64 + d];
        }
        #pragma unroll
        for (int j = 0; j < 10; j++) ea[(e * TX + tx) * 10 + j] = acc[j];
    }
    __syncthreads();

    // ---- decoder steps ----
    for (int t = 0; t < TY; t++) {
        // A: es[e][j] = b1[j] + s @ W1s[j]
        if (tid < DBE * 10) {
            int e = tid / 10, j = tid % 10;
            float acc = b1s[j];
            for (int k = 0; k < NS; k++) acc += ss[e * NS + k] * W1s[j * 64 + k];
            esm[e * 10 + j] = acc;
        }
        __syncthreads();

        // B: en[e][tx] = relu(b2 + sum_j tanh(ea+es)*W2[j])
        if (tid < DBE * TX) {
            int e = tid / TX, tx = tid % TX;
            float acc = b2v;
            #pragma unroll
            for (int j = 0; j < 10; j++)
                acc += ftanh(ea[(e * TX + tx) * 10 + j] + esm[e * 10 + j]) * W2s[j];
            alph[e * 32 + tx] = fmaxf(acc, 0.0f);
        }
        __syncthreads();

        // C: softmax over tx per elem
        if (tid < DBE) {
            int e = tid;
            float mx = -1e30f;
            for (int tx = 0; tx < TX; tx++) mx = fmaxf(mx, alph[e * 32 + tx]);
            float sum = 0.0f;
            for (int tx = 0; tx < TX; tx++) {
                float v = __expf(alph[e * 32 + tx] - mx);
                alph[e * 32 + tx] = v; sum += v;
            }
            float inv = __fdividef(1.0f, sum);
            for (int tx = 0; tx < TX; tx++) alph[e * 32 + tx] *= inv;
        }
        __syncthreads();

        // D: context -> ins[e][0:64], copy s -> ins[e][64:128]
        for (int i = tid; i < DBE * NS; i += DEC_THREADS) {
            int e = i / NS, d = i % NS;
            float acc = 0.0f;
            #pragma unroll 5
            for (int tx = 0; tx < TX; tx++)
                acc += alph[e * 32 + tx] * sa[(e * TX + tx) * SA_STRIDE + d];
            ins[e * HV + d]      = acc;
            ins[e * HV + NS + d] = ss[i];
        }
        __syncthreads();

        // E: gates z[e][g] = bp[g] + ins[e] @ Wp[:,g]  (2 gates x 4 elems per thread)
        {
            const int gl = (tid & 127) * 2;
            const int eb = (tid >> 7) * 4;
            float acc0[4], acc1[4];
            #pragma unroll
            for (int i = 0; i < 4; i++) { acc0[i] = bps[gl]; acc1[i] = bps[gl + 1]; }
            #pragma unroll 4
            for (int k = 0; k < HV; k++) {
                float2 w = *(const float2*)&Wp[k * GP + gl];
                #pragma unroll
                for (int i = 0; i < 4; i++) {
                    float xv = ins[(eb + i) * HV + k];
                    acc0[i] += xv * w.x; acc1[i] += xv * w.y;
                }
            }
            #pragma unroll
            for (int i = 0; i < 4; i++) {
                float2 z2; z2.x = acc0[i]; z2.y = acc1[i];
                *(float2*)&zsd[(eb + i) * GP + gl] = z2;
            }
        }
        __syncthreads();

        // F: LSTM cell (i,f,g,o)
        for (int i = tid; i < DBE * NS; i += DEC_THREADS) {
            int e = i / NS, n = i % NS;
            float zi = zsd[e * GP + n];
            float zf = zsd[e * GP + NS + n];
            float zg = zsd[e * GP + 2 * NS + n];
            float zo = zsd[e * GP + 3 * NS + n];
            float c = fsigmoid(zf) * cc[i] + fsigmoid(zi) * ftanh(zg);
            float h = fsigmoid(zo) * ftanh(c);
            cc[i] = c; ss[i] = h;
        }
        __syncthreads();

        // G: out[e][m] = bo[m] + s @ Wo[m]  via k-split partials in registers
        {
            #pragma unroll
            for (int e = 0; e < DBE; e++) {
                float p = 0.0f;
                #pragma unroll
                for (int kk = 0; kk < 16; kk++)
                    p += ss[e * NS + wkh * 16 + kk] * wreg[kk];
                zsd[(wkh * DBE + e) * 64 + wm] = p;
            }
        }
        __syncthreads();
        for (int i = tid; i < DBE * MV; i += DEC_THREADS) {
            int e = i / MV, m = i % MV;
            float o = bos[m]
                    + zsd[(0 * DBE + e) * 64 + m] + zsd[(1 * DBE + e) * 64 + m]
                    + zsd[(2 * DBE + e) * 64 + m] + zsd[(3 * DBE + e) * 64 + m];
            out[((size_t)(b0 + e) * TY + t) * MV + m] = o;
        }
        __syncthreads();
    }
}

// ============================================================================
extern "C" void kernel_launch(void* const* d_in, const int* in_sizes, int n_in,
                              void* d_out, int out_size)
{
    const float* X      = (const float*)d_in[0];
    const float* W_ih_f = (const float*)d_in[1];
    const float* W_hh_f = (const float*)d_in[2];
    const float* b_f    = (const float*)d_in[3];
    const float* W_ih_r = (const float*)d_in[4];
    const float* W_hh_r = (const float*)d_in[5];
    const float* b_r    = (const float*)d_in[6];
    const float* W1     = (const float*)d_in[7];
    const float* b1     = (const float*)d_in[8];
    const float* W2     = (const float*)d_in[9];
    const float* b2     = (const float*)d_in[10];
    const float* W_ih_p = (const float*)d_in[11];
    const float* W_hh_p = (const float*)d_in[12];
    const float* b_p    = (const float*)d_in[13];
    const float* Wo     = (const float*)d_in[14];
    const float* bo     = (const float*)d_in[15];
    float* out = (float*)d_out;

    const int enc_smem = ENC_SMEM_FLOATS * sizeof(float);
    const int dec_smem = DEC_SMEM_FLOATS * sizeof(float);
    cudaFuncSetAttribute(encoder_kernel, cudaFuncAttributeMaxDynamicSharedMemorySize, enc_smem);
    cudaFuncSetAttribute(decoder_kernel, cudaFuncAttributeMaxDynamicSharedMemorySize, dec_smem);

    dim3 eg(B_TOT / EBE, 2);
    encoder_kernel<<<eg, ENC_THREADS, enc_smem>>>(X, W_ih_f, W_hh_f, b_f, W_ih_r, W_hh_r, b_r);
    decoder_kernel<<<B_TOT / DBE, DEC_THREADS, dec_smem>>>(W1, b1, W2, b2,
                                                           W_ih_p, W_hh_p, b_p, Wo, bo, out);
}

// round 2
// speedup vs baseline: 1.2015x; 1.2015x over previous
#include <cuda_runtime.h>
#include <math.h>

#define B_TOT 16384
#define TX 30
#define TY 10
#define NA 32
#define NS 64
#define HV 128
#define MV 64
#define GE 128   // 4*NA
#define GP 256   // 4*NS

// scratch buffers
__device__ __align__(16) float g_a [(size_t)B_TOT * TX * (2 * NA)];     // 126 MB
__device__ __align__(16) float g_zx[(size_t)B_TOT * TX * 256];          // 504 MB

__device__ __forceinline__ float fsigmoid(float x) {
    return __fdividef(1.0f, 1.0f + __expf(-x));
}
__device__ __forceinline__ float ftanh(float x) {
    x = fminf(15.0f, fmaxf(-15.0f, x));
    float e = __expf(2.0f * x);
    return __fdividef(e - 1.0f, e + 1.0f);
}

__device__ __forceinline__ unsigned cvt_tf32(float x) {
    unsigned u;
    asm("cvt.rna.tf32.f32 %0, %1;" : "=r"(u) : "f"(x));
    return u;
}
__device__ __forceinline__ void mma_tf32(float* d, const unsigned* a, unsigned b0, unsigned b1) {
    asm("mma.sync.aligned.m16n8k8.row.col.f32.tf32.tf32.f32 "
        "{%0,%1,%2,%3}, {%4,%5,%6,%7}, {%8,%9}, {%0,%1,%2,%3};"
        : "+f"(d[0]), "+f"(d[1]), "+f"(d[2]), "+f"(d[3])
        : "r"(a[0]), "r"(a[1]), "r"(a[2]), "r"(a[3]), "r"(b0), "r"(b1));
}

// ============================================================================
// Kernel 1: Zx = X @ Wcat^T  via tf32 mma.sync.
// Block tile 128(M) x 128(N), K=128 resident. Grid: (M/128, 2 dirs).
// smem layout: per 8-wide k-chunk, k stored at pos (k%4)*2 + (k/4) so that
// the (tig, tig+4) fragment pair is one LDS.64.
// ============================================================================
#define XS_STRIDE 136
#define K1_SMEM (2 * 128 * XS_STRIDE * 4)

__global__ __launch_bounds__(256, 1)
void ingemm_kernel(const float* __restrict__ X,
                   const float* __restrict__ W_ih_f,
                   const float* __restrict__ W_ih_r)
{
    const int mbase = blockIdx.x * 128;
    const int nsel  = blockIdx.y;
    const float* W = nsel ? W_ih_r : W_ih_f;

    extern __shared__ unsigned smu[];
    unsigned* Xs = smu;
    unsigned* Ws = smu + 128 * XS_STRIDE;

    const int tid = threadIdx.x;

    for (int i = tid; i < 128 * 32; i += 256) {
        int row = i >> 5, q = i & 31;                  // q-th float4 (k=4q..4q+3)
        float4 v = *(const float4*)(X + (size_t)(mbase + row) * HV + q * 4);
        int c = q >> 1, hi = q & 1;
        unsigned* dst = &Xs[row * XS_STRIDE + c * 8 + hi];
        dst[0] = cvt_tf32(v.x); dst[2] = cvt_tf32(v.y);
        dst[4] = cvt_tf32(v.z); dst[6] = cvt_tf32(v.w);
    }
    for (int i = tid; i < 128 * 32; i += 256) {
        int row = i >> 5, q = i & 31;
        float4 v = *(const float4*)(W + (size_t)row * HV + q * 4);
        int c = q >> 1, hi = q & 1;
        unsigned* dst = &Ws[row * XS_STRIDE + c * 8 + hi];
        dst[0] = cvt_tf32(v.x); dst[2] = cvt_tf32(v.y);
        dst[4] = cvt_tf32(v.z); dst[6] = cvt_tf32(v.w);
    }
    __syncthreads();

    const int warp = tid >> 5, lane = tid & 31;
    const int g = lane >> 2, tg = lane & 3;
    const int wm = (warp & 3) * 32;      // 4 warps over M (32 rows each)
    const int wn = (warp >> 2) * 64;     // 2 warps over N (64 cols each)

    float d[2][8][4];
    #pragma unroll
    for (int mi = 0; mi < 2; mi++)
        #pragma unroll
        for (int ni = 0; ni < 8; ni++)
            #pragma unroll
            for (int r = 0; r < 4; r++) d[mi][ni][r] = 0.0f;

    #pragma unroll
    for (int c = 0; c < 16; c++) {
        unsigned a[2][4];
        #pragma unroll
        for (int mi = 0; mi < 2; mi++) {
            uint2 lo = *(uint2*)&Xs[(wm + mi * 16 + g)     * XS_STRIDE + c * 8 + 2 * tg];
            uint2 hi = *(uint2*)&Xs[(wm + mi * 16 + 8 + g) * XS_STRIDE + c * 8 + 2 * tg];
            a[mi][0] = lo.x; a[mi][2] = lo.y;
            a[mi][1] = hi.x; a[mi][3] = hi.y;
        }
        #pragma unroll
        for (int ni = 0; ni < 8; ni++) {
            uint2 b = *(uint2*)&Ws[(wn + ni * 8 + g) * XS_STRIDE + c * 8 + 2 * tg];
            mma_tf32(d[0][ni], a[0], b.x, b.y);
            mma_tf32(d[1][ni], a[1], b.x, b.y);
        }
    }

    // epilogue: Zx row-major [B*TX, 256], this block covers cols nsel*128 + wn..
    #pragma unroll
    for (int mi = 0; mi < 2; mi++)
        #pragma unroll
        for (int ni = 0; ni < 8; ni++) {
            size_t row0 = (size_t)(mbase + wm + mi * 16 + g);
            int col = nsel * 128 + wn + ni * 8 + tg * 2;
            float2 v0 = make_float2(d[mi][ni][0], d[mi][ni][1]);
            float2 v1 = make_float2(d[mi][ni][2], d[mi][ni][3]);
            *(float2*)(g_zx + row0 * 256 + col)       = v0;
            *(float2*)(g_zx + (row0 + 8) * 256 + col) = v1;
        }
}

// ============================================================================
// Kernel 2: encoder recurrence. z_t = Zx[:,t,:] + h@W_hh^T + b; LSTM cell.
// Block = 32 elems, one direction. Each thread: 4 elems x 4 gates.
// ============================================================================
#define RBE 32
#define REC_THREADS 256

__global__ __launch_bounds__(REC_THREADS, 4)
void recur_kernel(const float* __restrict__ W_hh_f, const float* __restrict__ b_f,
                  const float* __restrict__ W_hh_r, const float* __restrict__ b_r)
{
    const int dir = blockIdx.y;
    const int b0  = blockIdx.x * RBE;
    const float* W_hh = dir ? W_hh_r : W_hh_f;
    const float* bias = dir ? b_r    : b_f;

    __shared__ float Wh[NA * GE];     // Wh[k*128+g] = W_hh[g][k]
    __shared__ float bs[GE];
    __shared__ float hs[RBE * NA], cs[RBE * NA];
    __shared__ float zs[RBE * GE];

    const int tid = threadIdx.x;
    for (int i = tid; i < GE * NA; i += REC_THREADS) {
        int gg = i / NA, k = i % NA;
        Wh[k * GE + gg] = W_hh[i];
    }
    for (int i = tid; i < GE; i += REC_THREADS) bs[i] = bias[i];
    for (int i = tid; i < RBE * NA; i += REC_THREADS) { hs[i] = 0.0f; cs[i] = 0.0f; }
    __syncthreads();

    const int gg = tid & 31, ee = tid >> 5;
    const int g0 = gg * 4, e0 = ee * 4;

    for (int t = 0; t < TX; t++) {
        const int tt = dir ? (TX - 1 - t) : t;

        // issue this step's precomputed-z loads early (independent of hs)
        float4 zx[4];
        #pragma unroll
        for (int i = 0; i < 4; i++)
            zx[i] = *(const float4*)(g_zx + ((size_t)(b0 + e0 + i) * TX + tt) * 256
                                     + dir * 128 + g0);

        float acc[4][4];
        #pragma unroll
        for (int i = 0; i < 4; i++)
            #pragma unroll
            for (int j = 0; j < 4; j++) acc[i][j] = 0.0f;

        #pragma unroll 4
        for (int k = 0; k < NA; k++) {
            float4 w = *(const float4*)&Wh[k * GE + g0];
            #pragma unroll
            for (int i = 0; i < 4; i++) {
                float hv = hs[(e0 + i) * NA + k];
                acc[i][0] += hv * w.x; acc[i][1] += hv * w.y;
                acc[i][2] += hv * w.z; acc[i][3] += hv * w.w;
            }
        }

        float4 bv = *(const float4*)&bs[g0];
        #pragma unroll
        for (int i = 0; i < 4; i++) {
            float4 z4;
            z4.x = acc[i][0] + zx[i].x + bv.x;
            z4.y = acc[i][1] + zx[i].y + bv.y;
            z4.z = acc[i][2] + zx[i].z + bv.z;
            z4.w = acc[i][3] + zx[i].w + bv.w;
            *(float4*)&zs[(e0 + i) * GE + g0] = z4;
        }
        __syncthreads();

        for (int idx = tid; idx < RBE * NA; idx += REC_THREADS) {
            int e = idx >> 5, n = idx & 31;
            float zi = zs[e * GE + n];
            float zf = zs[e * GE + NA + n];
            float zg = zs[e * GE + 2 * NA + n];
            float zo = zs[e * GE + 3 * NA + n];
            float c = fsigmoid(zf) * cs[idx] + fsigmoid(zi) * ftanh(zg);
            float h = fsigmoid(zo) * ftanh(c);
            cs[idx] = c; hs[idx] = h;
            g_a[((size_t)(b0 + e) * TX + tt) * (2 * NA) + dir * NA + n] = h;
        }
        __syncthreads();
    }
}

// ============================================================================
// Decoder: one block = 8 batch elems, persistent over TY steps.
// ============================================================================
#define DBE 8
#define DEC_THREADS 256
#define SA_STRIDE 68

#define NF_WP   (HV * GP)
#define NF_SA   (DBE * TX * SA_STRIDE)
#define NF_EA   (DBE * TX * 10)
#define DEC_SMEM_FLOATS (NF_WP + NF_SA + NF_EA + 640 + 640 + 16 + 16 + GP + MV \
                         + DBE*NS + DBE*NS + DBE*HV + DBE*GP + DBE*32 + DBE*10)

__global__ __launch_bounds__(DEC_THREADS, 1)
void decoder_kernel(const float* __restrict__ W1, const float* __restrict__ b1,
                    const float* __restrict__ W2, const float* __restrict__ b2,
                    const float* __restrict__ W_ih_p, const float* __restrict__ W_hh_p,
                    const float* __restrict__ b_p,
                    const float* __restrict__ Wo, const float* __restrict__ bo,
                    float* __restrict__ out)
{
    const int b0 = blockIdx.x * DBE;
    const int tid = threadIdx.x;

    extern __shared__ float sm[];
    float* Wp   = sm;
    float* sa   = Wp + NF_WP;
    float* ea   = sa + NF_SA;
    float* W1a  = ea + NF_EA;
    float* W1s  = W1a + 640;
    float* b1s  = W1s + 640;
    float* W2s  = b1s + 16;
    float* bps  = W2s + 16;
    float* bos  = bps + GP;
    float* ss   = bos + MV;
    float* cc   = ss + DBE * NS;
    float* ins  = cc + DBE * NS;
    float* zsd  = ins + DBE * HV;
    float* alph = zsd + DBE * GP;
    float* esm  = alph + DBE * 32;

    for (int i = tid; i < NS * GP; i += DEC_THREADS) {
        int g = i / NS, k = i % NS;
        Wp[k * GP + g]        = W_ih_p[i];
        Wp[(k + NS) * GP + g] = W_hh_p[i];
    }
    for (int i = tid; i < 640; i += DEC_THREADS) {
        int j = i / 64, d = i % 64;
        W1a[i] = W1[j * 128 + d];
        W1s[i] = W1[j * 128 + 64 + d];
    }
    if (tid < 10) { b1s[tid] = b1[tid]; W2s[tid] = W2[tid]; }
    for (int i = tid; i < GP; i += DEC_THREADS) bps[i] = b_p[i];
    if (tid < MV) bos[tid] = bo[tid];
    for (int i = tid; i < DBE * NS; i += DEC_THREADS) { ss[i] = 0.0f; cc[i] = 0.0f; }
    const float b2v = b2[0];

    const int wm = tid & 63, wkh = tid >> 6;
    float wreg[16];
    #pragma unroll
    for (int kk = 0; kk < 16; kk++) wreg[kk] = Wo[wm * 64 + wkh * 16 + kk];

    for (int i = tid; i < DBE * TX * (NS / 4); i += DEC_THREADS) {
        int e = i / (TX * 16);
        int r = i % (TX * 16);
        int tx = r / 16, d4 = r % 16;
        float4 v = *(const float4*)(g_a + ((size_t)(b0 + e) * TX + tx) * (2 * NA) + d4 * 4);
        *(float4*)&sa[(e * TX + tx) * SA_STRIDE + d4 * 4] = v;
    }
    __syncthreads();

    if (tid < DBE * TX) {
        int e = tid / TX, tx = tid % TX;
        const float* arow = &sa[(e * TX + tx) * SA_STRIDE];
        float acc[10];
        #pragma unroll
        for (int j = 0; j < 10; j++) acc[j] = 0.0f;
        for (int d = 0; d < 64; d++) {
            float av = arow[d];
            #pragma unroll
            for (int j = 0; j < 10; j++) acc[j] += av * W1a[j * 64 + d];
        }
        #pragma unroll
        for (int j = 0; j < 10; j++) ea[(e * TX + tx) * 10 + j] = acc[j];
    }
    __syncthreads();

    for (int t = 0; t < TY; t++) {
        // A: es[e][j] = b1[j] + s @ W1s[j], k split over thread pairs
        if (tid < 160) {
            int e = tid / 20, r = tid % 20;
            int j = r >> 1, half = r & 1;
            float acc = 0.0f;
            const int kb = half * 32;
            #pragma unroll 8
            for (int k = 0; k < 32; k++)
                acc += ss[e * NS + kb + k] * W1s[j * 64 + kb + k];
            acc += __shfl_xor_sync(0xffffffffu, acc, 1);
            if (half == 0) esm[e * 10 + j] = acc + b1s[j];
        }
        __syncthreads();

        // B: en = relu(tanh(ea+es) @ W2 + b2)
        if (tid < DBE * TX) {
            int e = tid / TX, tx = tid % TX;
            float acc = b2v;
            #pragma unroll
            for (int j = 0; j < 10; j++)
                acc += ftanh(ea[(e * TX + tx) * 10 + j] + esm[e * 10 + j]) * W2s[j];
            alph[e * 32 + tx] = fmaxf(acc, 0.0f);
        }
        __syncthreads();

        // C: softmax over tx — one warp per elem, shuffle reductions
        {
            int w = tid >> 5, lane = tid & 31;
            float v = (lane < TX) ? alph[w * 32 + lane] : -1e30f;
            float mx = v;
            #pragma unroll
            for (int o = 16; o; o >>= 1) mx = fmaxf(mx, __shfl_xor_sync(0xffffffffu, mx, o));
            float ex = (lane < TX) ? __expf(v - mx) : 0.0f;
            float sum = ex;
            #pragma unroll
            for (int o = 16; o; o >>= 1) sum += __shfl_xor_sync(0xffffffffu, sum, o);
            if (lane < TX) alph[w * 32 + lane] = ex * __fdividef(1.0f, sum);
        }
        __syncthreads();

        // D: context | s -> ins
        for (int i = tid; i < DBE * NS; i += DEC_THREADS) {
            int e = i / NS, d = i % NS;
            float acc = 0.0f;
            #pragma unroll 5
            for (int tx = 0; tx < TX; tx++)
                acc += alph[e * 32 + tx] * sa[(e * TX + tx) * SA_STRIDE + d];
            ins[e * HV + d]      = acc;
            ins[e * HV + NS + d] = ss[i];
        }
        __syncthreads();

        // E: gates
        {
            const int gl = (tid & 127) * 2;
            const int eb = (tid >> 7) * 4;
            float acc0[4], acc1[4];
            #pragma unroll
            for (int i = 0; i < 4; i++) { acc0[i] = bps[gl]; acc1[i] = bps[gl + 1]; }
            #pragma unroll 4
            for (int k = 0; k < HV; k++) {
                float2 w = *(const float2*)&Wp[k * GP + gl];
                #pragma unroll
                for (int i = 0; i < 4; i++) {
                    float xv = ins[(eb + i) * HV + k];
                    acc0[i] += xv * w.x; acc1[i] += xv * w.y;
                }
            }
            #pragma unroll
            for (int i = 0; i < 4; i++) {
                float2 z2; z2.x = acc0[i]; z2.y = acc1[i];
                *(float2*)&zsd[(eb + i) * GP + gl] = z2;
            }
        }
        __syncthreads();

        // F: LSTM cell
        for (int i = tid; i < DBE * NS; i += DEC_THREADS) {
            int e = i / NS, n = i % NS;
            float zi = zsd[e * GP + n];
            float zf = zsd[e * GP + NS + n];
            float zg = zsd[e * GP + 2 * NS + n];
            float zo = zsd[e * GP + 3 * NS + n];
            float c = fsigmoid(zf) * cc[i] + fsigmoid(zi) * ftanh(zg);
            float h = fsigmoid(zo) * ftanh(c);
            cc[i] = c; ss[i] = h;
        }
        __syncthreads();

        // G: out = s @ Wo^T + bo via k-split register partials
        {
            #pragma unroll
            for (int e = 0; e < DBE; e++) {
                float p = 0.0f;
                #pragma unroll
                for (int kk = 0; kk < 16; kk++)
                    p += ss[e * NS + wkh * 16 + kk] * wreg[kk];
                zsd[(wkh * DBE + e) * 64 + wm] = p;
            }
        }
        __syncthreads();
        for (int i = tid; i < DBE * MV; i += DEC_THREADS) {
            int e = i / MV, m = i % MV;
            float o = bos[m]
                    + zsd[(0 * DBE + e) * 64 + m] + zsd[(1 * DBE + e) * 64 + m]
                    + zsd[(2 * DBE + e) * 64 + m] + zsd[(3 * DBE + e) * 64 + m];
            out[((size_t)(b0 + e) * TY + t) * MV + m] = o;
        }
        __syncthreads();
    }
}

// ============================================================================
extern "C" void kernel_launch(void* const* d_in, const int* in_sizes, int n_in,
                              void* d_out, int out_size)
{
    const float* X      = (const float*)d_in[0];
    const float* W_ih_f = (const float*)d_in[1];
    const float* W_hh_f = (const float*)d_in[2];
    const float* b_f    = (const float*)d_in[3];
    const float* W_ih_r = (const float*)d_in[4];
    const float* W_hh_r = (const float*)d_in[5];
    const float* b_r    = (const float*)d_in[6];
    const float* W1     = (const float*)d_in[7];
    const float* b1     = (const float*)d_in[8];
    const float* W2     = (const float*)d_in[9];
    const float* b2     = (const float*)d_in[10];
    const float* W_ih_p = (const float*)d_in[11];
    const float* W_hh_p = (const float*)d_in[12];
    const float* b_p    = (const float*)d_in[13];
    const float* Wo     = (const float*)d_in[14];
    const float* bo     = (const float*)d_in[15];
    float* out = (float*)d_out;

    const int dec_smem = DEC_SMEM_FLOATS * sizeof(float);
    cudaFuncSetAttribute(ingemm_kernel,  cudaFuncAttributeMaxDynamicSharedMemorySize, K1_SMEM);
    cudaFuncSetAttribute(decoder_kernel, cudaFuncAttributeMaxDynamicSharedMemorySize, dec_smem);

    dim3 g1((B_TOT * TX) / 128, 2);
    ingemm_kernel<<<g1, 256, K1_SMEM>>>(X, W_ih_f, W_ih_r);

    dim3 g2(B_TOT / RBE, 2);
    recur_kernel<<<g2, REC_THREADS>>>(W_hh_f, b_f, W_hh_r, b_r);

    decoder_kernel<<<B_TOT / DBE, DEC_THREADS, dec_smem>>>(W1, b1, W2, b2,
                                                           W_ih_p, W_hh_p, b_p, Wo, bo, out);
}

// round 3
// speedup vs baseline: 2.0612x; 1.7156x over previous
#include <cuda_runtime.h>
#include <cuda_bf16.h>
#include <math.h>

#define B_TOT 16384
#define TX 30
#define TY 10
#define NA 32
#define NS 64
#define HV 128
#define MV 64
#define GE 128   // 4*NA
#define GP 256   // 4*NS

// scratch buffers
__device__ __align__(16) float g_a [(size_t)B_TOT * TX * (2 * NA)];     // 126 MB
__device__ __align__(16) float g_zx[(size_t)B_TOT * TX * 256];          // 504 MB

__device__ __forceinline__ float fsigmoid(float x) {
    return __fdividef(1.0f, 1.0f + __expf(-x));
}
__device__ __forceinline__ float ftanh(float x) {
    x = fminf(15.0f, fmaxf(-15.0f, x));
    float e = __expf(2.0f * x);
    return __fdividef(e - 1.0f, e + 1.0f);
}
__device__ __forceinline__ unsigned cvt_tf32(float x) {
    unsigned u;
    asm("cvt.rna.tf32.f32 %0, %1;" : "=r"(u) : "f"(x));
    return u;
}
__device__ __forceinline__ unsigned pack_bf16(float a, float b) {
    __nv_bfloat162 h = __floats2bfloat162_rn(a, b);
    return *(unsigned*)&h;
}
__device__ __forceinline__ void mma_tf32(float* d, const unsigned* a, unsigned b0, unsigned b1) {
    asm("mma.sync.aligned.m16n8k8.row.col.f32.tf32.tf32.f32 "
        "{%0,%1,%2,%3}, {%4,%5,%6,%7}, {%8,%9}, {%0,%1,%2,%3};"
        : "+f"(d[0]), "+f"(d[1]), "+f"(d[2]), "+f"(d[3])
        : "r"(a[0]), "r"(a[1]), "r"(a[2]), "r"(a[3]), "r"(b0), "r"(b1));
}
__device__ __forceinline__ void mma_bf16(float* d, unsigned a0, unsigned a1,
                                         unsigned a2, unsigned a3,
                                         unsigned b0, unsigned b1) {
    asm("mma.sync.aligned.m16n8k16.row.col.f32.bf16.bf16.f32 "
        "{%0,%1,%2,%3}, {%4,%5,%6,%7}, {%8,%9}, {%0,%1,%2,%3};"
        : "+f"(d[0]), "+f"(d[1]), "+f"(d[2]), "+f"(d[3])
        : "r"(a0), "r"(a1), "r"(a2), "r"(a3), "r"(b0), "r"(b1));
}

// ============================================================================
// Kernel 1: Zx = X @ Wcat^T via bf16 mma m16n8k16.
// Tile 128Mx128N, K=128 resident. smem rows of 64 u32 (bf16 pairs) permuted:
// within each 8-u32 chunk (16 ks), pair j stored at (j%4)*2 + j/4 so the
// (tg, tg+4) fragment pair is a single LDS.64. Stride 68 u32 (pad 4) makes
// the 8 g-rows hit distinct bank groups (68*g mod 32 = 4g).
// ============================================================================
#define XS_U 68
#define K1_SMEM (2 * 128 * XS_U * 4)

__global__ __launch_bounds__(256, 2)
void ingemm_kernel(const float* __restrict__ X,
                   const float* __restrict__ W_ih_f,
                   const float* __restrict__ W_ih_r)
{
    const int mbase = blockIdx.x * 128;
    const int nsel  = blockIdx.y;
    const float* W = nsel ? W_ih_r : W_ih_f;

    extern __shared__ unsigned smu[];
    unsigned* Xs = smu;
    unsigned* Ws = smu + 128 * XS_U;

    const int tid = threadIdx.x;

    // load + cvt bf16 + permuted store. i -> (row, q): float4 q covers ks 4q..4q+3
    for (int i = tid; i < 128 * 32; i += 256) {
        int row = i >> 5, q = i & 31;
        float4 v = *(const float4*)(X + (size_t)(mbase + row) * HV + q * 4);
        int c = q >> 2;                 // 16-k chunk
        int jj0 = (q & 3) * 2;          // u32 index within chunk
        int p0 = (jj0 & 3) * 2 + (jj0 >> 2);
        int p1 = ((jj0 + 1) & 3) * 2 + ((jj0 + 1) >> 2);
        unsigned* dst = &Xs[row * XS_U + c * 8];
        dst[p0] = pack_bf16(v.x, v.y);
        dst[p1] = pack_bf16(v.z, v.w);
    }
    for (int i = tid; i < 128 * 32; i += 256) {
        int row = i >> 5, q = i & 31;
        float4 v = *(const float4*)(W + (size_t)row * HV + q * 4);
        int c = q >> 2;
        int jj0 = (q & 3) * 2;
        int p0 = (jj0 & 3) * 2 + (jj0 >> 2);
        int p1 = ((jj0 + 1) & 3) * 2 + ((jj0 + 1) >> 2);
        unsigned* dst = &Ws[row * XS_U + c * 8];
        dst[p0] = pack_bf16(v.x, v.y);
        dst[p1] = pack_bf16(v.z, v.w);
    }
    __syncthreads();

    const int warp = tid >> 5, lane = tid & 31;
    const int g = lane >> 2, tg = lane & 3;
    const int wm = (warp & 3) * 32;
    const int wn = (warp >> 2) * 64;

    float d[2][8][4];
    #pragma unroll
    for (int mi = 0; mi < 2; mi++)
        #pragma unroll
        for (int ni = 0; ni < 8; ni++)
            #pragma unroll
            for (int r = 0; r < 4; r++) d[mi][ni][r] = 0.0f;

    #pragma unroll
    for (int c = 0; c < 8; c++) {
        unsigned a[2][4];
        #pragma unroll
        for (int mi = 0; mi < 2; mi++) {
            uint2 lo = *(uint2*)&Xs[(wm + mi * 16 + g)     * XS_U + c * 8 + 2 * tg];
            uint2 hi = *(uint2*)&Xs[(wm + mi * 16 + 8 + g) * XS_U + c * 8 + 2 * tg];
            a[mi][0] = lo.x; a[mi][1] = hi.x;
            a[mi][2] = lo.y; a[mi][3] = hi.y;
        }
        #pragma unroll
        for (int ni = 0; ni < 8; ni++) {
            uint2 b = *(uint2*)&Ws[(wn + ni * 8 + g) * XS_U + c * 8 + 2 * tg];
            mma_bf16(d[0][ni], a[0][0], a[0][1], a[0][2], a[0][3], b.x, b.y);
            mma_bf16(d[1][ni], a[1][0], a[1][1], a[1][2], a[1][3], b.x, b.y);
        }
    }

    #pragma unroll
    for (int mi = 0; mi < 2; mi++)
        #pragma unroll
        for (int ni = 0; ni < 8; ni++) {
            size_t row0 = (size_t)(mbase + wm + mi * 16 + g);
            int col = nsel * 128 + wn + ni * 8 + tg * 2;
            *(float2*)(g_zx + row0 * 256 + col)       = make_float2(d[mi][ni][0], d[mi][ni][1]);
            *(float2*)(g_zx + (row0 + 8) * 256 + col) = make_float2(d[mi][ni][2], d[mi][ni][3]);
        }
}

// ============================================================================
// Kernel 2: encoder recurrence (unchanged)
// ============================================================================
#define RBE 32
#define REC_THREADS 256

__global__ __launch_bounds__(REC_THREADS, 4)
void recur_kernel(const float* __restrict__ W_hh_f, const float* __restrict__ b_f,
                  const float* __restrict__ W_hh_r, const float* __restrict__ b_r)
{
    const int dir = blockIdx.y;
    const int b0  = blockIdx.x * RBE;
    const float* W_hh = dir ? W_hh_r : W_hh_f;
    const float* bias = dir ? b_r    : b_f;

    __shared__ float Wh[NA * GE];
    __shared__ float bs[GE];
    __shared__ float hs[RBE * NA], cs[RBE * NA];
    __shared__ float zs[RBE * GE];

    const int tid = threadIdx.x;
    for (int i = tid; i < GE * NA; i += REC_THREADS) {
        int gg = i / NA, k = i % NA;
        Wh[k * GE + gg] = W_hh[i];
    }
    for (int i = tid; i < GE; i += REC_THREADS) bs[i] = bias[i];
    for (int i = tid; i < RBE * NA; i += REC_THREADS) { hs[i] = 0.0f; cs[i] = 0.0f; }
    __syncthreads();

    const int gg = tid & 31, ee = tid >> 5;
    const int g0 = gg * 4, e0 = ee * 4;

    for (int t = 0; t < TX; t++) {
        const int tt = dir ? (TX - 1 - t) : t;

        float4 zx[4];
        #pragma unroll
        for (int i = 0; i < 4; i++)
            zx[i] = *(const float4*)(g_zx + ((size_t)(b0 + e0 + i) * TX + tt) * 256
                                     + dir * 128 + g0);

        float acc[4][4];
        #pragma unroll
        for (int i = 0; i < 4; i++)
            #pragma unroll
            for (int j = 0; j < 4; j++) acc[i][j] = 0.0f;

        #pragma unroll 4
        for (int k = 0; k < NA; k++) {
            float4 w = *(const float4*)&Wh[k * GE + g0];
            #pragma unroll
            for (int i = 0; i < 4; i++) {
                float hv = hs[(e0 + i) * NA + k];
                acc[i][0] += hv * w.x; acc[i][1] += hv * w.y;
                acc[i][2] += hv * w.z; acc[i][3] += hv * w.w;
            }
        }

        float4 bv = *(const float4*)&bs[g0];
        #pragma unroll
        for (int i = 0; i < 4; i++) {
            float4 z4;
            z4.x = acc[i][0] + zx[i].x + bv.x;
            z4.y = acc[i][1] + zx[i].y + bv.y;
            z4.z = acc[i][2] + zx[i].z + bv.z;
            z4.w = acc[i][3] + zx[i].w + bv.w;
            *(float4*)&zs[(e0 + i) * GE + g0] = z4;
        }
        __syncthreads();

        for (int idx = tid; idx < RBE * NA; idx += REC_THREADS) {
            int e = idx >> 5, n = idx & 31;
            float zi = zs[e * GE + n];
            float zf = zs[e * GE + NA + n];
            float zg = zs[e * GE + 2 * NA + n];
            float zo = zs[e * GE + 3 * NA + n];
            float c = fsigmoid(zf) * cs[idx] + fsigmoid(zi) * ftanh(zg);
            float h = fsigmoid(zo) * ftanh(c);
            cs[idx] = c; hs[idx] = h;
            g_a[((size_t)(b0 + e) * TX + tt) * (2 * NA) + dir * NA + n] = h;
        }
        __syncthreads();
    }
}

// ============================================================================
// Decoder v3: DBE=16, 512 threads, persistent over TY.
// Gate GEMM z[16,256] = ins[16,128] @ Wcat^T via tf32 mma m16n8k8.
// Wcat fragments live in registers per warp (16 gates x K128 = 64 regs),
// loaded once per block. No Wp smem (frees 128 KB).
// ins (tf32, permuted) written by the context phase each step.
// ============================================================================
#define DBE 16
#define DEC_THREADS 512
#define SA_STRIDE 68
#define INSP_STRIDE 140   // u32 per row: 128 data + 12 pad (140 mod 32 = 12)

#define NF_SA   (DBE * TX * SA_STRIDE)   // 32640
#define NF_EA   (DBE * TX * 10)          // 4800
#define DEC_SMEM_FLOATS (NF_SA + NF_EA + 640 + 640 + 16 + 16 + GP + MV \
                         + DBE*NS + DBE*NS + DBE*INSP_STRIDE + DBE*GP + DBE*32 + DBE*10)

__global__ __launch_bounds__(DEC_THREADS, 1)
void decoder_kernel(const float* __restrict__ W1, const float* __restrict__ b1,
                    const float* __restrict__ W2, const float* __restrict__ b2,
                    const float* __restrict__ W_ih_p, const float* __restrict__ W_hh_p,
                    const float* __restrict__ b_p,
                    const float* __restrict__ Wo, const float* __restrict__ bo,
                    float* __restrict__ out)
{
    const int b0 = blockIdx.x * DBE;
    const int tid = threadIdx.x;

    extern __shared__ float sm[];
    float* sa   = sm;                    // [16][30][68]
    float* ea   = sa + NF_SA;            // [16][30][10]
    float* W1a  = ea + NF_EA;            // [10][64]
    float* W1s  = W1a + 640;             // [10][64]
    float* b1s  = W1s + 640;             // [16]
    float* W2s  = b1s + 16;              // [16]
    float* bps  = W2s + 16;              // [256]
    float* bos  = bps + GP;              // [64]
    float* ss   = bos + MV;              // [16][64]
    float* cc   = ss + DBE * NS;         // [16][64]
    unsigned* insp = (unsigned*)(cc + DBE * NS);   // [16][140] tf32 permuted
    float* zsd  = (float*)(insp + DBE * INSP_STRIDE); // [16][256], reused for out-reduce
    float* alph = zsd + DBE * GP;        // [16][32]
    float* esm  = alph + DBE * 32;       // [16][10]

    const int warp = tid >> 5, lane = tid & 31;
    const int g = lane >> 2, tg = lane & 3;

    // ---- Wcat B-fragments -> registers (per warp: gates [warp*16, warp*16+16)) ----
    // Bw[(nt*16+c)*2 + r]: n = warp*16 + nt*8 + g ; k = c*8 + tg + r*4
    unsigned Bw[64];
    #pragma unroll
    for (int nt = 0; nt < 2; nt++) {
        int n = warp * 16 + nt * 8 + g;
        #pragma unroll
        for (int c = 0; c < 8; c++) {   // k in [0,64): ctx part = W_ih_p
            Bw[(nt * 16 + c) * 2 + 0] = cvt_tf32(W_ih_p[n * 64 + c * 8 + tg]);
            Bw[(nt * 16 + c) * 2 + 1] = cvt_tf32(W_ih_p[n * 64 + c * 8 + tg + 4]);
        }
        #pragma unroll
        for (int c = 0; c < 8; c++) {   // k in [64,128): s part = W_hh_p
            Bw[(nt * 16 + (8 + c)) * 2 + 0] = cvt_tf32(W_hh_p[n * 64 + c * 8 + tg]);
            Bw[(nt * 16 + (8 + c)) * 2 + 1] = cvt_tf32(W_hh_p[n * 64 + c * 8 + tg + 4]);
        }
    }

    // Wo register cache: thread owns (m = tid&63, k-chunk wkh = (tid>>6)&3, e-half eh)
    const int wm = tid & 63, wkh = (tid >> 6) & 3, eh = tid >> 8;
    float wreg[16];
    #pragma unroll
    for (int kk = 0; kk < 16; kk++) wreg[kk] = Wo[wm * 64 + wkh * 16 + kk];

    // ---- stage small weights ----
    for (int i = tid; i < 640; i += DEC_THREADS) {
        int j = i / 64, d = i % 64;
        W1a[i] = W1[j * 128 + d];
        W1s[i] = W1[j * 128 + 64 + d];
    }
    if (tid < 10) { b1s[tid] = b1[tid]; W2s[tid] = W2[tid]; }
    for (int i = tid; i < GP; i += DEC_THREADS) bps[i] = b_p[i];
    if (tid < MV) bos[tid] = bo[tid];
    for (int i = tid; i < DBE * NS; i += DEC_THREADS) { ss[i] = 0.0f; cc[i] = 0.0f; }
    const float b2v = b2[0];

    // ---- load a tile ----
    for (int i = tid; i < DBE * TX * (NS / 4); i += DEC_THREADS) {
        int e = i / (TX * 16);
        int r = i % (TX * 16);
        int tx = r / 16, d4 = r % 16;
        float4 v = *(const float4*)(g_a + ((size_t)(b0 + e) * TX + tx) * (2 * NA) + d4 * 4);
        *(float4*)&sa[(e * TX + tx) * SA_STRIDE + d4 * 4] = v;
    }
    __syncthreads();

    // ---- Ea precompute ----
    if (tid < DBE * TX) {
        int e = tid / TX, tx = tid % TX;
        const float* arow = &sa[(e * TX + tx) * SA_STRIDE];
        float acc[10];
        #pragma unroll
        for (int j = 0; j < 10; j++) acc[j] = 0.0f;
        for (int d = 0; d < 64; d++) {
            float av = arow[d];
            #pragma unroll
            for (int j = 0; j < 10; j++) acc[j] += av * W1a[j * 64 + d];
        }
        #pragma unroll
        for (int j = 0; j < 10; j++) ea[(e * TX + tx) * 10 + j] = acc[j];
    }
    __syncthreads();

    for (int t = 0; t < TY; t++) {
        // A: es[e][j] = b1[j] + s @ W1s[j]  (k-split pairs; 320 threads = 10 warps)
        if (tid < 320) {
            int e = tid / 20, r = tid % 20;
            int j = r >> 1, half = r & 1;
            float acc = 0.0f;
            const int kb = half * 32;
            #pragma unroll 8
            for (int k = 0; k < 32; k++)
                acc += ss[e * NS + kb + k] * W1s[j * 64 + kb + k];
            acc += __shfl_xor_sync(0xffffffffu, acc, 1);
            if (half == 0) esm[e * 10 + j] = acc + b1s[j];
        }
        __syncthreads();

        // B: en = relu(tanh(ea+es) @ W2 + b2)   (480 threads = 15 warps)
        if (tid < DBE * TX) {
            int e = tid / TX, tx = tid % TX;
            float acc = b2v;
            #pragma unroll
            for (int j = 0; j < 10; j++)
                acc += ftanh(ea[(e * TX + tx) * 10 + j] + esm[e * 10 + j]) * W2s[j];
            alph[e * 32 + tx] = fmaxf(acc, 0.0f);
        }
        __syncthreads();

        // C: softmax — one warp per elem
        {
            float v = (lane < TX) ? alph[warp * 32 + lane] : -1e30f;
            float mx = v;
            #pragma unroll
            for (int o = 16; o; o >>= 1) mx = fmaxf(mx, __shfl_xor_sync(0xffffffffu, mx, o));
            float ex = (lane < TX) ? __expf(v - mx) : 0.0f;
            float sum = ex;
            #pragma unroll
            for (int o = 16; o; o >>= 1) sum += __shfl_xor_sync(0xffffffffu, sum, o);
            if (lane < TX) alph[warp * 32 + lane] = ex * __fdividef(1.0f, sum);
        }
        __syncthreads();

        // D: context + s -> insp (tf32, permuted for LDS.64 fragments)
        for (int i = tid; i < DBE * NS; i += DEC_THREADS) {
            int e = i >> 6, d = i & 63;
            float acc = 0.0f;
            #pragma unroll 5
            for (int tx = 0; tx < TX; tx++)
                acc += alph[e * 32 + tx] * sa[(e * TX + tx) * SA_STRIDE + d];
            int c = d >> 3, jj = d & 7;
            int p = (jj & 3) * 2 + (jj >> 2);
            insp[e * INSP_STRIDE + c * 8 + p]       = cvt_tf32(acc);
            insp[e * INSP_STRIDE + (8 + c) * 8 + p] = cvt_tf32(ss[i]);
        }
        __syncthreads();

        // E: gate GEMM via tf32 mma — warp covers gates [warp*16, warp*16+16)
        {
            float dd[2][4];
            #pragma unroll
            for (int nt = 0; nt < 2; nt++)
                #pragma unroll
                for (int r = 0; r < 4; r++) dd[nt][r] = 0.0f;
            #pragma unroll
            for (int c = 0; c < 16; c++) {
                uint2 va = *(uint2*)&insp[g * INSP_STRIDE + c * 8 + 2 * tg];
                uint2 vb = *(uint2*)&insp[(g + 8) * INSP_STRIDE + c * 8 + 2 * tg];
                unsigned a[4] = {va.x, vb.x, va.y, vb.y};
                mma_tf32(dd[0], a, Bw[(0 * 16 + c) * 2], Bw[(0 * 16 + c) * 2 + 1]);
                mma_tf32(dd[1], a, Bw[(1 * 16 + c) * 2], Bw[(1 * 16 + c) * 2 + 1]);
            }
            #pragma unroll
            for (int nt = 0; nt < 2; nt++) {
                int n0 = warp * 16 + nt * 8 + 2 * tg;
                *(float2*)&zsd[g * GP + n0]       = make_float2(dd[nt][0], dd[nt][1]);
                *(float2*)&zsd[(g + 8) * GP + n0] = make_float2(dd[nt][2], dd[nt][3]);
            }
        }
        __syncthreads();

        // F: LSTM cell (bias added here)
        for (int i = tid; i < DBE * NS; i += DEC_THREADS) {
            int e = i >> 6, n = i & 63;
            float zi = zsd[e * GP + n]           + bps[n];
            float zf = zsd[e * GP + NS + n]      + bps[NS + n];
            float zg = zsd[e * GP + 2 * NS + n]  + bps[2 * NS + n];
            float zo = zsd[e * GP + 3 * NS + n]  + bps[3 * NS + n];
            float c = fsigmoid(zf) * cc[i] + fsigmoid(zi) * ftanh(zg);
            float h = fsigmoid(zo) * ftanh(c);
            cc[i] = c; ss[i] = h;
        }
        __syncthreads();

        // G: out = s @ Wo^T + bo  (4-way k-split, 2-way e-split; reuse zsd)
        {
            #pragma unroll
            for (int ei = 0; ei < 8; ei++) {
                int e = eh * 8 + ei;
                float p = 0.0f;
                #pragma unroll
                for (int kk = 0; kk < 16; kk++)
                    p += ss[e * NS + wkh * 16 + kk] * wreg[kk];
                zsd[(wkh * DBE + e) * 64 + wm] = p;
            }
        }
        __syncthreads();
        for (int i = tid; i < DBE * MV; i += DEC_THREADS) {
            int e = i >> 6, m = i & 63;
            float o = bos[m]
                    + zsd[(0 * DBE + e) * 64 + m] + zsd[(1 * DBE + e) * 64 + m]
                    + zsd[(2 * DBE + e) * 64 + m] + zsd[(3 * DBE + e) * 64 + m];
            out[((size_t)(b0 + e) * TY + t) * MV + m] = o;
        }
        __syncthreads();
    }
}

// ============================================================================
extern "C" void kernel_launch(void* const* d_in, const int* in_sizes, int n_in,
                              void* d_out, int out_size)
{
    const float* X      = (const float*)d_in[0];
    const float* W_ih_f = (const float*)d_in[1];
    const float* W_hh_f = (const float*)d_in[2];
    const float* b_f    = (const float*)d_in[3];
    const float* W_ih_r = (const float*)d_in[4];
    const float* W_hh_r = (const float*)d_in[5];
    const float* b_r    = (const float*)d_in[6];
    const float* W1     = (const float*)d_in[7];
    const float* b1     = (const float*)d_in[8];
    const float* W2     = (const float*)d_in[9];
    const float* b2     = (const float*)d_in[10];
    const float* W_ih_p = (const float*)d_in[11];
    const float* W_hh_p = (const float*)d_in[12];
    const float* b_p    = (const float*)d_in[13];
    const float* Wo     = (const float*)d_in[14];
    const float* bo     = (const float*)d_in[15];
    float* out = (float*)d_out;

    const int dec_smem = DEC_SMEM_FLOATS * sizeof(float);
    cudaFuncSetAttribute(ingemm_kernel,  cudaFuncAttributeMaxDynamicSharedMemorySize, K1_SMEM);
    cudaFuncSetAttribute(decoder_kernel, cudaFuncAttributeMaxDynamicSharedMemorySize, dec_smem);

    dim3 g1((B_TOT * TX) / 128, 2);
    ingemm_kernel<<<g1, 256, K1_SMEM>>>(X, W_ih_f, W_ih_r);

    dim3 g2(B_TOT / RBE, 2);
    recur_kernel<<<g2, REC_THREADS>>>(W_hh_f, b_f, W_hh_r, b_r);

    decoder_kernel<<<B_TOT / DBE, DEC_THREADS, dec_smem>>>(W1, b1, W2, b2,
                                                           W_ih_p, W_hh_p, b_p, Wo, bo, out);
}

// round 4
// speedup vs baseline: 2.9861x; 1.4487x over previous
#include <cuda_runtime.h>
#include <cuda_bf16.h>
#include <math.h>

#define B_TOT 16384
#define TX 30
#define TY 10
#define NA 32
#define NS 64
#define HV 128
#define MV 64
#define GE 128   // 4*NA
#define GP 256   // 4*NS

// scratch: concat bidirectional hidden states a[B][TX][64]
__device__ __align__(16) float g_a[(size_t)B_TOT * TX * (2 * NA)];   // 126 MB

__device__ __forceinline__ float fsigmoid(float x) {
    return __fdividef(1.0f, 1.0f + __expf(-x));
}
__device__ __forceinline__ float ftanh(float x) {
    x = fminf(15.0f, fmaxf(-15.0f, x));
    float e = __expf(2.0f * x);
    return __fdividef(e - 1.0f, e + 1.0f);
}
__device__ __forceinline__ unsigned cvt_tf32(float x) {
    unsigned u;
    asm("cvt.rna.tf32.f32 %0, %1;" : "=r"(u) : "f"(x));
    return u;
}
__device__ __forceinline__ unsigned pack_bf16(float a, float b) {
    __nv_bfloat162 h = __floats2bfloat162_rn(a, b);
    return *(unsigned*)&h;
}
__device__ __forceinline__ void mma_tf32(float* d, const unsigned* a, unsigned b0, unsigned b1) {
    asm("mma.sync.aligned.m16n8k8.row.col.f32.tf32.tf32.f32 "
        "{%0,%1,%2,%3}, {%4,%5,%6,%7}, {%8,%9}, {%0,%1,%2,%3};"
        : "+f"(d[0]), "+f"(d[1]), "+f"(d[2]), "+f"(d[3])
        : "r"(a[0]), "r"(a[1]), "r"(a[2]), "r"(a[3]), "r"(b0), "r"(b1));
}
__device__ __forceinline__ void mma_bf16(float* d, unsigned a0, unsigned a1,
                                         unsigned a2, unsigned a3,
                                         unsigned b0, unsigned b1) {
    asm("mma.sync.aligned.m16n8k16.row.col.f32.bf16.bf16.f32 "
        "{%0,%1,%2,%3}, {%4,%5,%6,%7}, {%8,%9}, {%0,%1,%2,%3};"
        : "+f"(d[0]), "+f"(d[1]), "+f"(d[2]), "+f"(d[3])
        : "r"(a0), "r"(a1), "r"(a2), "r"(a3), "r"(b0), "r"(b1));
}

// ============================================================================
// Fused encoder: per block 64 batch elems, BOTH directions, persistent over
// TX steps. z[64,256] = x @ [Wih_f|Wih_r]^T + h @ Whh^T via bf16 mma with
// weight B-fragments in registers. LSTM cell in smem. No z global traffic.
//
// Warp layout (16 warps): warp w covers gate cols [16w,16w+16); dir = w>>3.
// Per warp per step: 4 m-tiles (16 rows) x 2 n-tiles, K=128 (x) + K=32 (h).
// smem xs: permuted bf16-pair layout (u32 j of a 16k chunk at (j%4)*2+j/4)
// so each A/B fragment pair is one LDS.64. xs stride 68 u32, hbf stride 20.
// ============================================================================
#define EBE 64
#define ENC_THREADS 512
#define XST 68
#define HST 20
#define ZST 260
#define ENC_SMEM_BYTES ((2*2*64*XST + 2*64*HST) * 4 + (64*ZST + 2*64*32 + 256) * 4)

__global__ __launch_bounds__(ENC_THREADS, 1)
void encoder_fused(const float* __restrict__ X,
                   const float* __restrict__ W_ih_f, const float* __restrict__ W_hh_f,
                   const float* __restrict__ b_f,
                   const float* __restrict__ W_ih_r, const float* __restrict__ W_hh_r,
                   const float* __restrict__ b_r)
{
    const int b0  = blockIdx.x * EBE;
    const int tid = threadIdx.x;
    const int warp = tid >> 5, lane = tid & 31;
    const int g = lane >> 2, tg = lane & 3;
    const int dir = warp >> 3;       // 0 fwd, 1 rev
    const int wl  = warp & 7;        // warp within dir

    extern __shared__ unsigned smu[];
    unsigned* xs  = smu;                          // [buf][dir][64][XST]
    unsigned* hbf = xs + 2 * 2 * 64 * XST;        // [dir][64][HST] bf16 pairs
    float* zs  = (float*)(hbf + 2 * 64 * HST);    // [64][ZST]
    float* cst = zs + 64 * ZST;                   // [dir][64][32]
    float* bs  = cst + 2 * 64 * 32;               // [256]

    const float* Wi = dir ? W_ih_r : W_ih_f;
    const float* Wh = dir ? W_hh_r : W_hh_f;

    // ---- weight B-fragments -> registers ----
    unsigned Bx[2][8][2], Bh[2][2][2];
    #pragma unroll
    for (int nt = 0; nt < 2; nt++) {
        int n = wl * 16 + nt * 8 + g;
        #pragma unroll
        for (int c = 0; c < 8; c++) {
            Bx[nt][c][0] = pack_bf16(Wi[n * 128 + c * 16 + 2 * tg],
                                     Wi[n * 128 + c * 16 + 2 * tg + 1]);
            Bx[nt][c][1] = pack_bf16(Wi[n * 128 + c * 16 + 8 + 2 * tg],
                                     Wi[n * 128 + c * 16 + 8 + 2 * tg + 1]);
        }
        #pragma unroll
        for (int c = 0; c < 2; c++) {
            Bh[nt][c][0] = pack_bf16(Wh[n * 32 + c * 16 + 2 * tg],
                                     Wh[n * 32 + c * 16 + 2 * tg + 1]);
            Bh[nt][c][1] = pack_bf16(Wh[n * 32 + c * 16 + 8 + 2 * tg],
                                     Wh[n * 32 + c * 16 + 8 + 2 * tg + 1]);
        }
    }

    // ---- init smem state ----
    for (int i = tid; i < 256; i += ENC_THREADS) bs[i] = (i < 128) ? b_f[i] : b_r[i - 128];
    for (int i = tid; i < 2 * 64 * HST; i += ENC_THREADS) hbf[i] = 0u;
    for (int i = tid; i < 2 * 64 * 32; i += ENC_THREADS) cst[i] = 0.0f;

    // ---- initial x tiles (t=0): dir0 -> x_0, dir1 -> x_{TX-1}, into buf 0 ----
    #pragma unroll
    for (int ii = 0; ii < 8; ii++) {
        int flat = tid + ii * ENC_THREADS;
        int dd = flat >> 11, r = flat & 2047;
        int row = r >> 5, q = r & 31;
        int ts = dd ? (TX - 1) : 0;
        float4 v = *(const float4*)(X + ((size_t)(b0 + row) * TX + ts) * HV + q * 4);
        int c = q >> 2, jj0 = (q & 3) * 2;
        int p0 = (jj0 & 3) * 2 + (jj0 >> 2);
        int p1 = ((jj0 + 1) & 3) * 2 + ((jj0 + 1) >> 2);
        unsigned* dst = &xs[((0 * 2 + dd) * 64 + row) * XST + c * 8];
        dst[p0] = pack_bf16(v.x, v.y);
        dst[p1] = pack_bf16(v.z, v.w);
    }
    __syncthreads();

    int buf = 0;
    for (int t = 0; t < TX; t++) {
        // ---- prefetch x for t+1 (clamped; overlaps mma) ----
        float4 xpre[8];
        #pragma unroll
        for (int ii = 0; ii < 8; ii++) {
            int flat = tid + ii * ENC_THREADS;
            int dd = flat >> 11, r = flat & 2047;
            int row = r >> 5, q = r & 31;
            int ts = dd ? max(TX - 2 - t, 0) : min(t + 1, TX - 1);
            xpre[ii] = *(const float4*)(X + ((size_t)(b0 + row) * TX + ts) * HV + q * 4);
        }

        // ---- mma: z = x @ Wi^T + h @ Wh^T ----
        float d[4][2][4];
        #pragma unroll
        for (int mi = 0; mi < 4; mi++)
            #pragma unroll
            for (int nt = 0; nt < 2; nt++)
                #pragma unroll
                for (int r = 0; r < 4; r++) d[mi][nt][r] = 0.0f;

        const unsigned* xbase = &xs[((buf * 2 + dir) * 64) * XST];
        #pragma unroll
        for (int c = 0; c < 8; c++) {
            unsigned a[4][4];
            #pragma unroll
            for (int mi = 0; mi < 4; mi++) {
                uint2 lo = *(uint2*)&xbase[(mi * 16 + g) * XST + c * 8 + 2 * tg];
                uint2 hi = *(uint2*)&xbase[(mi * 16 + 8 + g) * XST + c * 8 + 2 * tg];
                a[mi][0] = lo.x; a[mi][1] = hi.x; a[mi][2] = lo.y; a[mi][3] = hi.y;
            }
            #pragma unroll
            for (int mi = 0; mi < 4; mi++) {
                mma_bf16(d[mi][0], a[mi][0], a[mi][1], a[mi][2], a[mi][3],
                         Bx[0][c][0], Bx[0][c][1]);
                mma_bf16(d[mi][1], a[mi][0], a[mi][1], a[mi][2], a[mi][3],
                         Bx[1][c][0], Bx[1][c][1]);
            }
        }
        const unsigned* hbase = &hbf[(dir * 64) * HST];
        #pragma unroll
        for (int c = 0; c < 2; c++) {
            unsigned a[4][4];
            #pragma unroll
            for (int mi = 0; mi < 4; mi++) {
                uint2 lo = *(uint2*)&hbase[(mi * 16 + g) * HST + c * 8 + 2 * tg];
                uint2 hi = *(uint2*)&hbase[(mi * 16 + 8 + g) * HST + c * 8 + 2 * tg];
                a[mi][0] = lo.x; a[mi][1] = hi.x; a[mi][2] = lo.y; a[mi][3] = hi.y;
            }
            #pragma unroll
            for (int mi = 0; mi < 4; mi++) {
                mma_bf16(d[mi][0], a[mi][0], a[mi][1], a[mi][2], a[mi][3],
                         Bh[0][c][0], Bh[0][c][1]);
                mma_bf16(d[mi][1], a[mi][0], a[mi][1], a[mi][2], a[mi][3],
                         Bh[1][c][0], Bh[1][c][1]);
            }
        }

        // ---- stage z fragments to smem ----
        #pragma unroll
        for (int mi = 0; mi < 4; mi++)
            #pragma unroll
            for (int nt = 0; nt < 2; nt++) {
                int col = dir * 128 + wl * 16 + nt * 8 + 2 * tg;
                *(float2*)&zs[(mi * 16 + g) * ZST + col] =
                    make_float2(d[mi][nt][0], d[mi][nt][1]);
                *(float2*)&zs[(mi * 16 + 8 + g) * ZST + col] =
                    make_float2(d[mi][nt][2], d[mi][nt][3]);
            }
        __syncthreads();

        // ---- store prefetched x into other buffer ----
        #pragma unroll
        for (int ii = 0; ii < 8; ii++) {
            int flat = tid + ii * ENC_THREADS;
            int dd = flat >> 11, r = flat & 2047;
            int row = r >> 5, q = r & 31;
            int c = q >> 2, jj0 = (q & 3) * 2;
            int p0 = (jj0 & 3) * 2 + (jj0 >> 2);
            int p1 = ((jj0 + 1) & 3) * 2 + ((jj0 + 1) >> 2);
            unsigned* dst = &xs[(((buf ^ 1) * 2 + dd) * 64 + row) * XST + c * 8];
            dst[p0] = pack_bf16(xpre[ii].x, xpre[ii].y);
            dst[p1] = pack_bf16(xpre[ii].z, xpre[ii].w);
        }

        // ---- LSTM cell: 2048 n-pairs; warp covers one elem (both dirs) ----
        #pragma unroll
        for (int ii = 0; ii < 4; ii++) {
            int flat = tid + ii * ENC_THREADS;
            int e = flat >> 5, r = flat & 31;
            int dd = r >> 4, np = r & 15;
            int base = dd * 128 + 2 * np;
            float2 zi = *(float2*)&zs[e * ZST + base];
            float2 zf = *(float2*)&zs[e * ZST + base + 32];
            float2 zg = *(float2*)&zs[e * ZST + base + 64];
            float2 zo = *(float2*)&zs[e * ZST + base + 96];
            zi.x += bs[base];      zi.y += bs[base + 1];
            zf.x += bs[base + 32]; zf.y += bs[base + 33];
            zg.x += bs[base + 64]; zg.y += bs[base + 65];
            zo.x += bs[base + 96]; zo.y += bs[base + 97];
            float2 cold = *(float2*)&cst[dd * 2048 + e * 32 + 2 * np];
            float c0 = fsigmoid(zf.x) * cold.x + fsigmoid(zi.x) * ftanh(zg.x);
            float c1 = fsigmoid(zf.y) * cold.y + fsigmoid(zi.y) * ftanh(zg.y);
            float h0 = fsigmoid(zo.x) * ftanh(c0);
            float h1 = fsigmoid(zo.y) * ftanh(c1);
            *(float2*)&cst[dd * 2048 + e * 32 + 2 * np] = make_float2(c0, c1);
            hbf[(dd * 64 + e) * HST + (np >> 3) * 8 + ((np & 7) & 3) * 2 + ((np & 7) >> 2)]
                = pack_bf16(h0, h1);
            int tt = dd ? (TX - 1 - t) : t;
            *(float2*)(g_a + ((size_t)(b0 + e) * TX + tt) * 64 + dd * 32 + 2 * np)
                = make_float2(h0, h1);
        }
        __syncthreads();
        buf ^= 1;
    }
}

// ============================================================================
// Decoder (unchanged from R3): DBE=16, 512 threads, persistent over TY.
// ============================================================================
#define DBE 16
#define DEC_THREADS 512
#define SA_STRIDE 68
#define INSP_STRIDE 140

#define NF_SA   (DBE * TX * SA_STRIDE)
#define NF_EA   (DBE * TX * 10)
#define DEC_SMEM_FLOATS (NF_SA + NF_EA + 640 + 640 + 16 + 16 + GP + MV \
                         + DBE*NS + DBE*NS + DBE*INSP_STRIDE + DBE*GP + DBE*32 + DBE*10)

__global__ __launch_bounds__(DEC_THREADS, 1)
void decoder_kernel(const float* __restrict__ W1, const float* __restrict__ b1,
                    const float* __restrict__ W2, const float* __restrict__ b2,
                    const float* __restrict__ W_ih_p, const float* __restrict__ W_hh_p,
                    const float* __restrict__ b_p,
                    const float* __restrict__ Wo, const float* __restrict__ bo,
                    float* __restrict__ out)
{
    const int b0 = blockIdx.x * DBE;
    const int tid = threadIdx.x;

    extern __shared__ float sm[];
    float* sa   = sm;
    float* ea   = sa + NF_SA;
    float* W1a  = ea + NF_EA;
    float* W1s  = W1a + 640;
    float* b1s  = W1s + 640;
    float* W2s  = b1s + 16;
    float* bps  = W2s + 16;
    float* bos  = bps + GP;
    float* ss   = bos + MV;
    float* cc   = ss + DBE * NS;
    unsigned* insp = (unsigned*)(cc + DBE * NS);
    float* zsd  = (float*)(insp + DBE * INSP_STRIDE);
    float* alph = zsd + DBE * GP;
    float* esm  = alph + DBE * 32;

    const int warp = tid >> 5, lane = tid & 31;
    const int g = lane >> 2, tg = lane & 3;

    unsigned Bw[64];
    #pragma unroll
    for (int nt = 0; nt < 2; nt++) {
        int n = warp * 16 + nt * 8 + g;
        #pragma unroll
        for (int c = 0; c < 8; c++) {
            Bw[(nt * 16 + c) * 2 + 0] = cvt_tf32(W_ih_p[n * 64 + c * 8 + tg]);
            Bw[(nt * 16 + c) * 2 + 1] = cvt_tf32(W_ih_p[n * 64 + c * 8 + tg + 4]);
        }
        #pragma unroll
        for (int c = 0; c < 8; c++) {
            Bw[(nt * 16 + (8 + c)) * 2 + 0] = cvt_tf32(W_hh_p[n * 64 + c * 8 + tg]);
            Bw[(nt * 16 + (8 + c)) * 2 + 1] = cvt_tf32(W_hh_p[n * 64 + c * 8 + tg + 4]);
        }
    }

    const int wm = tid & 63, wkh = (tid >> 6) & 3, eh = tid >> 8;
    float wreg[16];
    #pragma unroll
    for (int kk = 0; kk < 16; kk++) wreg[kk] = Wo[wm * 64 + wkh * 16 + kk];

    for (int i = tid; i < 640; i += DEC_THREADS) {
        int j = i / 64, d = i % 64;
        W1a[i] = W1[j * 128 + d];
        W1s[i] = W1[j * 128 + 64 + d];
    }
    if (tid < 10) { b1s[tid] = b1[tid]; W2s[tid] = W2[tid]; }
    for (int i = tid; i < GP; i += DEC_THREADS) bps[i] = b_p[i];
    if (tid < MV) bos[tid] = bo[tid];
    for (int i = tid; i < DBE * NS; i += DEC_THREADS) { ss[i] = 0.0f; cc[i] = 0.0f; }
    const float b2v = b2[0];

    for (int i = tid; i < DBE * TX * (NS / 4); i += DEC_THREADS) {
        int e = i / (TX * 16);
        int r = i % (TX * 16);
        int tx = r / 16, d4 = r % 16;
        float4 v = *(const float4*)(g_a + ((size_t)(b0 + e) * TX + tx) * (2 * NA) + d4 * 4);
        *(float4*)&sa[(e * TX + tx) * SA_STRIDE + d4 * 4] = v;
    }
    __syncthreads();

    if (tid < DBE * TX) {
        int e = tid / TX, tx = tid % TX;
        const float* arow = &sa[(e * TX + tx) * SA_STRIDE];
        float acc[10];
        #pragma unroll
        for (int j = 0; j < 10; j++) acc[j] = 0.0f;
        for (int d = 0; d < 64; d++) {
            float av = arow[d];
            #pragma unroll
            for (int j = 0; j < 10; j++) acc[j] += av * W1a[j * 64 + d];
        }
        #pragma unroll
        for (int j = 0; j < 10; j++) ea[(e * TX + tx) * 10 + j] = acc[j];
    }
    __syncthreads();

    for (int t = 0; t < TY; t++) {
        if (tid < 320) {
            int e = tid / 20, r = tid % 20;
            int j = r >> 1, half = r & 1;
            float acc = 0.0f;
            const int kb = half * 32;
            #pragma unroll 8
            for (int k = 0; k < 32; k++)
                acc += ss[e * NS + kb + k] * W1s[j * 64 + kb + k];
            acc += __shfl_xor_sync(0xffffffffu, acc, 1);
            if (half == 0) esm[e * 10 + j] = acc + b1s[j];
        }
        __syncthreads();

        if (tid < DBE * TX) {
            int e = tid / TX, tx = tid % TX;
            float acc = b2v;
            #pragma unroll
            for (int j = 0; j < 10; j++)
                acc += ftanh(ea[(e * TX + tx) * 10 + j] + esm[e * 10 + j]) * W2s[j];
            alph[e * 32 + tx] = fmaxf(acc, 0.0f);
        }
        __syncthreads();

        {
            float v = (lane < TX) ? alph[warp * 32 + lane] : -1e30f;
            float mx = v;
            #pragma unroll
            for (int o = 16; o; o >>= 1) mx = fmaxf(mx, __shfl_xor_sync(0xffffffffu, mx, o));
            float ex = (lane < TX) ? __expf(v - mx) : 0.0f;
            float sum = ex;
            #pragma unroll
            for (int o = 16; o; o >>= 1) sum += __shfl_xor_sync(0xffffffffu, sum, o);
            if (lane < TX) alph[warp * 32 + lane] = ex * __fdividef(1.0f, sum);
        }
        __syncthreads();

        for (int i = tid; i < DBE * NS; i += DEC_THREADS) {
            int e = i >> 6, d = i & 63;
            float acc = 0.0f;
            #pragma unroll 5
            for (int tx = 0; tx < TX; tx++)
                acc += alph[e * 32 + tx] * sa[(e * TX + tx) * SA_STRIDE + d];
            int c = d >> 3, jj = d & 7;
            int p = (jj & 3) * 2 + (jj >> 2);
            insp[e * INSP_STRIDE + c * 8 + p]       = cvt_tf32(acc);
            insp[e * INSP_STRIDE + (8 + c) * 8 + p] = cvt_tf32(ss[i]);
        }
        __syncthreads();

        {
            float dd[2][4];
            #pragma unroll
            for (int nt = 0; nt < 2; nt++)
                #pragma unroll
                for (int r = 0; r < 4; r++) dd[nt][r] = 0.0f;
            #pragma unroll
            for (int c = 0; c < 16; c++) {
                uint2 va = *(uint2*)&insp[g * INSP_STRIDE + c * 8 + 2 * tg];
                uint2 vb = *(uint2*)&insp[(g + 8) * INSP_STRIDE + c * 8 + 2 * tg];
                unsigned a[4] = {va.x, vb.x, va.y, vb.y};
                mma_tf32(dd[0], a, Bw[(0 * 16 + c) * 2], Bw[(0 * 16 + c) * 2 + 1]);
                mma_tf32(dd[1], a, Bw[(1 * 16 + c) * 2], Bw[(1 * 16 + c) * 2 + 1]);
            }
            #pragma unroll
            for (int nt = 0; nt < 2; nt++) {
                int n0 = warp * 16 + nt * 8 + 2 * tg;
                *(float2*)&zsd[g * GP + n0]       = make_float2(dd[nt][0], dd[nt][1]);
                *(float2*)&zsd[(g + 8) * GP + n0] = make_float2(dd[nt][2], dd[nt][3]);
            }
        }
        __syncthreads();

        for (int i = tid; i < DBE * NS; i += DEC_THREADS) {
            int e = i >> 6, n = i & 63;
            float zi = zsd[e * GP + n]           + bps[n];
            float zf = zsd[e * GP + NS + n]      + bps[NS + n];
            float zg = zsd[e * GP + 2 * NS + n]  + bps[2 * NS + n];
            float zo = zsd[e * GP + 3 * NS + n]  + bps[3 * NS + n];
            float c = fsigmoid(zf) * cc[i] + fsigmoid(zi) * ftanh(zg);
            float h = fsigmoid(zo) * ftanh(c);
            cc[i] = c; ss[i] = h;
        }
        __syncthreads();

        {
            #pragma unroll
            for (int ei = 0; ei < 8; ei++) {
                int e = eh * 8 + ei;
                float p = 0.0f;
                #pragma unroll
                for (int kk = 0; kk < 16; kk++)
                    p += ss[e * NS + wkh * 16 + kk] * wreg[kk];
                zsd[(wkh * DBE + e) * 64 + wm] = p;
            }
        }
        __syncthreads();
        for (int i = tid; i < DBE * MV; i += DEC_THREADS) {
            int e = i >> 6, m = i & 63;
            float o = bos[m]
                    + zsd[(0 * DBE + e) * 64 + m] + zsd[(1 * DBE + e) * 64 + m]
                    + zsd[(2 * DBE + e) * 64 + m] + zsd[(3 * DBE + e) * 64 + m];
            out[((size_t)(b0 + e) * TY + t) * MV + m] = o;
        }
        __syncthreads();
    }
}

// ============================================================================
extern "C" void kernel_launch(void* const* d_in, const int* in_sizes, int n_in,
                              void* d_out, int out_size)
{
    const float* X      = (const float*)d_in[0];
    const float* W_ih_f = (const float*)d_in[1];
    const float* W_hh_f = (const float*)d_in[2];
    const float* b_f    = (const float*)d_in[3];
    const float* W_ih_r = (const float*)d_in[4];
    const float* W_hh_r = (const float*)d_in[5];
    const float* b_r    = (const float*)d_in[6];
    const float* W1     = (const float*)d_in[7];
    const float* b1     = (const float*)d_in[8];
    const float* W2     = (const float*)d_in[9];
    const float* b2     = (const float*)d_in[10];
    const float* W_ih_p = (const float*)d_in[11];
    const float* W_hh_p = (const float*)d_in[12];
    const float* b_p    = (const float*)d_in[13];
    const float* Wo     = (const float*)d_in[14];
    const float* bo     = (const float*)d_in[15];
    float* out = (float*)d_out;

    const int dec_smem = DEC_SMEM_FLOATS * sizeof(float);
    cudaFuncSetAttribute(encoder_fused,  cudaFuncAttributeMaxDynamicSharedMemorySize, ENC_SMEM_BYTES);
    cudaFuncSetAttribute(decoder_kernel, cudaFuncAttributeMaxDynamicSharedMemorySize, dec_smem);

    encoder_fused<<<B_TOT / EBE, ENC_THREADS, ENC_SMEM_BYTES>>>(
        X, W_ih_f, W_hh_f, b_f, W_ih_r, W_hh_r, b_r);

    decoder_kernel<<<B_TOT / DBE, DEC_THREADS, dec_smem>>>(W1, b1, W2, b2,
                                                           W_ih_p, W_hh_p, b_p, Wo, bo, out);
}

// round 6
// speedup vs baseline: 3.1775x; 1.0641x over previous
#include <cuda_runtime.h>
#include <cuda_bf16.h>
#include <math.h>

#define B_TOT 16384
#define TX 30
#define TY 10
#define NA 32
#define NS 64
#define HV 128
#define MV 64
#define GE 128   // 4*NA
#define GP 256   // 4*NS

__device__ __align__(16) float g_a[(size_t)B_TOT * TX * (2 * NA)];   // 126 MB

__device__ __forceinline__ float fsigmoid(float x) {
    return __fdividef(1.0f, 1.0f + __expf(-x));
}
__device__ __forceinline__ float ftanh(float x) {
    x = fminf(15.0f, fmaxf(-15.0f, x));
    float e = __expf(2.0f * x);
    return __fdividef(e - 1.0f, e + 1.0f);
}
__device__ __forceinline__ unsigned cvt_tf32(float x) {
    unsigned u;
    asm("cvt.rna.tf32.f32 %0, %1;" : "=r"(u) : "f"(x));
    return u;
}
__device__ __forceinline__ unsigned pack_bf16(float a, float b) {
    __nv_bfloat162 h = __floats2bfloat162_rn(a, b);
    return *(unsigned*)&h;
}
__device__ __forceinline__ void mma_tf32(float* d, const unsigned* a, unsigned b0, unsigned b1) {
    asm("mma.sync.aligned.m16n8k8.row.col.f32.tf32.tf32.f32 "
        "{%0,%1,%2,%3}, {%4,%5,%6,%7}, {%8,%9}, {%0,%1,%2,%3};"
        : "+f"(d[0]), "+f"(d[1]), "+f"(d[2]), "+f"(d[3])
        : "r"(a[0]), "r"(a[1]), "r"(a[2]), "r"(a[3]), "r"(b0), "r"(b1));
}
__device__ __forceinline__ void mma_bf16(float* d, unsigned a0, unsigned a1,
                                         unsigned a2, unsigned a3,
                                         unsigned b0, unsigned b1) {
    asm("mma.sync.aligned.m16n8k16.row.col.f32.bf16.bf16.f32 "
        "{%0,%1,%2,%3}, {%4,%5,%6,%7}, {%8,%9}, {%0,%1,%2,%3};"
        : "+f"(d[0]), "+f"(d[1]), "+f"(d[2]), "+f"(d[3])
        : "r"(a0), "r"(a1), "r"(a2), "r"(a3), "r"(b0), "r"(b1));
}

// ============================================================================
// Fused encoder (exact R4 version)
// ============================================================================
#define EBE 64
#define ENC_THREADS 512
#define XST 68
#define HST 20
#define ZST 260
#define ENC_SMEM_BYTES ((2*2*64*XST + 2*64*HST) * 4 + (64*ZST + 2*64*32 + 256) * 4)

__global__ __launch_bounds__(ENC_THREADS, 1)
void encoder_fused(const float* __restrict__ X,
                   const float* __restrict__ W_ih_f, const float* __restrict__ W_hh_f,
                   const float* __restrict__ b_f,
                   const float* __restrict__ W_ih_r, const float* __restrict__ W_hh_r,
                   const float* __restrict__ b_r)
{
    const int b0  = blockIdx.x * EBE;
    const int tid = threadIdx.x;
    const int warp = tid >> 5, lane = tid & 31;
    const int g = lane >> 2, tg = lane & 3;
    const int dir = warp >> 3;
    const int wl  = warp & 7;

    extern __shared__ unsigned smu[];
    unsigned* xs  = smu;
    unsigned* hbf = xs + 2 * 2 * 64 * XST;
    float* zs  = (float*)(hbf + 2 * 64 * HST);
    float* cst = zs + 64 * ZST;
    float* bs  = cst + 2 * 64 * 32;

    const float* Wi = dir ? W_ih_r : W_ih_f;
    const float* Wh = dir ? W_hh_r : W_hh_f;

    unsigned Bx[2][8][2], Bh[2][2][2];
    #pragma unroll
    for (int nt = 0; nt < 2; nt++) {
        int n = wl * 16 + nt * 8 + g;
        #pragma unroll
        for (int c = 0; c < 8; c++) {
            Bx[nt][c][0] = pack_bf16(Wi[n * 128 + c * 16 + 2 * tg],
                                     Wi[n * 128 + c * 16 + 2 * tg + 1]);
            Bx[nt][c][1] = pack_bf16(Wi[n * 128 + c * 16 + 8 + 2 * tg],
                                     Wi[n * 128 + c * 16 + 8 + 2 * tg + 1]);
        }
        #pragma unroll
        for (int c = 0; c < 2; c++) {
            Bh[nt][c][0] = pack_bf16(Wh[n * 32 + c * 16 + 2 * tg],
                                     Wh[n * 32 + c * 16 + 2 * tg + 1]);
            Bh[nt][c][1] = pack_bf16(Wh[n * 32 + c * 16 + 8 + 2 * tg],
                                     Wh[n * 32 + c * 16 + 8 + 2 * tg + 1]);
        }
    }

    for (int i = tid; i < 256; i += ENC_THREADS) bs[i] = (i < 128) ? b_f[i] : b_r[i - 128];
    for (int i = tid; i < 2 * 64 * HST; i += ENC_THREADS) hbf[i] = 0u;
    for (int i = tid; i < 2 * 64 * 32; i += ENC_THREADS) cst[i] = 0.0f;

    #pragma unroll
    for (int ii = 0; ii < 8; ii++) {
        int flat = tid + ii * ENC_THREADS;
        int dd = flat >> 11, r = flat & 2047;
        int row = r >> 5, q = r & 31;
        int ts = dd ? (TX - 1) : 0;
        float4 v = *(const float4*)(X + ((size_t)(b0 + row) * TX + ts) * HV + q * 4);
        int c = q >> 2, jj0 = (q & 3) * 2;
        int p0 = (jj0 & 3) * 2 + (jj0 >> 2);
        int p1 = ((jj0 + 1) & 3) * 2 + ((jj0 + 1) >> 2);
        unsigned* dst = &xs[((0 * 2 + dd) * 64 + row) * XST + c * 8];
        dst[p0] = pack_bf16(v.x, v.y);
        dst[p1] = pack_bf16(v.z, v.w);
    }
    __syncthreads();

    int buf = 0;
    for (int t = 0; t < TX; t++) {
        float4 xpre[8];
        #pragma unroll
        for (int ii = 0; ii < 8; ii++) {
            int flat = tid + ii * ENC_THREADS;
            int dd = flat >> 11, r = flat & 2047;
            int row = r >> 5, q = r & 31;
            int ts = dd ? max(TX - 2 - t, 0) : min(t + 1, TX - 1);
            xpre[ii] = *(const float4*)(X + ((size_t)(b0 + row) * TX + ts) * HV + q * 4);
        }

        float d[4][2][4];
        #pragma unroll
        for (int mi = 0; mi < 4; mi++)
            #pragma unroll
            for (int nt = 0; nt < 2; nt++)
                #pragma unroll
                for (int r = 0; r < 4; r++) d[mi][nt][r] = 0.0f;

        const unsigned* xbase = &xs[((buf * 2 + dir) * 64) * XST];
        #pragma unroll
        for (int c = 0; c < 8; c++) {
            unsigned a[4][4];
            #pragma unroll
            for (int mi = 0; mi < 4; mi++) {
                uint2 lo = *(uint2*)&xbase[(mi * 16 + g) * XST + c * 8 + 2 * tg];
                uint2 hi = *(uint2*)&xbase[(mi * 16 + 8 + g) * XST + c * 8 + 2 * tg];
                a[mi][0] = lo.x; a[mi][1] = hi.x; a[mi][2] = lo.y; a[mi][3] = hi.y;
            }
            #pragma unroll
            for (int mi = 0; mi < 4; mi++) {
                mma_bf16(d[mi][0], a[mi][0], a[mi][1], a[mi][2], a[mi][3],
                         Bx[0][c][0], Bx[0][c][1]);
                mma_bf16(d[mi][1], a[mi][0], a[mi][1], a[mi][2], a[mi][3],
                         Bx[1][c][0], Bx[1][c][1]);
            }
        }
        const unsigned* hbase = &hbf[(dir * 64) * HST];
        #pragma unroll
        for (int c = 0; c < 2; c++) {
            unsigned a[4][4];
            #pragma unroll
            for (int mi = 0; mi < 4; mi++) {
                uint2 lo = *(uint2*)&hbase[(mi * 16 + g) * HST + c * 8 + 2 * tg];
                uint2 hi = *(uint2*)&hbase[(mi * 16 + 8 + g) * HST + c * 8 + 2 * tg];
                a[mi][0] = lo.x; a[mi][1] = hi.x; a[mi][2] = lo.y; a[mi][3] = hi.y;
            }
            #pragma unroll
            for (int mi = 0; mi < 4; mi++) {
                mma_bf16(d[mi][0], a[mi][0], a[mi][1], a[mi][2], a[mi][3],
                         Bh[0][c][0], Bh[0][c][1]);
                mma_bf16(d[mi][1], a[mi][0], a[mi][1], a[mi][2], a[mi][3],
                         Bh[1][c][0], Bh[1][c][1]);
            }
        }

        #pragma unroll
        for (int mi = 0; mi < 4; mi++)
            #pragma unroll
            for (int nt = 0; nt < 2; nt++) {
                int col = dir * 128 + wl * 16 + nt * 8 + 2 * tg;
                *(float2*)&zs[(mi * 16 + g) * ZST + col] =
                    make_float2(d[mi][nt][0], d[mi][nt][1]);
                *(float2*)&zs[(mi * 16 + 8 + g) * ZST + col] =
                    make_float2(d[mi][nt][2], d[mi][nt][3]);
            }
        __syncthreads();

        #pragma unroll
        for (int ii = 0; ii < 8; ii++) {
            int flat = tid + ii * ENC_THREADS;
            int dd = flat >> 11, r = flat & 2047;
            int row = r >> 5, q = r & 31;
            int c = q >> 2, jj0 = (q & 3) * 2;
            int p0 = (jj0 & 3) * 2 + (jj0 >> 2);
            int p1 = ((jj0 + 1) & 3) * 2 + ((jj0 + 1) >> 2);
            unsigned* dst = &xs[(((buf ^ 1) * 2 + dd) * 64 + row) * XST + c * 8];
            dst[p0] = pack_bf16(xpre[ii].x, xpre[ii].y);
            dst[p1] = pack_bf16(xpre[ii].z, xpre[ii].w);
        }

        #pragma unroll
        for (int ii = 0; ii < 4; ii++) {
            int flat = tid + ii * ENC_THREADS;
            int e = flat >> 5, r = flat & 31;
            int dd = r >> 4, np = r & 15;
            int base = dd * 128 + 2 * np;
            float2 zi = *(float2*)&zs[e * ZST + base];
            float2 zf = *(float2*)&zs[e * ZST + base + 32];
            float2 zg = *(float2*)&zs[e * ZST + base + 64];
            float2 zo = *(float2*)&zs[e * ZST + base + 96];
            zi.x += bs[base];      zi.y += bs[base + 1];
            zf.x += bs[base + 32]; zf.y += bs[base + 33];
            zg.x += bs[base + 64]; zg.y += bs[base + 65];
            zo.x += bs[base + 96]; zo.y += bs[base + 97];
            float2 cold = *(float2*)&cst[dd * 2048 + e * 32 + 2 * np];
            float c0 = fsigmoid(zf.x) * cold.x + fsigmoid(zi.x) * ftanh(zg.x);
            float c1 = fsigmoid(zf.y) * cold.y + fsigmoid(zi.y) * ftanh(zg.y);
            float h0 = fsigmoid(zo.x) * ftanh(c0);
            float h1 = fsigmoid(zo.y) * ftanh(c1);
            *(float2*)&cst[dd * 2048 + e * 32 + 2 * np] = make_float2(c0, c1);
            hbf[(dd * 64 + e) * HST + (np >> 3) * 8 + ((np & 7) & 3) * 2 + ((np & 7) >> 2)]
                = pack_bf16(h0, h1);
            int tt = dd ? (TX - 1 - t) : t;
            *(float2*)(g_a + ((size_t)(b0 + e) * TX + tt) * 64 + dd * 32 + 2 * np)
                = make_float2(h0, h1);
        }
        __syncthreads();
        buf ^= 1;
    }
}

// ============================================================================
// Decoder: R4 structure, with phases A+B+C fused into one warp-per-element
// block (no esm, 6 barriers/step) and W1s padded to stride 68 for
// conflict-free float4 reads. D/E/F/G identical to R4.
// ============================================================================
#define DBE 16
#define DEC_THREADS 512
#define SA_STRIDE 68
#define W1ST 68
#define INSP_STRIDE 140

#define NF_SA   (DBE * TX * SA_STRIDE)
#define NF_EA   (DBE * TX * 10)
#define DEC_SMEM_FLOATS (NF_SA + NF_EA + 640 + 680 + 16 + 16 + GP + MV \
                         + DBE*NS + DBE*NS + DBE*INSP_STRIDE + DBE*GP + DBE*32)

__global__ __launch_bounds__(DEC_THREADS, 1)
void decoder_kernel(const float* __restrict__ W1, const float* __restrict__ b1,
                    const float* __restrict__ W2, const float* __restrict__ b2,
                    const float* __restrict__ W_ih_p, const float* __restrict__ W_hh_p,
                    const float* __restrict__ b_p,
                    const float* __restrict__ Wo, const float* __restrict__ bo,
                    float* __restrict__ out)
{
    const int b0 = blockIdx.x * DBE;
    const int tid = threadIdx.x;
    const unsigned FULL = 0xffffffffu;

    extern __shared__ float sm[];
    float* sa   = sm;
    float* ea   = sa + NF_SA;
    float* W1a  = ea + NF_EA;            // 640
    float* W1s  = W1a + 640;             // 680 (10 rows, stride 68)
    float* b1s  = W1s + 680;             // 16
    float* W2s  = b1s + 16;              // 16
    float* bps  = W2s + 16;              // 256
    float* bos  = bps + GP;              // 64
    float* ss   = bos + MV;              // 16*64
    float* cc   = ss + DBE * NS;         // 16*64
    unsigned* insp = (unsigned*)(cc + DBE * NS);       // 16*140
    float* zsd  = (float*)(insp + DBE * INSP_STRIDE);  // 16*256
    float* alph = zsd + DBE * GP;        // 16*32

    const int warp = tid >> 5, lane = tid & 31;
    const int g = lane >> 2, tg = lane & 3;

    unsigned Bw[64];
    #pragma unroll
    for (int nt = 0; nt < 2; nt++) {
        int n = warp * 16 + nt * 8 + g;
        #pragma unroll
        for (int c = 0; c < 8; c++) {
            Bw[(nt * 16 + c) * 2 + 0] = cvt_tf32(W_ih_p[n * 64 + c * 8 + tg]);
            Bw[(nt * 16 + c) * 2 + 1] = cvt_tf32(W_ih_p[n * 64 + c * 8 + tg + 4]);
        }
        #pragma unroll
        for (int c = 0; c < 8; c++) {
            Bw[(nt * 16 + (8 + c)) * 2 + 0] = cvt_tf32(W_hh_p[n * 64 + c * 8 + tg]);
            Bw[(nt * 16 + (8 + c)) * 2 + 1] = cvt_tf32(W_hh_p[n * 64 + c * 8 + tg + 4]);
        }
    }

    const int wm = tid & 63, wkh = (tid >> 6) & 3, eh = tid >> 8;
    float wreg[16];
    #pragma unroll
    for (int kk = 0; kk < 16; kk++) wreg[kk] = Wo[wm * 64 + wkh * 16 + kk];

    for (int i = tid; i < 640; i += DEC_THREADS) {
        int j = i / 64, d = i % 64;
        W1a[i]            = W1[j * 128 + d];
        W1s[j * W1ST + d] = W1[j * 128 + 64 + d];
    }
    if (tid < 10) { b1s[tid] = b1[tid]; W2s[tid] = W2[tid]; }
    for (int i = tid; i < GP; i += DEC_THREADS) bps[i] = b_p[i];
    if (tid < MV) bos[tid] = bo[tid];
    for (int i = tid; i < DBE * NS; i += DEC_THREADS) { ss[i] = 0.0f; cc[i] = 0.0f; }
    const float b2v = b2[0];

    for (int i = tid; i < DBE * TX * (NS / 4); i += DEC_THREADS) {
        int e = i / (TX * 16);
        int r = i % (TX * 16);
        int tx = r / 16, d4 = r % 16;
        float4 v = *(const float4*)(g_a + ((size_t)(b0 + e) * TX + tx) * (2 * NA) + d4 * 4);
        *(float4*)&sa[(e * TX + tx) * SA_STRIDE + d4 * 4] = v;
    }
    __syncthreads();

    if (tid < DBE * TX) {
        int e = tid / TX, tx = tid % TX;
        const float* arow = &sa[(e * TX + tx) * SA_STRIDE];
        float acc[10];
        #pragma unroll
        for (int j = 0; j < 10; j++) acc[j] = 0.0f;
        for (int d = 0; d < 64; d++) {
            float av = arow[d];
            #pragma unroll
            for (int j = 0; j < 10; j++) acc[j] += av * W1a[j * 64 + d];
        }
        #pragma unroll
        for (int j = 0; j < 10; j++) ea[(e * TX + tx) * 10 + j] = acc[j];
    }
    __syncthreads();

    for (int t = 0; t < TY; t++) {
        // ---- A+B+C fused: warp e handles element e ----
        {
            const int e = warp;
            // A: es_j partials on lanes 0..19 (j = lane>>1, half = lane&1)
            float accA = 0.0f;
            if (lane < 20) {
                int j = lane >> 1, half = lane & 1;
                const float4* sp = (const float4*)&ss[e * NS + half * 32];
                const float4* wp = (const float4*)&W1s[j * W1ST + half * 32];
                #pragma unroll
                for (int q = 0; q < 8; q++) {
                    float4 sv = sp[q], wv = wp[q];
                    accA += sv.x * wv.x + sv.y * wv.y + sv.z * wv.z + sv.w * wv.w;
                }
            }
            accA += __shfl_xor_sync(FULL, accA, 1);
            if (lane < 20) accA += b1s[lane >> 1];

            // B: en = relu(tanh(ea + es) @ W2 + b2), lane = tx
            int txc = (lane < TX) ? lane : 0;
            float acc = b2v;
            #pragma unroll
            for (int j = 0; j < 10; j++) {
                float esj = __shfl_sync(FULL, accA, 2 * j);
                acc += ftanh(ea[(e * TX + txc) * 10 + j] + esj) * W2s[j];
            }
            float en = (lane < TX) ? fmaxf(acc, 0.0f) : -1e30f;

            // C: softmax over lanes
            float mx = en;
            #pragma unroll
            for (int o = 16; o; o >>= 1) mx = fmaxf(mx, __shfl_xor_sync(FULL, mx, o));
            float ex = (lane < TX) ? __expf(en - mx) : 0.0f;
            float sum = ex;
            #pragma unroll
            for (int o = 16; o; o >>= 1) sum += __shfl_xor_sync(FULL, sum, o);
            alph[e * 32 + lane] = ex * __fdividef(1.0f, sum);
        }
        __syncthreads();

        // ---- D: context + s -> insp (tf32, permuted) — exact R4 ----
        for (int i = tid; i < DBE * NS; i += DEC_THREADS) {
            int e = i >> 6, d = i & 63;
            float acc = 0.0f;
            #pragma unroll 5
            for (int tx = 0; tx < TX; tx++)
                acc += alph[e * 32 + tx] * sa[(e * TX + tx) * SA_STRIDE + d];
            int c = d >> 3, jj = d & 7;
            int p = (jj & 3) * 2 + (jj >> 2);
            insp[e * INSP_STRIDE + c * 8 + p]       = cvt_tf32(acc);
            insp[e * INSP_STRIDE + (8 + c) * 8 + p] = cvt_tf32(ss[i]);
        }
        __syncthreads();

        // ---- E: gate GEMM via tf32 mma — exact R4 ----
        {
            float dd[2][4];
            #pragma unroll
            for (int nt = 0; nt < 2; nt++)
                #pragma unroll
                for (int r = 0; r < 4; r++) dd[nt][r] = 0.0f;
            #pragma unroll
            for (int c = 0; c < 16; c++) {
                uint2 va = *(uint2*)&insp[g * INSP_STRIDE + c * 8 + 2 * tg];
                uint2 vb = *(uint2*)&insp[(g + 8) * INSP_STRIDE + c * 8 + 2 * tg];
                unsigned a[4] = {va.x, vb.x, va.y, vb.y};
                mma_tf32(dd[0], a, Bw[(0 * 16 + c) * 2], Bw[(0 * 16 + c) * 2 + 1]);
                mma_tf32(dd[1], a, Bw[(1 * 16 + c) * 2], Bw[(1 * 16 + c) * 2 + 1]);
            }
            #pragma unroll
            for (int nt = 0; nt < 2; nt++) {
                int n0 = warp * 16 + nt * 8 + 2 * tg;
                *(float2*)&zsd[g * GP + n0]       = make_float2(dd[nt][0], dd[nt][1]);
                *(float2*)&zsd[(g + 8) * GP + n0] = make_float2(dd[nt][2], dd[nt][3]);
            }
        }
        __syncthreads();

        // ---- F: LSTM cell — exact R4 ----
        for (int i = tid; i < DBE * NS; i += DEC_THREADS) {
            int e = i >> 6, n = i & 63;
            float zi = zsd[e * GP + n]           + bps[n];
            float zf = zsd[e * GP + NS + n]      + bps[NS + n];
            float zg = zsd[e * GP + 2 * NS + n]  + bps[2 * NS + n];
            float zo = zsd[e * GP + 3 * NS + n]  + bps[3 * NS + n];
            float c = fsigmoid(zf) * cc[i] + fsigmoid(zi) * ftanh(zg);
            float h = fsigmoid(zo) * ftanh(c);
            cc[i] = c; ss[i] = h;
        }
        __syncthreads();

        // ---- G: out partials — exact R4 ----
        {
            #pragma unroll
            for (int ei = 0; ei < 8; ei++) {
                int e = eh * 8 + ei;
                float p = 0.0f;
                #pragma unroll
                for (int kk = 0; kk < 16; kk++)
                    p += ss[e * NS + wkh * 16 + kk] * wreg[kk];
                zsd[(wkh * DBE + e) * 64 + wm] = p;
            }
        }
        __syncthreads();
        for (int i = tid; i < DBE * MV; i += DEC_THREADS) {
            int e = i >> 6, m = i & 63;
            float o = bos[m]
                    + zsd[(0 * DBE + e) * 64 + m] + zsd[(1 * DBE + e) * 64 + m]
                    + zsd[(2 * DBE + e) * 64 + m] + zsd[(3 * DBE + e) * 64 + m];
            out[((size_t)(b0 + e) * TY + t) * MV + m] = o;
        }
        __syncthreads();
    }
}

// ============================================================================
extern "C" void kernel_launch(void* const* d_in, const int* in_sizes, int n_in,
                              void* d_out, int out_size)
{
    const float* X      = (const float*)d_in[0];
    const float* W_ih_f = (const float*)d_in[1];
    const float* W_hh_f = (const float*)d_in[2];
    const float* b_f    = (const float*)d_in[3];
    const float* W_ih_r = (const float*)d_in[4];
    const float* W_hh_r = (const float*)d_in[5];
    const float* b_r    = (const float*)d_in[6];
    const float* W1     = (const float*)d_in[7];
    const float* b1     = (const float*)d_in[8];
    const float* W2     = (const float*)d_in[9];
    const float* b2     = (const float*)d_in[10];
    const float* W_ih_p = (const float*)d_in[11];
    const float* W_hh_p = (const float*)d_in[12];
    const float* b_p    = (const float*)d_in[13];
    const float* Wo     = (const float*)d_in[14];
    const float* bo     = (const float*)d_in[15];
    float* out = (float*)d_out;

    const int dec_smem = DEC_SMEM_FLOATS * sizeof(float);
    cudaFuncSetAttribute(encoder_fused,  cudaFuncAttributeMaxDynamicSharedMemorySize, ENC_SMEM_BYTES);
    cudaFuncSetAttribute(decoder_kernel, cudaFuncAttributeMaxDynamicSharedMemorySize, dec_smem);

    encoder_fused<<<B_TOT / EBE, ENC_THREADS, ENC_SMEM_BYTES>>>(
        X, W_ih_f, W_hh_f, b_f, W_ih_r, W_hh_r, b_r);

    decoder_kernel<<<B_TOT / DBE, DEC_THREADS, dec_smem>>>(W1, b1, W2, b2,
                                                           W_ih_p, W_hh_p, b_p, Wo, bo, out);
}

// round 7
// speedup vs baseline: 3.3943x; 1.0683x over previous
#include <cuda_runtime.h>
#include <cuda_bf16.h>
#include <math.h>

#define B_TOT 16384
#define TX 30
#define TY 10
#define NA 32
#define NS 64
#define HV 128
#define MV 64
#define GE 128   // 4*NA
#define GP 256   // 4*NS

__device__ __align__(16) float g_a[(size_t)B_TOT * TX * (2 * NA)];   // 126 MB

__device__ __forceinline__ float fsigmoid(float x) {
    return __fdividef(1.0f, 1.0f + __expf(-x));
}
__device__ __forceinline__ float ftanh(float x) {
    x = fminf(15.0f, fmaxf(-15.0f, x));
    float e = __expf(2.0f * x);
    return __fdividef(e - 1.0f, e + 1.0f);
}
__device__ __forceinline__ float tanhapx(float x) {
    float y;
    asm("tanh.approx.f32 %0, %1;" : "=f"(y) : "f"(x));
    return y;
}
__device__ __forceinline__ float sigapx(float x) {
    return fmaf(tanhapx(0.5f * x), 0.5f, 0.5f);
}
__device__ __forceinline__ unsigned cvt_tf32(float x) {
    unsigned u;
    asm("cvt.rna.tf32.f32 %0, %1;" : "=r"(u) : "f"(x));
    return u;
}
__device__ __forceinline__ unsigned pack_bf16(float a, float b) {
    __nv_bfloat162 h = __floats2bfloat162_rn(a, b);
    return *(unsigned*)&h;
}
__device__ __forceinline__ void mma_tf32(float* d, const unsigned* a, unsigned b0, unsigned b1) {
    asm("mma.sync.aligned.m16n8k8.row.col.f32.tf32.tf32.f32 "
        "{%0,%1,%2,%3}, {%4,%5,%6,%7}, {%8,%9}, {%0,%1,%2,%3};"
        : "+f"(d[0]), "+f"(d[1]), "+f"(d[2]), "+f"(d[3])
        : "r"(a[0]), "r"(a[1]), "r"(a[2]), "r"(a[3]), "r"(b0), "r"(b1));
}
__device__ __forceinline__ void mma_bf16(float* d, unsigned a0, unsigned a1,
                                         unsigned a2, unsigned a3,
                                         unsigned b0, unsigned b1) {
    asm("mma.sync.aligned.m16n8k16.row.col.f32.bf16.bf16.f32 "
        "{%0,%1,%2,%3}, {%4,%5,%6,%7}, {%8,%9}, {%0,%1,%2,%3};"
        : "+f"(d[0]), "+f"(d[1]), "+f"(d[2]), "+f"(d[3])
        : "r"(a0), "r"(a1), "r"(a2), "r"(a3), "r"(b0), "r"(b1));
}

// ============================================================================
// Fused encoder (R6 structure; cell uses approx transcendentals)
// ============================================================================
#define EBE 64
#define ENC_THREADS 512
#define XST 68
#define HST 20
#define ZST 260
#define ENC_SMEM_BYTES ((2*2*64*XST + 2*64*HST) * 4 + (64*ZST + 2*64*32 + 256) * 4)

__global__ __launch_bounds__(ENC_THREADS, 1)
void encoder_fused(const float* __restrict__ X,
                   const float* __restrict__ W_ih_f, const float* __restrict__ W_hh_f,
                   const float* __restrict__ b_f,
                   const float* __restrict__ W_ih_r, const float* __restrict__ W_hh_r,
                   const float* __restrict__ b_r)
{
    const int b0  = blockIdx.x * EBE;
    const int tid = threadIdx.x;
    const int warp = tid >> 5, lane = tid & 31;
    const int g = lane >> 2, tg = lane & 3;
    const int dir = warp >> 3;
    const int wl  = warp & 7;

    extern __shared__ unsigned smu[];
    unsigned* xs  = smu;
    unsigned* hbf = xs + 2 * 2 * 64 * XST;
    float* zs  = (float*)(hbf + 2 * 64 * HST);
    float* cst = zs + 64 * ZST;
    float* bs  = cst + 2 * 64 * 32;

    const float* Wi = dir ? W_ih_r : W_ih_f;
    const float* Wh = dir ? W_hh_r : W_hh_f;

    unsigned Bx[2][8][2], Bh[2][2][2];
    #pragma unroll
    for (int nt = 0; nt < 2; nt++) {
        int n = wl * 16 + nt * 8 + g;
        #pragma unroll
        for (int c = 0; c < 8; c++) {
            Bx[nt][c][0] = pack_bf16(Wi[n * 128 + c * 16 + 2 * tg],
                                     Wi[n * 128 + c * 16 + 2 * tg + 1]);
            Bx[nt][c][1] = pack_bf16(Wi[n * 128 + c * 16 + 8 + 2 * tg],
                                     Wi[n * 128 + c * 16 + 8 + 2 * tg + 1]);
        }
        #pragma unroll
        for (int c = 0; c < 2; c++) {
            Bh[nt][c][0] = pack_bf16(Wh[n * 32 + c * 16 + 2 * tg],
                                     Wh[n * 32 + c * 16 + 2 * tg + 1]);
            Bh[nt][c][1] = pack_bf16(Wh[n * 32 + c * 16 + 8 + 2 * tg],
                                     Wh[n * 32 + c * 16 + 8 + 2 * tg + 1]);
        }
    }

    for (int i = tid; i < 256; i += ENC_THREADS) bs[i] = (i < 128) ? b_f[i] : b_r[i - 128];
    for (int i = tid; i < 2 * 64 * HST; i += ENC_THREADS) hbf[i] = 0u;
    for (int i = tid; i < 2 * 64 * 32; i += ENC_THREADS) cst[i] = 0.0f;

    #pragma unroll
    for (int ii = 0; ii < 8; ii++) {
        int flat = tid + ii * ENC_THREADS;
        int dd = flat >> 11, r = flat & 2047;
        int row = r >> 5, q = r & 31;
        int ts = dd ? (TX - 1) : 0;
        float4 v = *(const float4*)(X + ((size_t)(b0 + row) * TX + ts) * HV + q * 4);
        int c = q >> 2, jj0 = (q & 3) * 2;
        int p0 = (jj0 & 3) * 2 + (jj0 >> 2);
        int p1 = ((jj0 + 1) & 3) * 2 + ((jj0 + 1) >> 2);
        unsigned* dst = &xs[((0 * 2 + dd) * 64 + row) * XST + c * 8];
        dst[p0] = pack_bf16(v.x, v.y);
        dst[p1] = pack_bf16(v.z, v.w);
    }
    __syncthreads();

    int buf = 0;
    for (int t = 0; t < TX; t++) {
        float4 xpre[8];
        #pragma unroll
        for (int ii = 0; ii < 8; ii++) {
            int flat = tid + ii * ENC_THREADS;
            int dd = flat >> 11, r = flat & 2047;
            int row = r >> 5, q = r & 31;
            int ts = dd ? max(TX - 2 - t, 0) : min(t + 1, TX - 1);
            xpre[ii] = *(const float4*)(X + ((size_t)(b0 + row) * TX + ts) * HV + q * 4);
        }

        float d[4][2][4];
        #pragma unroll
        for (int mi = 0; mi < 4; mi++)
            #pragma unroll
            for (int nt = 0; nt < 2; nt++)
                #pragma unroll
                for (int r = 0; r < 4; r++) d[mi][nt][r] = 0.0f;

        const unsigned* xbase = &xs[((buf * 2 + dir) * 64) * XST];
        #pragma unroll
        for (int c = 0; c < 8; c++) {
            unsigned a[4][4];
            #pragma unroll
            for (int mi = 0; mi < 4; mi++) {
                uint2 lo = *(uint2*)&xbase[(mi * 16 + g) * XST + c * 8 + 2 * tg];
                uint2 hi = *(uint2*)&xbase[(mi * 16 + 8 + g) * XST + c * 8 + 2 * tg];
                a[mi][0] = lo.x; a[mi][1] = hi.x; a[mi][2] = lo.y; a[mi][3] = hi.y;
            }
            #pragma unroll
            for (int mi = 0; mi < 4; mi++) {
                mma_bf16(d[mi][0], a[mi][0], a[mi][1], a[mi][2], a[mi][3],
                         Bx[0][c][0], Bx[0][c][1]);
                mma_bf16(d[mi][1], a[mi][0], a[mi][1], a[mi][2], a[mi][3],
                         Bx[1][c][0], Bx[1][c][1]);
            }
        }
        const unsigned* hbase = &hbf[(dir * 64) * HST];
        #pragma unroll
        for (int c = 0; c < 2; c++) {
            unsigned a[4][4];
            #pragma unroll
            for (int mi = 0; mi < 4; mi++) {
                uint2 lo = *(uint2*)&hbase[(mi * 16 + g) * HST + c * 8 + 2 * tg];
                uint2 hi = *(uint2*)&hbase[(mi * 16 + 8 + g) * HST + c * 8 + 2 * tg];
                a[mi][0] = lo.x; a[mi][1] = hi.x; a[mi][2] = lo.y; a[mi][3] = hi.y;
            }
            #pragma unroll
            for (int mi = 0; mi < 4; mi++) {
                mma_bf16(d[mi][0], a[mi][0], a[mi][1], a[mi][2], a[mi][3],
                         Bh[0][c][0], Bh[0][c][1]);
                mma_bf16(d[mi][1], a[mi][0], a[mi][1], a[mi][2], a[mi][3],
                         Bh[1][c][0], Bh[1][c][1]);
            }
        }

        #pragma unroll
        for (int mi = 0; mi < 4; mi++)
            #pragma unroll
            for (int nt = 0; nt < 2; nt++) {
                int col = dir * 128 + wl * 16 + nt * 8 + 2 * tg;
                *(float2*)&zs[(mi * 16 + g) * ZST + col] =
                    make_float2(d[mi][nt][0], d[mi][nt][1]);
                *(float2*)&zs[(mi * 16 + 8 + g) * ZST + col] =
                    make_float2(d[mi][nt][2], d[mi][nt][3]);
            }
        __syncthreads();

        #pragma unroll
        for (int ii = 0; ii < 8; ii++) {
            int flat = tid + ii * ENC_THREADS;
            int dd = flat >> 11, r = flat & 2047;
            int row = r >> 5, q = r & 31;
            int c = q >> 2, jj0 = (q & 3) * 2;
            int p0 = (jj0 & 3) * 2 + (jj0 >> 2);
            int p1 = ((jj0 + 1) & 3) * 2 + ((jj0 + 1) >> 2);
            unsigned* dst = &xs[(((buf ^ 1) * 2 + dd) * 64 + row) * XST + c * 8];
            dst[p0] = pack_bf16(xpre[ii].x, xpre[ii].y);
            dst[p1] = pack_bf16(xpre[ii].z, xpre[ii].w);
        }

        #pragma unroll
        for (int ii = 0; ii < 4; ii++) {
            int flat = tid + ii * ENC_THREADS;
            int e = flat >> 5, r = flat & 31;
            int dd = r >> 4, np = r & 15;
            int base = dd * 128 + 2 * np;
            float2 zi = *(float2*)&zs[e * ZST + base];
            float2 zf = *(float2*)&zs[e * ZST + base + 32];
            float2 zg = *(float2*)&zs[e * ZST + base + 64];
            float2 zo = *(float2*)&zs[e * ZST + base + 96];
            zi.x += bs[base];      zi.y += bs[base + 1];
            zf.x += bs[base + 32]; zf.y += bs[base + 33];
            zg.x += bs[base + 64]; zg.y += bs[base + 65];
            zo.x += bs[base + 96]; zo.y += bs[base + 97];
            float2 cold = *(float2*)&cst[dd * 2048 + e * 32 + 2 * np];
            float c0 = sigapx(zf.x) * cold.x + sigapx(zi.x) * tanhapx(zg.x);
            float c1 = sigapx(zf.y) * cold.y + sigapx(zi.y) * tanhapx(zg.y);
            float h0 = sigapx(zo.x) * tanhapx(c0);
            float h1 = sigapx(zo.y) * tanhapx(c1);
            *(float2*)&cst[dd * 2048 + e * 32 + 2 * np] = make_float2(c0, c1);
            hbf[(dd * 64 + e) * HST + (np >> 3) * 8 + ((np & 7) & 3) * 2 + ((np & 7) >> 2)]
                = pack_bf16(h0, h1);
            int tt = dd ? (TX - 1 - t) : t;
            *(float2*)(g_a + ((size_t)(b0 + e) * TX + tt) * 64 + dd * 32 + 2 * np)
                = make_float2(h0, h1);
        }
        __syncthreads();
        buf ^= 1;
    }
}

// ============================================================================
// Decoder: R6 structure; D = pair-per-thread float2, G = float4 ss reads.
// ============================================================================
#define DBE 16
#define DEC_THREADS 512
#define SA_STRIDE 68
#define W1ST 68
#define INSP_STRIDE 140

#define NF_SA   (DBE * TX * SA_STRIDE)
#define NF_EA   (DBE * TX * 10)
#define DEC_SMEM_FLOATS (NF_SA + NF_EA + 640 + 680 + 16 + 16 + GP + MV \
                         + DBE*NS + DBE*NS + DBE*INSP_STRIDE + DBE*GP + DBE*32)

__global__ __launch_bounds__(DEC_THREADS, 1)
void decoder_kernel(const float* __restrict__ W1, const float* __restrict__ b1,
                    const float* __restrict__ W2, const float* __restrict__ b2,
                    const float* __restrict__ W_ih_p, const float* __restrict__ W_hh_p,
                    const float* __restrict__ b_p,
                    const float* __restrict__ Wo, const float* __restrict__ bo,
                    float* __restrict__ out)
{
    const int b0 = blockIdx.x * DBE;
    const int tid = threadIdx.x;
    const unsigned FULL = 0xffffffffu;

    extern __shared__ float sm[];
    float* sa   = sm;
    float* ea   = sa + NF_SA;
    float* W1a  = ea + NF_EA;
    float* W1s  = W1a + 640;
    float* b1s  = W1s + 680;
    float* W2s  = b1s + 16;
    float* bps  = W2s + 16;
    float* bos  = bps + GP;
    float* ss   = bos + MV;
    float* cc   = ss + DBE * NS;
    unsigned* insp = (unsigned*)(cc + DBE * NS);
    float* zsd  = (float*)(insp + DBE * INSP_STRIDE);
    float* alph = zsd + DBE * GP;

    const int warp = tid >> 5, lane = tid & 31;
    const int g = lane >> 2, tg = lane & 3;

    unsigned Bw[64];
    #pragma unroll
    for (int nt = 0; nt < 2; nt++) {
        int n = warp * 16 + nt * 8 + g;
        #pragma unroll
        for (int c = 0; c < 8; c++) {
            Bw[(nt * 16 + c) * 2 + 0] = cvt_tf32(W_ih_p[n * 64 + c * 8 + tg]);
            Bw[(nt * 16 + c) * 2 + 1] = cvt_tf32(W_ih_p[n * 64 + c * 8 + tg + 4]);
        }
        #pragma unroll
        for (int c = 0; c < 8; c++) {
            Bw[(nt * 16 + (8 + c)) * 2 + 0] = cvt_tf32(W_hh_p[n * 64 + c * 8 + tg]);
            Bw[(nt * 16 + (8 + c)) * 2 + 1] = cvt_tf32(W_hh_p[n * 64 + c * 8 + tg + 4]);
        }
    }

    const int wm = tid & 63, wkh = (tid >> 6) & 3, eh = tid >> 8;
    float wreg[16];
    #pragma unroll
    for (int kk = 0; kk < 16; kk++) wreg[kk] = Wo[wm * 64 + wkh * 16 + kk];

    for (int i = tid; i < 640; i += DEC_THREADS) {
        int j = i / 64, d = i % 64;
        W1a[i]            = W1[j * 128 + d];
        W1s[j * W1ST + d] = W1[j * 128 + 64 + d];
    }
    if (tid < 10) { b1s[tid] = b1[tid]; W2s[tid] = W2[tid]; }
    for (int i = tid; i < GP; i += DEC_THREADS) bps[i] = b_p[i];
    if (tid < MV) bos[tid] = bo[tid];
    for (int i = tid; i < DBE * NS; i += DEC_THREADS) { ss[i] = 0.0f; cc[i] = 0.0f; }
    const float b2v = b2[0];

    for (int i = tid; i < DBE * TX * (NS / 4); i += DEC_THREADS) {
        int e = i / (TX * 16);
        int r = i % (TX * 16);
        int tx = r / 16, d4 = r % 16;
        float4 v = *(const float4*)(g_a + ((size_t)(b0 + e) * TX + tx) * (2 * NA) + d4 * 4);
        *(float4*)&sa[(e * TX + tx) * SA_STRIDE + d4 * 4] = v;
    }
    __syncthreads();

    if (tid < DBE * TX) {
        int e = tid / TX, tx = tid % TX;
        const float* arow = &sa[(e * TX + tx) * SA_STRIDE];
        float acc[10];
        #pragma unroll
        for (int j = 0; j < 10; j++) acc[j] = 0.0f;
        for (int d = 0; d < 64; d++) {
            float av = arow[d];
            #pragma unroll
            for (int j = 0; j < 10; j++) acc[j] += av * W1a[j * 64 + d];
        }
        #pragma unroll
        for (int j = 0; j < 10; j++) ea[(e * TX + tx) * 10 + j] = acc[j];
    }
    __syncthreads();

    for (int t = 0; t < TY; t++) {
        // ---- A+B+C fused: warp e handles element e ----
        {
            const int e = warp;
            float accA = 0.0f;
            if (lane < 20) {
                int j = lane >> 1, half = lane & 1;
                const float4* sp = (const float4*)&ss[e * NS + half * 32];
                const float4* wp = (const float4*)&W1s[j * W1ST + half * 32];
                #pragma unroll
                for (int q = 0; q < 8; q++) {
                    float4 sv = sp[q], wv = wp[q];
                    accA += sv.x * wv.x + sv.y * wv.y + sv.z * wv.z + sv.w * wv.w;
                }
            }
            accA += __shfl_xor_sync(FULL, accA, 1);
            if (lane < 20) accA += b1s[lane >> 1];

            int txc = (lane < TX) ? lane : 0;
            float acc = b2v;
            #pragma unroll
            for (int j = 0; j < 10; j++) {
                float esj = __shfl_sync(FULL, accA, 2 * j);
                acc += ftanh(ea[(e * TX + txc) * 10 + j] + esj) * W2s[j];
            }
            float en = (lane < TX) ? fmaxf(acc, 0.0f) : -1e30f;

            float mx = en;
            #pragma unroll
            for (int o = 16; o; o >>= 1) mx = fmaxf(mx, __shfl_xor_sync(FULL, mx, o));
            float ex = (lane < TX) ? __expf(en - mx) : 0.0f;
            float sum = ex;
            #pragma unroll
            for (int o = 16; o; o >>= 1) sum += __shfl_xor_sync(FULL, sum, o);
            alph[e * 32 + lane] = ex * __fdividef(1.0f, sum);
        }
        __syncthreads();

        // ---- D: context pair-per-thread (float2) -> insp ----
        {
            const int e = tid >> 5, d0 = (tid & 31) * 2;
            const float* ap = &alph[e * 32];
            float ctx0 = 0.0f, ctx1 = 0.0f;
            #pragma unroll 5
            for (int tx = 0; tx < TX; tx++) {
                float al = ap[tx];
                float2 sv = *(const float2*)&sa[(e * TX + tx) * SA_STRIDE + d0];
                ctx0 += al * sv.x;
                ctx1 += al * sv.y;
            }
            int c = d0 >> 3, jj0 = d0 & 7;
            int p0 = (jj0 & 3) * 2 + (jj0 >> 2);
            int p1 = ((jj0 + 1) & 3) * 2 + ((jj0 + 1) >> 2);
            insp[e * INSP_STRIDE + c * 8 + p0] = cvt_tf32(ctx0);
            insp[e * INSP_STRIDE + c * 8 + p1] = cvt_tf32(ctx1);
            float2 sv = *(const float2*)&ss[e * NS + d0];
            insp[e * INSP_STRIDE + (8 + c) * 8 + p0] = cvt_tf32(sv.x);
            insp[e * INSP_STRIDE + (8 + c) * 8 + p1] = cvt_tf32(sv.y);
        }
        __syncthreads();

        // ---- E: gate GEMM via tf32 mma ----
        {
            float dd[2][4];
            #pragma unroll
            for (int nt = 0; nt < 2; nt++)
                #pragma unroll
                for (int r = 0; r < 4; r++) dd[nt][r] = 0.0f;
            #pragma unroll
            for (int c = 0; c < 16; c++) {
                uint2 va = *(uint2*)&insp[g * INSP_STRIDE + c * 8 + 2 * tg];
                uint2 vb = *(uint2*)&insp[(g + 8) * INSP_STRIDE + c * 8 + 2 * tg];
                unsigned a[4] = {va.x, vb.x, va.y, vb.y};
                mma_tf32(dd[0], a, Bw[(0 * 16 + c) * 2], Bw[(0 * 16 + c) * 2 + 1]);
                mma_tf32(dd[1], a, Bw[(1 * 16 + c) * 2], Bw[(1 * 16 + c) * 2 + 1]);
            }
            #pragma unroll
            for (int nt = 0; nt < 2; nt++) {
                int n0 = warp * 16 + nt * 8 + 2 * tg;
                *(float2*)&zsd[g * GP + n0]       = make_float2(dd[nt][0], dd[nt][1]);
                *(float2*)&zsd[(g + 8) * GP + n0] = make_float2(dd[nt][2], dd[nt][3]);
            }
        }
        __syncthreads();

        // ---- F: LSTM cell (exact transcendentals) ----
        for (int i = tid; i < DBE * NS; i += DEC_THREADS) {
            int e = i >> 6, n = i & 63;
            float zi = zsd[e * GP + n]           + bps[n];
            float zf = zsd[e * GP + NS + n]      + bps[NS + n];
            float zg = zsd[e * GP + 2 * NS + n]  + bps[2 * NS + n];
            float zo = zsd[e * GP + 3 * NS + n]  + bps[3 * NS + n];
            float c = fsigmoid(zf) * cc[i] + fsigmoid(zi) * ftanh(zg);
            float h = fsigmoid(zo) * ftanh(c);
            cc[i] = c; ss[i] = h;
        }
        __syncthreads();

        // ---- G: out partials via float4 ss reads ----
        {
            #pragma unroll
            for (int ei = 0; ei < 8; ei++) {
                int e = eh * 8 + ei;
                const float4* sp = (const float4*)&ss[e * NS + wkh * 16];
                float p = 0.0f;
                #pragma unroll
                for (int q = 0; q < 4; q++) {
                    float4 sv = sp[q];
                    p += sv.x * wreg[4 * q]     + sv.y * wreg[4 * q + 1]
                       + sv.z * wreg[4 * q + 2] + sv.w * wreg[4 * q + 3];
                }
                zsd[(wkh * DBE + e) * 64 + wm] = p;
            }
        }
        __syncthreads();
        for (int i = tid; i < DBE * MV; i += DEC_THREADS) {
            int e = i >> 6, m = i & 63;
            float o = bos[m]
                    + zsd[(0 * DBE + e) * 64 + m] + zsd[(1 * DBE + e) * 64 + m]
                    + zsd[(2 * DBE + e) * 64 + m] + zsd[(3 * DBE + e) * 64 + m];
            out[((size_t)(b0 + e) * TY + t) * MV + m] = o;
        }
        __syncthreads();
    }
}

// ============================================================================
extern "C" void kernel_launch(void* const* d_in, const int* in_sizes, int n_in,
                              void* d_out, int out_size)
{
    const float* X      = (const float*)d_in[0];
    const float* W_ih_f = (const float*)d_in[1];
    const float* W_hh_f = (const float*)d_in[2];
    const float* b_f    = (const float*)d_in[3];
    const float* W_ih_r = (const float*)d_in[4];
    const float* W_hh_r = (const float*)d_in[5];
    const float* b_r    = (const float*)d_in[6];
    const float* W1     = (const float*)d_in[7];
    const float* b1     = (const float*)d_in[8];
    const float* W2     = (const float*)d_in[9];
    const float* b2     = (const float*)d_in[10];
    const float* W_ih_p = (const float*)d_in[11];
    const float* W_hh_p = (const float*)d_in[12];
    const float* b_p    = (const float*)d_in[13];
    const float* Wo     = (const float*)d_in[14];
    const float* bo     = (const float*)d_in[15];
    float* out = (float*)d_out;

    const int dec_smem = DEC_SMEM_FLOATS * sizeof(float);
    cudaFuncSetAttribute(encoder_fused,  cudaFuncAttributeMaxDynamicSharedMemorySize, ENC_SMEM_BYTES);
    cudaFuncSetAttribute(decoder_kernel, cudaFuncAttributeMaxDynamicSharedMemorySize, dec_smem);

    encoder_fused<<<B_TOT / EBE, ENC_THREADS, ENC_SMEM_BYTES>>>(
        X, W_ih_f, W_hh_f, b_f, W_ih_r, W_hh_r, b_r);

    decoder_kernel<<<B_TOT / DBE, DEC_THREADS, dec_smem>>>(W1, b1, W2, b2,
                                                           W_ih_p, W_hh_p, b_p, Wo, bo, out);
}

// round 8
// speedup vs baseline: 3.5256x; 1.0387x over previous
#include <cuda_runtime.h>
#include <cuda_bf16.h>
#include <math.h>

#define B_TOT 16384
#define TX 30
#define TY 10
#define NA 32
#define NS 64
#define HV 128
#define MV 64
#define GE 128   // 4*NA
#define GP 256   // 4*NS

__device__ __align__(16) float g_a[(size_t)B_TOT * TX * (2 * NA)];   // 126 MB

__device__ __forceinline__ float tanhapx(float x) {
    float y;
    asm("tanh.approx.f32 %0, %1;" : "=f"(y) : "f"(x));
    return y;
}
__device__ __forceinline__ float sigapx(float x) {
    return fmaf(tanhapx(0.5f * x), 0.5f, 0.5f);
}
__device__ __forceinline__ unsigned cvt_tf32(float x) {
    unsigned u;
    asm("cvt.rna.tf32.f32 %0, %1;" : "=r"(u) : "f"(x));
    return u;
}
__device__ __forceinline__ unsigned pack_bf16(float a, float b) {
    __nv_bfloat162 h = __floats2bfloat162_rn(a, b);
    return *(unsigned*)&h;
}
__device__ __forceinline__ void mma_tf32(float* d, const unsigned* a, unsigned b0, unsigned b1) {
    asm("mma.sync.aligned.m16n8k8.row.col.f32.tf32.tf32.f32 "
        "{%0,%1,%2,%3}, {%4,%5,%6,%7}, {%8,%9}, {%0,%1,%2,%3};"
        : "+f"(d[0]), "+f"(d[1]), "+f"(d[2]), "+f"(d[3])
        : "r"(a[0]), "r"(a[1]), "r"(a[2]), "r"(a[3]), "r"(b0), "r"(b1));
}
__device__ __forceinline__ void mma_bf16(float* d, unsigned a0, unsigned a1,
                                         unsigned a2, unsigned a3,
                                         unsigned b0, unsigned b1) {
    asm("mma.sync.aligned.m16n8k16.row.col.f32.bf16.bf16.f32 "
        "{%0,%1,%2,%3}, {%4,%5,%6,%7}, {%8,%9}, {%0,%1,%2,%3};"
        : "+f"(d[0]), "+f"(d[1]), "+f"(d[2]), "+f"(d[3])
        : "r"(a0), "r"(a1), "r"(a2), "r"(a3), "r"(b0), "r"(b1));
}

// ============================================================================
// Fused encoder (identical to R7)
// ============================================================================
#define EBE 64
#define ENC_THREADS 512
#define XST 68
#define HST 20
#define ZST 260
#define ENC_SMEM_BYTES ((2*2*64*XST + 2*64*HST) * 4 + (64*ZST + 2*64*32 + 256) * 4)

__global__ __launch_bounds__(ENC_THREADS, 1)
void encoder_fused(const float* __restrict__ X,
                   const float* __restrict__ W_ih_f, const float* __restrict__ W_hh_f,
                   const float* __restrict__ b_f,
                   const float* __restrict__ W_ih_r, const float* __restrict__ W_hh_r,
                   const float* __restrict__ b_r)
{
    const int b0  = blockIdx.x * EBE;
    const int tid = threadIdx.x;
    const int warp = tid >> 5, lane = tid & 31;
    const int g = lane >> 2, tg = lane & 3;
    const int dir = warp >> 3;
    const int wl  = warp & 7;

    extern __shared__ unsigned smu[];
    unsigned* xs  = smu;
    unsigned* hbf = xs + 2 * 2 * 64 * XST;
    float* zs  = (float*)(hbf + 2 * 64 * HST);
    float* cst = zs + 64 * ZST;
    float* bs  = cst + 2 * 64 * 32;

    const float* Wi = dir ? W_ih_r : W_ih_f;
    const float* Wh = dir ? W_hh_r : W_hh_f;

    unsigned Bx[2][8][2], Bh[2][2][2];
    #pragma unroll
    for (int nt = 0; nt < 2; nt++) {
        int n = wl * 16 + nt * 8 + g;
        #pragma unroll
        for (int c = 0; c < 8; c++) {
            Bx[nt][c][0] = pack_bf16(Wi[n * 128 + c * 16 + 2 * tg],
                                     Wi[n * 128 + c * 16 + 2 * tg + 1]);
            Bx[nt][c][1] = pack_bf16(Wi[n * 128 + c * 16 + 8 + 2 * tg],
                                     Wi[n * 128 + c * 16 + 8 + 2 * tg + 1]);
        }
        #pragma unroll
        for (int c = 0; c < 2; c++) {
            Bh[nt][c][0] = pack_bf16(Wh[n * 32 + c * 16 + 2 * tg],
                                     Wh[n * 32 + c * 16 + 2 * tg + 1]);
            Bh[nt][c][1] = pack_bf16(Wh[n * 32 + c * 16 + 8 + 2 * tg],
                                     Wh[n * 32 + c * 16 + 8 + 2 * tg + 1]);
        }
    }

    for (int i = tid; i < 256; i += ENC_THREADS) bs[i] = (i < 128) ? b_f[i] : b_r[i - 128];
    for (int i = tid; i < 2 * 64 * HST; i += ENC_THREADS) hbf[i] = 0u;
    for (int i = tid; i < 2 * 64 * 32; i += ENC_THREADS) cst[i] = 0.0f;

    #pragma unroll
    for (int ii = 0; ii < 8; ii++) {
        int flat = tid + ii * ENC_THREADS;
        int dd = flat >> 11, r = flat & 2047;
        int row = r >> 5, q = r & 31;
        int ts = dd ? (TX - 1) : 0;
        float4 v = *(const float4*)(X + ((size_t)(b0 + row) * TX + ts) * HV + q * 4);
        int c = q >> 2, jj0 = (q & 3) * 2;
        int p0 = (jj0 & 3) * 2 + (jj0 >> 2);
        int p1 = ((jj0 + 1) & 3) * 2 + ((jj0 + 1) >> 2);
        unsigned* dst = &xs[((0 * 2 + dd) * 64 + row) * XST + c * 8];
        dst[p0] = pack_bf16(v.x, v.y);
        dst[p1] = pack_bf16(v.z, v.w);
    }
    __syncthreads();

    int buf = 0;
    for (int t = 0; t < TX; t++) {
        float4 xpre[8];
        #pragma unroll
        for (int ii = 0; ii < 8; ii++) {
            int flat = tid + ii * ENC_THREADS;
            int dd = flat >> 11, r = flat & 2047;
            int row = r >> 5, q = r & 31;
            int ts = dd ? max(TX - 2 - t, 0) : min(t + 1, TX - 1);
            xpre[ii] = *(const float4*)(X + ((size_t)(b0 + row) * TX + ts) * HV + q * 4);
        }

        float d[4][2][4];
        #pragma unroll
        for (int mi = 0; mi < 4; mi++)
            #pragma unroll
            for (int nt = 0; nt < 2; nt++)
                #pragma unroll
                for (int r = 0; r < 4; r++) d[mi][nt][r] = 0.0f;

        const unsigned* xbase = &xs[((buf * 2 + dir) * 64) * XST];
        #pragma unroll
        for (int c = 0; c < 8; c++) {
            unsigned a[4][4];
            #pragma unroll
            for (int mi = 0; mi < 4; mi++) {
                uint2 lo = *(uint2*)&xbase[(mi * 16 + g) * XST + c * 8 + 2 * tg];
                uint2 hi = *(uint2*)&xbase[(mi * 16 + 8 + g) * XST + c * 8 + 2 * tg];
                a[mi][0] = lo.x; a[mi][1] = hi.x; a[mi][2] = lo.y; a[mi][3] = hi.y;
            }
            #pragma unroll
            for (int mi = 0; mi < 4; mi++) {
                mma_bf16(d[mi][0], a[mi][0], a[mi][1], a[mi][2], a[mi][3],
                         Bx[0][c][0], Bx[0][c][1]);
                mma_bf16(d[mi][1], a[mi][0], a[mi][1], a[mi][2], a[mi][3],
                         Bx[1][c][0], Bx[1][c][1]);
            }
        }
        const unsigned* hbase = &hbf[(dir * 64) * HST];
        #pragma unroll
        for (int c = 0; c < 2; c++) {
            unsigned a[4][4];
            #pragma unroll
            for (int mi = 0; mi < 4; mi++) {
                uint2 lo = *(uint2*)&hbase[(mi * 16 + g) * HST + c * 8 + 2 * tg];
                uint2 hi = *(uint2*)&hbase[(mi * 16 + 8 + g) * HST + c * 8 + 2 * tg];
                a[mi][0] = lo.x; a[mi][1] = hi.x; a[mi][2] = lo.y; a[mi][3] = hi.y;
            }
            #pragma unroll
            for (int mi = 0; mi < 4; mi++) {
                mma_bf16(d[mi][0], a[mi][0], a[mi][1], a[mi][2], a[mi][3],
                         Bh[0][c][0], Bh[0][c][1]);
                mma_bf16(d[mi][1], a[mi][0], a[mi][1], a[mi][2], a[mi][3],
                         Bh[1][c][0], Bh[1][c][1]);
            }
        }

        #pragma unroll
        for (int mi = 0; mi < 4; mi++)
            #pragma unroll
            for (int nt = 0; nt < 2; nt++) {
                int col = dir * 128 + wl * 16 + nt * 8 + 2 * tg;
                *(float2*)&zs[(mi * 16 + g) * ZST + col] =
                    make_float2(d[mi][nt][0], d[mi][nt][1]);
                *(float2*)&zs[(mi * 16 + 8 + g) * ZST + col] =
                    make_float2(d[mi][nt][2], d[mi][nt][3]);
            }
        __syncthreads();

        #pragma unroll
        for (int ii = 0; ii < 8; ii++) {
            int flat = tid + ii * ENC_THREADS;
            int dd = flat >> 11, r = flat & 2047;
            int row = r >> 5, q = r & 31;
            int c = q >> 2, jj0 = (q & 3) * 2;
            int p0 = (jj0 & 3) * 2 + (jj0 >> 2);
            int p1 = ((jj0 + 1) & 3) * 2 + ((jj0 + 1) >> 2);
            unsigned* dst = &xs[(((buf ^ 1) * 2 + dd) * 64 + row) * XST + c * 8];
            dst[p0] = pack_bf16(xpre[ii].x, xpre[ii].y);
            dst[p1] = pack_bf16(xpre[ii].z, xpre[ii].w);
        }

        #pragma unroll
        for (int ii = 0; ii < 4; ii++) {
            int flat = tid + ii * ENC_THREADS;
            int e = flat >> 5, r = flat & 31;
            int dd = r >> 4, np = r & 15;
            int base = dd * 128 + 2 * np;
            float2 zi = *(float2*)&zs[e * ZST + base];
            float2 zf = *(float2*)&zs[e * ZST + base + 32];
            float2 zg = *(float2*)&zs[e * ZST + base + 64];
            float2 zo = *(float2*)&zs[e * ZST + base + 96];
            zi.x += bs[base];      zi.y += bs[base + 1];
            zf.x += bs[base + 32]; zf.y += bs[base + 33];
            zg.x += bs[base + 64]; zg.y += bs[base + 65];
            zo.x += bs[base + 96]; zo.y += bs[base + 97];
            float2 cold = *(float2*)&cst[dd * 2048 + e * 32 + 2 * np];
            float c0 = sigapx(zf.x) * cold.x + sigapx(zi.x) * tanhapx(zg.x);
            float c1 = sigapx(zf.y) * cold.y + sigapx(zi.y) * tanhapx(zg.y);
            float h0 = sigapx(zo.x) * tanhapx(c0);
            float h1 = sigapx(zo.y) * tanhapx(c1);
            *(float2*)&cst[dd * 2048 + e * 32 + 2 * np] = make_float2(c0, c1);
            hbf[(dd * 64 + e) * HST + (np >> 3) * 8 + ((np & 7) & 3) * 2 + ((np & 7) >> 2)]
                = pack_bf16(h0, h1);
            int tt = dd ? (TX - 1 - t) : t;
            *(float2*)(g_a + ((size_t)(b0 + e) * TX + tt) * 64 + dd * 32 + 2 * np)
                = make_float2(h0, h1);
        }
        __syncthreads();
        buf ^= 1;
    }
}

// ============================================================================
// Decoder: R7 structure; B and F now use approx transcendentals (MUFU halved)
// ============================================================================
#define DBE 16
#define DEC_THREADS 512
#define SA_STRIDE 68
#define W1ST 68
#define INSP_STRIDE 140

#define NF_SA   (DBE * TX * SA_STRIDE)
#define NF_EA   (DBE * TX * 10)
#define DEC_SMEM_FLOATS (NF_SA + NF_EA + 640 + 680 + 16 + 16 + GP + MV \
                         + DBE*NS + DBE*NS + DBE*INSP_STRIDE + DBE*GP + DBE*32)

__global__ __launch_bounds__(DEC_THREADS, 1)
void decoder_kernel(const float* __restrict__ W1, const float* __restrict__ b1,
                    const float* __restrict__ W2, const float* __restrict__ b2,
                    const float* __restrict__ W_ih_p, const float* __restrict__ W_hh_p,
                    const float* __restrict__ b_p,
                    const float* __restrict__ Wo, const float* __restrict__ bo,
                    float* __restrict__ out)
{
    const int b0 = blockIdx.x * DBE;
    const int tid = threadIdx.x;
    const unsigned FULL = 0xffffffffu;

    extern __shared__ float sm[];
    float* sa   = sm;
    float* ea   = sa + NF_SA;
    float* W1a  = ea + NF_EA;
    float* W1s  = W1a + 640;
    float* b1s  = W1s + 680;
    float* W2s  = b1s + 16;
    float* bps  = W2s + 16;
    float* bos  = bps + GP;
    float* ss   = bos + MV;
    float* cc   = ss + DBE * NS;
    unsigned* insp = (unsigned*)(cc + DBE * NS);
    float* zsd  = (float*)(insp + DBE * INSP_STRIDE);
    float* alph = zsd + DBE * GP;

    const int warp = tid >> 5, lane = tid & 31;
    const int g = lane >> 2, tg = lane & 3;

    unsigned Bw[64];
    #pragma unroll
    for (int nt = 0; nt < 2; nt++) {
        int n = warp * 16 + nt * 8 + g;
        #pragma unroll
        for (int c = 0; c < 8; c++) {
            Bw[(nt * 16 + c) * 2 + 0] = cvt_tf32(W_ih_p[n * 64 + c * 8 + tg]);
            Bw[(nt * 16 + c) * 2 + 1] = cvt_tf32(W_ih_p[n * 64 + c * 8 + tg + 4]);
        }
        #pragma unroll
        for (int c = 0; c < 8; c++) {
            Bw[(nt * 16 + (8 + c)) * 2 + 0] = cvt_tf32(W_hh_p[n * 64 + c * 8 + tg]);
            Bw[(nt * 16 + (8 + c)) * 2 + 1] = cvt_tf32(W_hh_p[n * 64 + c * 8 + tg + 4]);
        }
    }

    const int wm = tid & 63, wkh = (tid >> 6) & 3, eh = tid >> 8;
    float wreg[16];
    #pragma unroll
    for (int kk = 0; kk < 16; kk++) wreg[kk] = Wo[wm * 64 + wkh * 16 + kk];

    for (int i = tid; i < 640; i += DEC_THREADS) {
        int j = i / 64, d = i % 64;
        W1a[i]            = W1[j * 128 + d];
        W1s[j * W1ST + d] = W1[j * 128 + 64 + d];
    }
    if (tid < 10) { b1s[tid] = b1[tid]; W2s[tid] = W2[tid]; }
    for (int i = tid; i < GP; i += DEC_THREADS) bps[i] = b_p[i];
    if (tid < MV) bos[tid] = bo[tid];
    for (int i = tid; i < DBE * NS; i += DEC_THREADS) { ss[i] = 0.0f; cc[i] = 0.0f; }
    const float b2v = b2[0];

    for (int i = tid; i < DBE * TX * (NS / 4); i += DEC_THREADS) {
        int e = i / (TX * 16);
        int r = i % (TX * 16);
        int tx = r / 16, d4 = r % 16;
        float4 v = *(const float4*)(g_a + ((size_t)(b0 + e) * TX + tx) * (2 * NA) + d4 * 4);
        *(float4*)&sa[(e * TX + tx) * SA_STRIDE + d4 * 4] = v;
    }
    __syncthreads();

    if (tid < DBE * TX) {
        int e = tid / TX, tx = tid % TX;
        const float* arow = &sa[(e * TX + tx) * SA_STRIDE];
        float acc[10];
        #pragma unroll
        for (int j = 0; j < 10; j++) acc[j] = 0.0f;
        for (int d = 0; d < 64; d++) {
            float av = arow[d];
            #pragma unroll
            for (int j = 0; j < 10; j++) acc[j] += av * W1a[j * 64 + d];
        }
        #pragma unroll
        for (int j = 0; j < 10; j++) ea[(e * TX + tx) * 10 + j] = acc[j];
    }
    __syncthreads();

    for (int t = 0; t < TY; t++) {
        // ---- A+B+C fused: warp e handles element e ----
        {
            const int e = warp;
            float accA = 0.0f;
            if (lane < 20) {
                int j = lane >> 1, half = lane & 1;
                const float4* sp = (const float4*)&ss[e * NS + half * 32];
                const float4* wp = (const float4*)&W1s[j * W1ST + half * 32];
                #pragma unroll
                for (int q = 0; q < 8; q++) {
                    float4 sv = sp[q], wv = wp[q];
                    accA += sv.x * wv.x + sv.y * wv.y + sv.z * wv.z + sv.w * wv.w;
                }
            }
            accA += __shfl_xor_sync(FULL, accA, 1);
            if (lane < 20) accA += b1s[lane >> 1];

            int txc = (lane < TX) ? lane : 0;
            float acc = b2v;
            #pragma unroll
            for (int j = 0; j < 10; j++) {
                float esj = __shfl_sync(FULL, accA, 2 * j);
                acc += tanhapx(ea[(e * TX + txc) * 10 + j] + esj) * W2s[j];
            }
            float en = (lane < TX) ? fmaxf(acc, 0.0f) : -1e30f;

            float mx = en;
            #pragma unroll
            for (int o = 16; o; o >>= 1) mx = fmaxf(mx, __shfl_xor_sync(FULL, mx, o));
            float ex = (lane < TX) ? __expf(en - mx) : 0.0f;
            float sum = ex;
            #pragma unroll
            for (int o = 16; o; o >>= 1) sum += __shfl_xor_sync(FULL, sum, o);
            alph[e * 32 + lane] = ex * __fdividef(1.0f, sum);
        }
        __syncthreads();

        // ---- D: context pair-per-thread (float2) -> insp ----
        {
            const int e = tid >> 5, d0 = (tid & 31) * 2;
            const float* ap = &alph[e * 32];
            float ctx0 = 0.0f, ctx1 = 0.0f;
            #pragma unroll 5
            for (int tx = 0; tx < TX; tx++) {
                float al = ap[tx];
                float2 sv = *(const float2*)&sa[(e * TX + tx) * SA_STRIDE + d0];
                ctx0 += al * sv.x;
                ctx1 += al * sv.y;
            }
            int c = d0 >> 3, jj0 = d0 & 7;
            int p0 = (jj0 & 3) * 2 + (jj0 >> 2);
            int p1 = ((jj0 + 1) & 3) * 2 + ((jj0 + 1) >> 2);
            insp[e * INSP_STRIDE + c * 8 + p0] = cvt_tf32(ctx0);
            insp[e * INSP_STRIDE + c * 8 + p1] = cvt_tf32(ctx1);
            float2 sv = *(const float2*)&ss[e * NS + d0];
            insp[e * INSP_STRIDE + (8 + c) * 8 + p0] = cvt_tf32(sv.x);
            insp[e * INSP_STRIDE + (8 + c) * 8 + p1] = cvt_tf32(sv.y);
        }
        __syncthreads();

        // ---- E: gate GEMM via tf32 mma ----
        {
            float dd[2][4];
            #pragma unroll
            for (int nt = 0; nt < 2; nt++)
                #pragma unroll
                for (int r = 0; r < 4; r++) dd[nt][r] = 0.0f;
            #pragma unroll
            for (int c = 0; c < 16; c++) {
                uint2 va = *(uint2*)&insp[g * INSP_STRIDE + c * 8 + 2 * tg];
                uint2 vb = *(uint2*)&insp[(g + 8) * INSP_STRIDE + c * 8 + 2 * tg];
                unsigned a[4] = {va.x, vb.x, va.y, vb.y};
                mma_tf32(dd[0], a, Bw[(0 * 16 + c) * 2], Bw[(0 * 16 + c) * 2 + 1]);
                mma_tf32(dd[1], a, Bw[(1 * 16 + c) * 2], Bw[(1 * 16 + c) * 2 + 1]);
            }
            #pragma unroll
            for (int nt = 0; nt < 2; nt++) {
                int n0 = warp * 16 + nt * 8 + 2 * tg;
                *(float2*)&zsd[g * GP + n0]       = make_float2(dd[nt][0], dd[nt][1]);
                *(float2*)&zsd[(g + 8) * GP + n0] = make_float2(dd[nt][2], dd[nt][3]);
            }
        }
        __syncthreads();

        // ---- F: LSTM cell (approx transcendentals) ----
        for (int i = tid; i < DBE * NS; i += DEC_THREADS) {
            int e = i >> 6, n = i & 63;
            float zi = zsd[e * GP + n]           + bps[n];
            float zf = zsd[e * GP + NS + n]      + bps[NS + n];
            float zg = zsd[e * GP + 2 * NS + n]  + bps[2 * NS + n];
            float zo = zsd[e * GP + 3 * NS + n]  + bps[3 * NS + n];
            float c = sigapx(zf) * cc[i] + sigapx(zi) * tanhapx(zg);
            float h = sigapx(zo) * tanhapx(c);
            cc[i] = c; ss[i] = h;
        }
        __syncthreads();

        // ---- G: out partials via float4 ss reads ----
        {
            #pragma unroll
            for (int ei = 0; ei < 8; ei++) {
                int e = eh * 8 + ei;
                const float4* sp = (const float4*)&ss[e * NS + wkh * 16];
                float p = 0.0f;
                #pragma unroll
                for (int q = 0; q < 4; q++) {
                    float4 sv = sp[q];
                    p += sv.x * wreg[4 * q]     + sv.y * wreg[4 * q + 1]
                       + sv.z * wreg[4 * q + 2] + sv.w * wreg[4 * q + 3];
                }
                zsd[(wkh * DBE + e) * 64 + wm] = p;
            }
        }
        __syncthreads();
        for (int i = tid; i < DBE * MV; i += DEC_THREADS) {
            int e = i >> 6, m = i & 63;
            float o = bos[m]
                    + zsd[(0 * DBE + e) * 64 + m] + zsd[(1 * DBE + e) * 64 + m]
                    + zsd[(2 * DBE + e) * 64 + m] + zsd[(3 * DBE + e) * 64 + m];
            out[((size_t)(b0 + e) * TY + t) * MV + m] = o;
        }
        __syncthreads();
    }
}

// ============================================================================
extern "C" void kernel_launch(void* const* d_in, const int* in_sizes, int n_in,
                              void* d_out, int out_size)
{
    const float* X      = (const float*)d_in[0];
    const float* W_ih_f = (const float*)d_in[1];
    const float* W_hh_f = (const float*)d_in[2];
    const float* b_f    = (const float*)d_in[3];
    const float* W_ih_r = (const float*)d_in[4];
    const float* W_hh_r = (const float*)d_in[5];
    const float* b_r    = (const float*)d_in[6];
    const float* W1     = (const float*)d_in[7];
    const float* b1     = (const float*)d_in[8];
    const float* W2     = (const float*)d_in[9];
    const float* b2     = (const float*)d_in[10];
    const float* W_ih_p = (const float*)d_in[11];
    const float* W_hh_p = (const float*)d_in[12];
    const float* b_p    = (const float*)d_in[13];
    const float* Wo     = (const float*)d_in[14];
    const float* bo     = (const float*)d_in[15];
    float* out = (float*)d_out;

    const int dec_smem = DEC_SMEM_FLOATS * sizeof(float);
    cudaFuncSetAttribute(encoder_fused,  cudaFuncAttributeMaxDynamicSharedMemorySize, ENC_SMEM_BYTES);
    cudaFuncSetAttribute(decoder_kernel, cudaFuncAttributeMaxDynamicSharedMemorySize, dec_smem);

    encoder_fused<<<B_TOT / EBE, ENC_THREADS, ENC_SMEM_BYTES>>>(
        X, W_ih_f, W_hh_f, b_f, W_ih_r, W_hh_r, b_r);

    decoder_kernel<<<B_TOT / DBE, DEC_THREADS, dec_smem>>>(W1, b1, W2, b2,
                                                           W_ih_p, W_hh_p, b_p, Wo, bo, out);
}

// round 9
// speedup vs baseline: 3.6106x; 1.0241x over previous
#include <cuda_runtime.h>
#include <cuda_bf16.h>
#include <math.h>

#define B_TOT 16384
#define TX 30
#define TY 10
#define NA 32
#define NS 64
#define HV 128
#define MV 64
#define GE 128   // 4*NA
#define GP 256   // 4*NS

__device__ __align__(16) float g_a[(size_t)B_TOT * TX * (2 * NA)];   // 126 MB

__device__ __forceinline__ float tanhapx(float x) {
    float y;
    asm("tanh.approx.f32 %0, %1;" : "=f"(y) : "f"(x));
    return y;
}
__device__ __forceinline__ float sigapx(float x) {
    return fmaf(tanhapx(0.5f * x), 0.5f, 0.5f);
}
__device__ __forceinline__ unsigned cvt_tf32(float x) {
    unsigned u;
    asm("cvt.rna.tf32.f32 %0, %1;" : "=r"(u) : "f"(x));
    return u;
}
__device__ __forceinline__ unsigned pack_bf16(float a, float b) {
    __nv_bfloat162 h = __floats2bfloat162_rn(a, b);
    return *(unsigned*)&h;
}
__device__ __forceinline__ void mma_tf32(float* d, const unsigned* a, unsigned b0, unsigned b1) {
    asm("mma.sync.aligned.m16n8k8.row.col.f32.tf32.tf32.f32 "
        "{%0,%1,%2,%3}, {%4,%5,%6,%7}, {%8,%9}, {%0,%1,%2,%3};"
        : "+f"(d[0]), "+f"(d[1]), "+f"(d[2]), "+f"(d[3])
        : "r"(a[0]), "r"(a[1]), "r"(a[2]), "r"(a[3]), "r"(b0), "r"(b1));
}
__device__ __forceinline__ void mma_bf16(float* d, unsigned a0, unsigned a1,
                                         unsigned a2, unsigned a3,
                                         unsigned b0, unsigned b1) {
    asm("mma.sync.aligned.m16n8k16.row.col.f32.bf16.bf16.f32 "
        "{%0,%1,%2,%3}, {%4,%5,%6,%7}, {%8,%9}, {%0,%1,%2,%3};"
        : "+f"(d[0]), "+f"(d[1]), "+f"(d[2]), "+f"(d[3])
        : "r"(a0), "r"(a1), "r"(a2), "r"(a3), "r"(b0), "r"(b1));
}

// ============================================================================
// Fused encoder (identical to R8)
// ============================================================================
#define EBE 64
#define ENC_THREADS 512
#define XST 68
#define HST 20
#define ZST 260
#define ENC_SMEM_BYTES ((2*2*64*XST + 2*64*HST) * 4 + (64*ZST + 2*64*32 + 256) * 4)

__global__ __launch_bounds__(ENC_THREADS, 1)
void encoder_fused(const float* __restrict__ X,
                   const float* __restrict__ W_ih_f, const float* __restrict__ W_hh_f,
                   const float* __restrict__ b_f,
                   const float* __restrict__ W_ih_r, const float* __restrict__ W_hh_r,
                   const float* __restrict__ b_r)
{
    const int b0  = blockIdx.x * EBE;
    const int tid = threadIdx.x;
    const int warp = tid >> 5, lane = tid & 31;
    const int g = lane >> 2, tg = lane & 3;
    const int dir = warp >> 3;
    const int wl  = warp & 7;

    extern __shared__ unsigned smu[];
    unsigned* xs  = smu;
    unsigned* hbf = xs + 2 * 2 * 64 * XST;
    float* zs  = (float*)(hbf + 2 * 64 * HST);
    float* cst = zs + 64 * ZST;
    float* bs  = cst + 2 * 64 * 32;

    const float* Wi = dir ? W_ih_r : W_ih_f;
    const float* Wh = dir ? W_hh_r : W_hh_f;

    unsigned Bx[2][8][2], Bh[2][2][2];
    #pragma unroll
    for (int nt = 0; nt < 2; nt++) {
        int n = wl * 16 + nt * 8 + g;
        #pragma unroll
        for (int c = 0; c < 8; c++) {
            Bx[nt][c][0] = pack_bf16(Wi[n * 128 + c * 16 + 2 * tg],
                                     Wi[n * 128 + c * 16 + 2 * tg + 1]);
            Bx[nt][c][1] = pack_bf16(Wi[n * 128 + c * 16 + 8 + 2 * tg],
                                     Wi[n * 128 + c * 16 + 8 + 2 * tg + 1]);
        }
        #pragma unroll
        for (int c = 0; c < 2; c++) {
            Bh[nt][c][0] = pack_bf16(Wh[n * 32 + c * 16 + 2 * tg],
                                     Wh[n * 32 + c * 16 + 2 * tg + 1]);
            Bh[nt][c][1] = pack_bf16(Wh[n * 32 + c * 16 + 8 + 2 * tg],
                                     Wh[n * 32 + c * 16 + 8 + 2 * tg + 1]);
        }
    }

    for (int i = tid; i < 256; i += ENC_THREADS) bs[i] = (i < 128) ? b_f[i] : b_r[i - 128];
    for (int i = tid; i < 2 * 64 * HST; i += ENC_THREADS) hbf[i] = 0u;
    for (int i = tid; i < 2 * 64 * 32; i += ENC_THREADS) cst[i] = 0.0f;

    #pragma unroll
    for (int ii = 0; ii < 8; ii++) {
        int flat = tid + ii * ENC_THREADS;
        int dd = flat >> 11, r = flat & 2047;
        int row = r >> 5, q = r & 31;
        int ts = dd ? (TX - 1) : 0;
        float4 v = *(const float4*)(X + ((size_t)(b0 + row) * TX + ts) * HV + q * 4);
        int c = q >> 2, jj0 = (q & 3) * 2;
        int p0 = (jj0 & 3) * 2 + (jj0 >> 2);
        int p1 = ((jj0 + 1) & 3) * 2 + ((jj0 + 1) >> 2);
        unsigned* dst = &xs[((0 * 2 + dd) * 64 + row) * XST + c * 8];
        dst[p0] = pack_bf16(v.x, v.y);
        dst[p1] = pack_bf16(v.z, v.w);
    }
    __syncthreads();

    int buf = 0;
    for (int t = 0; t < TX; t++) {
        float4 xpre[8];
        #pragma unroll
        for (int ii = 0; ii < 8; ii++) {
            int flat = tid + ii * ENC_THREADS;
            int dd = flat >> 11, r = flat & 2047;
            int row = r >> 5, q = r & 31;
            int ts = dd ? max(TX - 2 - t, 0) : min(t + 1, TX - 1);
            xpre[ii] = *(const float4*)(X + ((size_t)(b0 + row) * TX + ts) * HV + q * 4);
        }

        float d[4][2][4];
        #pragma unroll
        for (int mi = 0; mi < 4; mi++)
            #pragma unroll
            for (int nt = 0; nt < 2; nt++)
                #pragma unroll
                for (int r = 0; r < 4; r++) d[mi][nt][r] = 0.0f;

        const unsigned* xbase = &xs[((buf * 2 + dir) * 64) * XST];
        #pragma unroll
        for (int c = 0; c < 8; c++) {
            unsigned a[4][4];
            #pragma unroll
            for (int mi = 0; mi < 4; mi++) {
                uint2 lo = *(uint2*)&xbase[(mi * 16 + g) * XST + c * 8 + 2 * tg];
                uint2 hi = *(uint2*)&xbase[(mi * 16 + 8 + g) * XST + c * 8 + 2 * tg];
                a[mi][0] = lo.x; a[mi][1] = hi.x; a[mi][2] = lo.y; a[mi][3] = hi.y;
            }
            #pragma unroll
            for (int mi = 0; mi < 4; mi++) {
                mma_bf16(d[mi][0], a[mi][0], a[mi][1], a[mi][2], a[mi][3],
                         Bx[0][c][0], Bx[0][c][1]);
                mma_bf16(d[mi][1], a[mi][0], a[mi][1], a[mi][2], a[mi][3],
                         Bx[1][c][0], Bx[1][c][1]);
            }
        }
        const unsigned* hbase = &hbf[(dir * 64) * HST];
        #pragma unroll
        for (int c = 0; c < 2; c++) {
            unsigned a[4][4];
            #pragma unroll
            for (int mi = 0; mi < 4; mi++) {
                uint2 lo = *(uint2*)&hbase[(mi * 16 + g) * HST + c * 8 + 2 * tg];
                uint2 hi = *(uint2*)&hbase[(mi * 16 + 8 + g) * HST + c * 8 + 2 * tg];
                a[mi][0] = lo.x; a[mi][1] = hi.x; a[mi][2] = lo.y; a[mi][3] = hi.y;
            }
            #pragma unroll
            for (int mi = 0; mi < 4; mi++) {
                mma_bf16(d[mi][0], a[mi][0], a[mi][1], a[mi][2], a[mi][3],
                         Bh[0][c][0], Bh[0][c][1]);
                mma_bf16(d[mi][1], a[mi][0], a[mi][1], a[mi][2], a[mi][3],
                         Bh[1][c][0], Bh[1][c][1]);
            }
        }

        #pragma unroll
        for (int mi = 0; mi < 4; mi++)
            #pragma unroll
            for (int nt = 0; nt < 2; nt++) {
                int col = dir * 128 + wl * 16 + nt * 8 + 2 * tg;
                *(float2*)&zs[(mi * 16 + g) * ZST + col] =
                    make_float2(d[mi][nt][0], d[mi][nt][1]);
                *(float2*)&zs[(mi * 16 + 8 + g) * ZST + col] =
                    make_float2(d[mi][nt][2], d[mi][nt][3]);
            }
        __syncthreads();

        #pragma unroll
        for (int ii = 0; ii < 8; ii++) {
            int flat = tid + ii * ENC_THREADS;
            int dd = flat >> 11, r = flat & 2047;
            int row = r >> 5, q = r & 31;
            int c = q >> 2, jj0 = (q & 3) * 2;
            int p0 = (jj0 & 3) * 2 + (jj0 >> 2);
            int p1 = ((jj0 + 1) & 3) * 2 + ((jj0 + 1) >> 2);
            unsigned* dst = &xs[(((buf ^ 1) * 2 + dd) * 64 + row) * XST + c * 8];
            dst[p0] = pack_bf16(xpre[ii].x, xpre[ii].y);
            dst[p1] = pack_bf16(xpre[ii].z, xpre[ii].w);
        }

        #pragma unroll
        for (int ii = 0; ii < 4; ii++) {
            int flat = tid + ii * ENC_THREADS;
            int e = flat >> 5, r = flat & 31;
            int dd = r >> 4, np = r & 15;
            int base = dd * 128 + 2 * np;
            float2 zi = *(float2*)&zs[e * ZST + base];
            float2 zf = *(float2*)&zs[e * ZST + base + 32];
            float2 zg = *(float2*)&zs[e * ZST + base + 64];
            float2 zo = *(float2*)&zs[e * ZST + base + 96];
            zi.x += bs[base];      zi.y += bs[base + 1];
            zf.x += bs[base + 32]; zf.y += bs[base + 33];
            zg.x += bs[base + 64]; zg.y += bs[base + 65];
            zo.x += bs[base + 96]; zo.y += bs[base + 97];
            float2 cold = *(float2*)&cst[dd * 2048 + e * 32 + 2 * np];
            float c0 = sigapx(zf.x) * cold.x + sigapx(zi.x) * tanhapx(zg.x);
            float c1 = sigapx(zf.y) * cold.y + sigapx(zi.y) * tanhapx(zg.y);
            float h0 = sigapx(zo.x) * tanhapx(c0);
            float h1 = sigapx(zo.y) * tanhapx(c1);
            *(float2*)&cst[dd * 2048 + e * 32 + 2 * np] = make_float2(c0, c1);
            hbf[(dd * 64 + e) * HST + (np >> 3) * 8 + ((np & 7) & 3) * 2 + ((np & 7) >> 2)]
                = pack_bf16(h0, h1);
            int tt = dd ? (TX - 1 - t) : t;
            *(float2*)(g_a + ((size_t)(b0 + e) * TX + tt) * 64 + dd * 32 + 2 * np)
                = make_float2(h0, h1);
        }
        __syncthreads();
        buf ^= 1;
    }
}

// ============================================================================
// Decoder: R8 structure; a-tile in bf16x2 with zero-padded rows 30-31,
// D uses float4 alph broadcasts over 32 padded rows, ea stride 11.
// ============================================================================
#define DBE 16
#define DEC_THREADS 512
#define SABST 34     // u32 per (e,tx) row: 32 data (64 bf16) + 2 pad
#define EAST 11      // ea row stride (conflict-free)
#define W1ST 68
#define INSP_STRIDE 140

// layout in u32 units
#define OFF_SAB   0
#define SZ_SAB    (DBE * 32 * SABST)        // 17408 (32 rows per e, rows 30-31 zero)
#define OFF_EA    (OFF_SAB + SZ_SAB)
#define SZ_EA     (DBE * TX * EAST + 2)     // 5282 -> round to keep alignment
#define SZ_EA_AL  5284
#define OFF_W1A   (OFF_EA + SZ_EA_AL)
#define OFF_W1S   (OFF_W1A + 640)
#define OFF_B1S   (OFF_W1S + 680)
#define OFF_W2S   (OFF_B1S + 16)
#define OFF_BPS   (OFF_W2S + 16)
#define OFF_BOS   (OFF_BPS + 256)
#define OFF_SS    (OFF_BOS + 64)
#define OFF_CC    (OFF_SS + DBE * NS)
#define OFF_INSP  (OFF_CC + DBE * NS)
#define OFF_ZSD   (OFF_INSP + DBE * INSP_STRIDE)
#define OFF_ALPH  (OFF_ZSD + DBE * GP)
#define DEC_UNITS (OFF_ALPH + DBE * 32)
#define DEC_SMEM_BYTES (DEC_UNITS * 4)

__global__ __launch_bounds__(DEC_THREADS, 1)
void decoder_kernel(const float* __restrict__ W1, const float* __restrict__ b1,
                    const float* __restrict__ W2, const float* __restrict__ b2,
                    const float* __restrict__ W_ih_p, const float* __restrict__ W_hh_p,
                    const float* __restrict__ b_p,
                    const float* __restrict__ Wo, const float* __restrict__ bo,
                    float* __restrict__ out)
{
    const int b0 = blockIdx.x * DBE;
    const int tid = threadIdx.x;
    const unsigned FULL = 0xffffffffu;

    extern __shared__ unsigned smw[];
    unsigned* sab = smw + OFF_SAB;
    float* ea   = (float*)(smw + OFF_EA);
    float* W1a  = (float*)(smw + OFF_W1A);
    float* W1s  = (float*)(smw + OFF_W1S);
    float* b1s  = (float*)(smw + OFF_B1S);
    float* W2s  = (float*)(smw + OFF_W2S);
    float* bps  = (float*)(smw + OFF_BPS);
    float* bos  = (float*)(smw + OFF_BOS);
    float* ss   = (float*)(smw + OFF_SS);
    float* cc   = (float*)(smw + OFF_CC);
    unsigned* insp = smw + OFF_INSP;
    float* zsd  = (float*)(smw + OFF_ZSD);
    float* alph = (float*)(smw + OFF_ALPH);

    const int warp = tid >> 5, lane = tid & 31;
    const int g = lane >> 2, tg = lane & 3;

    unsigned Bw[64];
    #pragma unroll
    for (int nt = 0; nt < 2; nt++) {
        int n = warp * 16 + nt * 8 + g;
        #pragma unroll
        for (int c = 0; c < 8; c++) {
            Bw[(nt * 16 + c) * 2 + 0] = cvt_tf32(W_ih_p[n * 64 + c * 8 + tg]);
            Bw[(nt * 16 + c) * 2 + 1] = cvt_tf32(W_ih_p[n * 64 + c * 8 + tg + 4]);
        }
        #pragma unroll
        for (int c = 0; c < 8; c++) {
            Bw[(nt * 16 + (8 + c)) * 2 + 0] = cvt_tf32(W_hh_p[n * 64 + c * 8 + tg]);
            Bw[(nt * 16 + (8 + c)) * 2 + 1] = cvt_tf32(W_hh_p[n * 64 + c * 8 + tg + 4]);
        }
    }

    const int wm = tid & 63, wkh = (tid >> 6) & 3, eh = tid >> 8;
    float wreg[16];
    #pragma unroll
    for (int kk = 0; kk < 16; kk++) wreg[kk] = Wo[wm * 64 + wkh * 16 + kk];

    for (int i = tid; i < 640; i += DEC_THREADS) {
        int j = i / 64, d = i % 64;
        W1a[i]            = W1[j * 128 + d];
        W1s[j * W1ST + d] = W1[j * 128 + 64 + d];
    }
    if (tid < 10) { b1s[tid] = b1[tid]; W2s[tid] = W2[tid]; }
    for (int i = tid; i < GP; i += DEC_THREADS) bps[i] = b_p[i];
    if (tid < MV) bos[tid] = bo[tid];
    for (int i = tid; i < DBE * NS; i += DEC_THREADS) { ss[i] = 0.0f; cc[i] = 0.0f; }
    const float b2v = b2[0];

    // zero pad rows 30,31 of each e (rows 0-29 fully overwritten below; disjoint)
    for (int i = tid; i < DBE * 2 * SABST; i += DEC_THREADS) {
        int e = i / (2 * SABST), r = i % (2 * SABST);
        sab[(e * 32 + 30) * SABST + r] = 0u;
    }

    // load a tile as bf16x2
    for (int i = tid; i < DBE * TX * 16; i += DEC_THREADS) {
        int e = i / (TX * 16);
        int r = i % (TX * 16);
        int tx = r / 16, d4 = r % 16;
        float4 v = *(const float4*)(g_a + ((size_t)(b0 + e) * TX + tx) * (2 * NA) + d4 * 4);
        sab[(e * 32 + tx) * SABST + 2 * d4]     = pack_bf16(v.x, v.y);
        sab[(e * 32 + tx) * SABST + 2 * d4 + 1] = pack_bf16(v.z, v.w);
    }
    __syncthreads();

    // Ea precompute (reads bf16 a)
    if (tid < DBE * TX) {
        int e = tid / TX, tx = tid % TX;
        float acc[10];
        #pragma unroll
        for (int j = 0; j < 10; j++) acc[j] = 0.0f;
        #pragma unroll 4
        for (int d2 = 0; d2 < 32; d2++) {
            unsigned av = sab[(e * 32 + tx) * SABST + d2];
            float f0 = __uint_as_float(av << 16);
            float f1 = __uint_as_float(av & 0xffff0000u);
            #pragma unroll
            for (int j = 0; j < 10; j++)
                acc[j] += f0 * W1a[j * 64 + 2 * d2] + f1 * W1a[j * 64 + 2 * d2 + 1];
        }
        #pragma unroll
        for (int j = 0; j < 10; j++) ea[(e * TX + tx) * EAST + j] = acc[j];
    }
    __syncthreads();

    for (int t = 0; t < TY; t++) {
        // ---- A+B+C fused: warp e handles element e ----
        {
            const int e = warp;
            float accA = 0.0f;
            if (lane < 20) {
                int j = lane >> 1, half = lane & 1;
                const float4* sp = (const float4*)&ss[e * NS + half * 32];
                const float4* wp = (const float4*)&W1s[j * W1ST + half * 32];
                #pragma unroll
                for (int q = 0; q < 8; q++) {
                    float4 sv = sp[q], wv = wp[q];
                    accA += sv.x * wv.x + sv.y * wv.y + sv.z * wv.z + sv.w * wv.w;
                }
            }
            accA += __shfl_xor_sync(FULL, accA, 1);
            if (lane < 20) accA += b1s[lane >> 1];

            int txc = (lane < TX) ? lane : 0;
            float acc = b2v;
            #pragma unroll
            for (int j = 0; j < 10; j++) {
                float esj = __shfl_sync(FULL, accA, 2 * j);
                acc += tanhapx(ea[(e * TX + txc) * EAST + j] + esj) * W2s[j];
            }
            float en = (lane < TX) ? fmaxf(acc, 0.0f) : -1e30f;

            float mx = en;
            #pragma unroll
            for (int o = 16; o; o >>= 1) mx = fmaxf(mx, __shfl_xor_sync(FULL, mx, o));
            float ex = (lane < TX) ? __expf(en - mx) : 0.0f;
            float sum = ex;
            #pragma unroll
            for (int o = 16; o; o >>= 1) sum += __shfl_xor_sync(FULL, sum, o);
            alph[e * 32 + lane] = ex * __fdividef(1.0f, sum);   // pad lanes write 0
        }
        __syncthreads();

        // ---- D: context pair-per-thread (bf16 a, float4 alph) -> insp ----
        {
            const int e = tid >> 5, d2 = tid & 31;
            const float4* ap = (const float4*)&alph[e * 32];
            float ctx0 = 0.0f, ctx1 = 0.0f;
            #pragma unroll
            for (int c = 0; c < 8; c++) {
                float4 a4 = ap[c];
                unsigned v0 = sab[(e * 32 + 4 * c + 0) * SABST + d2];
                unsigned v1 = sab[(e * 32 + 4 * c + 1) * SABST + d2];
                unsigned v2 = sab[(e * 32 + 4 * c + 2) * SABST + d2];
                unsigned v3 = sab[(e * 32 + 4 * c + 3) * SABST + d2];
                ctx0 += a4.x * __uint_as_float(v0 << 16)
                      + a4.y * __uint_as_float(v1 << 16)
                      + a4.z * __uint_as_float(v2 << 16)
                      + a4.w * __uint_as_float(v3 << 16);
                ctx1 += a4.x * __uint_as_float(v0 & 0xffff0000u)
                      + a4.y * __uint_as_float(v1 & 0xffff0000u)
                      + a4.z * __uint_as_float(v2 & 0xffff0000u)
                      + a4.w * __uint_as_float(v3 & 0xffff0000u);
            }
            int d0 = 2 * d2;
            int c0 = d0 >> 3, jj0 = d0 & 7;
            int p0 = (jj0 & 3) * 2 + (jj0 >> 2);
            int p1 = ((jj0 + 1) & 3) * 2 + ((jj0 + 1) >> 2);
            insp[e * INSP_STRIDE + c0 * 8 + p0] = cvt_tf32(ctx0);
            insp[e * INSP_STRIDE + c0 * 8 + p1] = cvt_tf32(ctx1);
            float2 sv = *(const float2*)&ss[e * NS + d0];
            insp[e * INSP_STRIDE + (8 + c0) * 8 + p0] = cvt_tf32(sv.x);
            insp[e * INSP_STRIDE + (8 + c0) * 8 + p1] = cvt_tf32(sv.y);
        }
        __syncthreads();

        // ---- E: gate GEMM via tf32 mma ----
        {
            float dd[2][4];
            #pragma unroll
            for (int nt = 0; nt < 2; nt++)
                #pragma unroll
                for (int r = 0; r < 4; r++) dd[nt][r] = 0.0f;
            #pragma unroll
            for (int c = 0; c < 16; c++) {
                uint2 va = *(uint2*)&insp[g * INSP_STRIDE + c * 8 + 2 * tg];
                uint2 vb = *(uint2*)&insp[(g + 8) * INSP_STRIDE + c * 8 + 2 * tg];
                unsigned a[4] = {va.x, vb.x, va.y, vb.y};
                mma_tf32(dd[0], a, Bw[(0 * 16 + c) * 2], Bw[(0 * 16 + c) * 2 + 1]);
                mma_tf32(dd[1], a, Bw[(1 * 16 + c) * 2], Bw[(1 * 16 + c) * 2 + 1]);
            }
            #pragma unroll
            for (int nt = 0; nt < 2; nt++) {
                int n0 = warp * 16 + nt * 8 + 2 * tg;
                *(float2*)&zsd[g * GP + n0]       = make_float2(dd[nt][0], dd[nt][1]);
                *(float2*)&zsd[(g + 8) * GP + n0] = make_float2(dd[nt][2], dd[nt][3]);
            }
        }
        __syncthreads();

        // ---- F: LSTM cell (approx transcendentals) ----
        for (int i = tid; i < DBE * NS; i += DEC_THREADS) {
            int e = i >> 6, n = i & 63;
            float zi = zsd[e * GP + n]           + bps[n];
            float zf = zsd[e * GP + NS + n]      + bps[NS + n];
            float zg = zsd[e * GP + 2 * NS + n]  + bps[2 * NS + n];
            float zo = zsd[e * GP + 3 * NS + n]  + bps[3 * NS + n];
            float c = sigapx(zf) * cc[i] + sigapx(zi) * tanhapx(zg);
            float h = sigapx(zo) * tanhapx(c);
            cc[i] = c; ss[i] = h;
        }
        __syncthreads();

        // ---- G: out partials via float4 ss reads ----
        {
            #pragma unroll
            for (int ei = 0; ei < 8; ei++) {
                int e = eh * 8 + ei;
                const float4* sp = (const float4*)&ss[e * NS + wkh * 16];
                float p = 0.0f;
                #pragma unroll
                for (int q = 0; q < 4; q++) {
                    float4 sv = sp[q];
                    p += sv.x * wreg[4 * q]     + sv.y * wreg[4 * q + 1]
                       + sv.z * wreg[4 * q + 2] + sv.w * wreg[4 * q + 3];
                }
                zsd[(wkh * DBE + e) * 64 + wm] = p;
            }
        }
        __syncthreads();
        for (int i = tid; i < DBE * MV; i += DEC_THREADS) {
            int e = i >> 6, m = i & 63;
            float o = bos[m]
                    + zsd[(0 * DBE + e) * 64 + m] + zsd[(1 * DBE + e) * 64 + m]
                    + zsd[(2 * DBE + e) * 64 + m] + zsd[(3 * DBE + e) * 64 + m];
            out[((size_t)(b0 + e) * TY + t) * MV + m] = o;
        }
        __syncthreads();
    }
}

// ============================================================================
extern "C" void kernel_launch(void* const* d_in, const int* in_sizes, int n_in,
                              void* d_out, int out_size)
{
    const float* X      = (const float*)d_in[0];
    const float* W_ih_f = (const float*)d_in[1];
    const float* W_hh_f = (const float*)d_in[2];
    const float* b_f    = (const float*)d_in[3];
    const float* W_ih_r = (const float*)d_in[4];
    const float* W_hh_r = (const float*)d_in[5];
    const float* b_r    = (const float*)d_in[6];
    const float* W1     = (const float*)d_in[7];
    const float* b1     = (const float*)d_in[8];
    const float* W2     = (const float*)d_in[9];
    const float* b2     = (const float*)d_in[10];
    const float* W_ih_p = (const float*)d_in[11];
    const float* W_hh_p = (const float*)d_in[12];
    const float* b_p    = (const float*)d_in[13];
    const float* Wo     = (const float*)d_in[14];
    const float* bo     = (const float*)d_in[15];
    float* out = (float*)d_out;

    cudaFuncSetAttribute(encoder_fused,  cudaFuncAttributeMaxDynamicSharedMemorySize, ENC_SMEM_BYTES);
    cudaFuncSetAttribute(decoder_kernel, cudaFuncAttributeMaxDynamicSharedMemorySize, DEC_SMEM_BYTES);

    encoder_fused<<<B_TOT / EBE, ENC_THREADS, ENC_SMEM_BYTES>>>(
        X, W_ih_f, W_hh_f, b_f, W_ih_r, W_hh_r, b_r);

    decoder_kernel<<<B_TOT / DBE, DEC_THREADS, DEC_SMEM_BYTES>>>(W1, b1, W2, b2,
                                                                 W_ih_p, W_hh_p, b_p, Wo, bo, out);
}

// round 10
// speedup vs baseline: 3.7232x; 1.0312x over previous
#include <cuda_runtime.h>
#include <cuda_bf16.h>
#include <math.h>

#define B_TOT 16384
#define TX 30
#define TY 10
#define NA 32
#define NS 64
#define HV 128
#define MV 64
#define GE 128   // 4*NA
#define GP 256   // 4*NS

__device__ __align__(16) float g_a[(size_t)B_TOT * TX * (2 * NA)];   // 126 MB

__device__ __forceinline__ float tanhapx(float x) {
    float y;
    asm("tanh.approx.f32 %0, %1;" : "=f"(y) : "f"(x));
    return y;
}
__device__ __forceinline__ float sigapx(float x) {
    return fmaf(tanhapx(0.5f * x), 0.5f, 0.5f);
}
__device__ __forceinline__ unsigned cvt_tf32(float x) {
    unsigned u;
    asm("cvt.rna.tf32.f32 %0, %1;" : "=r"(u) : "f"(x));
    return u;
}
__device__ __forceinline__ unsigned pack_bf16(float a, float b) {
    __nv_bfloat162 h = __floats2bfloat162_rn(a, b);
    return *(unsigned*)&h;
}
__device__ __forceinline__ void mma_tf32(float* d, const unsigned* a, unsigned b0, unsigned b1) {
    asm("mma.sync.aligned.m16n8k8.row.col.f32.tf32.tf32.f32 "
        "{%0,%1,%2,%3}, {%4,%5,%6,%7}, {%8,%9}, {%0,%1,%2,%3};"
        : "+f"(d[0]), "+f"(d[1]), "+f"(d[2]), "+f"(d[3])
        : "r"(a[0]), "r"(a[1]), "r"(a[2]), "r"(a[3]), "r"(b0), "r"(b1));
}
__device__ __forceinline__ void mma_bf16(float* d, unsigned a0, unsigned a1,
                                         unsigned a2, unsigned a3,
                                         unsigned b0, unsigned b1) {
    asm("mma.sync.aligned.m16n8k16.row.col.f32.bf16.bf16.f32 "
        "{%0,%1,%2,%3}, {%4,%5,%6,%7}, {%8,%9}, {%0,%1,%2,%3};"
        : "+f"(d[0]), "+f"(d[1]), "+f"(d[2]), "+f"(d[3])
        : "r"(a0), "r"(a1), "r"(a2), "r"(a3), "r"(b0), "r"(b1));
}

// ============================================================================
// Fused encoder (identical to R9)
// ============================================================================
#define EBE 64
#define ENC_THREADS 512
#define XST 68
#define HST 20
#define ZST 260
#define ENC_SMEM_BYTES ((2*2*64*XST + 2*64*HST) * 4 + (64*ZST + 2*64*32 + 256) * 4)

__global__ __launch_bounds__(ENC_THREADS, 1)
void encoder_fused(const float* __restrict__ X,
                   const float* __restrict__ W_ih_f, const float* __restrict__ W_hh_f,
                   const float* __restrict__ b_f,
                   const float* __restrict__ W_ih_r, const float* __restrict__ W_hh_r,
                   const float* __restrict__ b_r)
{
    const int b0  = blockIdx.x * EBE;
    const int tid = threadIdx.x;
    const int warp = tid >> 5, lane = tid & 31;
    const int g = lane >> 2, tg = lane & 3;
    const int dir = warp >> 3;
    const int wl  = warp & 7;

    extern __shared__ unsigned smu[];
    unsigned* xs  = smu;
    unsigned* hbf = xs + 2 * 2 * 64 * XST;
    float* zs  = (float*)(hbf + 2 * 64 * HST);
    float* cst = zs + 64 * ZST;
    float* bs  = cst + 2 * 64 * 32;

    const float* Wi = dir ? W_ih_r : W_ih_f;
    const float* Wh = dir ? W_hh_r : W_hh_f;

    unsigned Bx[2][8][2], Bh[2][2][2];
    #pragma unroll
    for (int nt = 0; nt < 2; nt++) {
        int n = wl * 16 + nt * 8 + g;
        #pragma unroll
        for (int c = 0; c < 8; c++) {
            Bx[nt][c][0] = pack_bf16(Wi[n * 128 + c * 16 + 2 * tg],
                                     Wi[n * 128 + c * 16 + 2 * tg + 1]);
            Bx[nt][c][1] = pack_bf16(Wi[n * 128 + c * 16 + 8 + 2 * tg],
                                     Wi[n * 128 + c * 16 + 8 + 2 * tg + 1]);
        }
        #pragma unroll
        for (int c = 0; c < 2; c++) {
            Bh[nt][c][0] = pack_bf16(Wh[n * 32 + c * 16 + 2 * tg],
                                     Wh[n * 32 + c * 16 + 2 * tg + 1]);
            Bh[nt][c][1] = pack_bf16(Wh[n * 32 + c * 16 + 8 + 2 * tg],
                                     Wh[n * 32 + c * 16 + 8 + 2 * tg + 1]);
        }
    }

    for (int i = tid; i < 256; i += ENC_THREADS) bs[i] = (i < 128) ? b_f[i] : b_r[i - 128];
    for (int i = tid; i < 2 * 64 * HST; i += ENC_THREADS) hbf[i] = 0u;
    for (int i = tid; i < 2 * 64 * 32; i += ENC_THREADS) cst[i] = 0.0f;

    #pragma unroll
    for (int ii = 0; ii < 8; ii++) {
        int flat = tid + ii * ENC_THREADS;
        int dd = flat >> 11, r = flat & 2047;
        int row = r >> 5, q = r & 31;
        int ts = dd ? (TX - 1) : 0;
        float4 v = *(const float4*)(X + ((size_t)(b0 + row) * TX + ts) * HV + q * 4);
        int c = q >> 2, jj0 = (q & 3) * 2;
        int p0 = (jj0 & 3) * 2 + (jj0 >> 2);
        int p1 = ((jj0 + 1) & 3) * 2 + ((jj0 + 1) >> 2);
        unsigned* dst = &xs[((0 * 2 + dd) * 64 + row) * XST + c * 8];
        dst[p0] = pack_bf16(v.x, v.y);
        dst[p1] = pack_bf16(v.z, v.w);
    }
    __syncthreads();

    int buf = 0;
    for (int t = 0; t < TX; t++) {
        float4 xpre[8];
        #pragma unroll
        for (int ii = 0; ii < 8; ii++) {
            int flat = tid + ii * ENC_THREADS;
            int dd = flat >> 11, r = flat & 2047;
            int row = r >> 5, q = r & 31;
            int ts = dd ? max(TX - 2 - t, 0) : min(t + 1, TX - 1);
            xpre[ii] = *(const float4*)(X + ((size_t)(b0 + row) * TX + ts) * HV + q * 4);
        }

        float d[4][2][4];
        #pragma unroll
        for (int mi = 0; mi < 4; mi++)
            #pragma unroll
            for (int nt = 0; nt < 2; nt++)
                #pragma unroll
                for (int r = 0; r < 4; r++) d[mi][nt][r] = 0.0f;

        const unsigned* xbase = &xs[((buf * 2 + dir) * 64) * XST];
        #pragma unroll
        for (int c = 0; c < 8; c++) {
            unsigned a[4][4];
            #pragma unroll
            for (int mi = 0; mi < 4; mi++) {
                uint2 lo = *(uint2*)&xbase[(mi * 16 + g) * XST + c * 8 + 2 * tg];
                uint2 hi = *(uint2*)&xbase[(mi * 16 + 8 + g) * XST + c * 8 + 2 * tg];
                a[mi][0] = lo.x; a[mi][1] = hi.x; a[mi][2] = lo.y; a[mi][3] = hi.y;
            }
            #pragma unroll
            for (int mi = 0; mi < 4; mi++) {
                mma_bf16(d[mi][0], a[mi][0], a[mi][1], a[mi][2], a[mi][3],
                         Bx[0][c][0], Bx[0][c][1]);
                mma_bf16(d[mi][1], a[mi][0], a[mi][1], a[mi][2], a[mi][3],
                         Bx[1][c][0], Bx[1][c][1]);
            }
        }
        const unsigned* hbase = &hbf[(dir * 64) * HST];
        #pragma unroll
        for (int c = 0; c < 2; c++) {
            unsigned a[4][4];
            #pragma unroll
            for (int mi = 0; mi < 4; mi++) {
                uint2 lo = *(uint2*)&hbase[(mi * 16 + g) * HST + c * 8 + 2 * tg];
                uint2 hi = *(uint2*)&hbase[(mi * 16 + 8 + g) * HST + c * 8 + 2 * tg];
                a[mi][0] = lo.x; a[mi][1] = hi.x; a[mi][2] = lo.y; a[mi][3] = hi.y;
            }
            #pragma unroll
            for (int mi = 0; mi < 4; mi++) {
                mma_bf16(d[mi][0], a[mi][0], a[mi][1], a[mi][2], a[mi][3],
                         Bh[0][c][0], Bh[0][c][1]);
                mma_bf16(d[mi][1], a[mi][0], a[mi][1], a[mi][2], a[mi][3],
                         Bh[1][c][0], Bh[1][c][1]);
            }
        }

        #pragma unroll
        for (int mi = 0; mi < 4; mi++)
            #pragma unroll
            for (int nt = 0; nt < 2; nt++) {
                int col = dir * 128 + wl * 16 + nt * 8 + 2 * tg;
                *(float2*)&zs[(mi * 16 + g) * ZST + col] =
                    make_float2(d[mi][nt][0], d[mi][nt][1]);
                *(float2*)&zs[(mi * 16 + 8 + g) * ZST + col] =
                    make_float2(d[mi][nt][2], d[mi][nt][3]);
            }
        __syncthreads();

        #pragma unroll
        for (int ii = 0; ii < 8; ii++) {
            int flat = tid + ii * ENC_THREADS;
            int dd = flat >> 11, r = flat & 2047;
            int row = r >> 5, q = r & 31;
            int c = q >> 2, jj0 = (q & 3) * 2;
            int p0 = (jj0 & 3) * 2 + (jj0 >> 2);
            int p1 = ((jj0 + 1) & 3) * 2 + ((jj0 + 1) >> 2);
            unsigned* dst = &xs[(((buf ^ 1) * 2 + dd) * 64 + row) * XST + c * 8];
            dst[p0] = pack_bf16(xpre[ii].x, xpre[ii].y);
            dst[p1] = pack_bf16(xpre[ii].z, xpre[ii].w);
        }

        #pragma unroll
        for (int ii = 0; ii < 4; ii++) {
            int flat = tid + ii * ENC_THREADS;
            int e = flat >> 5, r = flat & 31;
            int dd = r >> 4, np = r & 15;
            int base = dd * 128 + 2 * np;
            float2 zi = *(float2*)&zs[e * ZST + base];
            float2 zf = *(float2*)&zs[e * ZST + base + 32];
            float2 zg = *(float2*)&zs[e * ZST + base + 64];
            float2 zo = *(float2*)&zs[e * ZST + base + 96];
            zi.x += bs[base];      zi.y += bs[base + 1];
            zf.x += bs[base + 32]; zf.y += bs[base + 33];
            zg.x += bs[base + 64]; zg.y += bs[base + 65];
            zo.x += bs[base + 96]; zo.y += bs[base + 97];
            float2 cold = *(float2*)&cst[dd * 2048 + e * 32 + 2 * np];
            float c0 = sigapx(zf.x) * cold.x + sigapx(zi.x) * tanhapx(zg.x);
            float c1 = sigapx(zf.y) * cold.y + sigapx(zi.y) * tanhapx(zg.y);
            float h0 = sigapx(zo.x) * tanhapx(c0);
            float h1 = sigapx(zo.y) * tanhapx(c1);
            *(float2*)&cst[dd * 2048 + e * 32 + 2 * np] = make_float2(c0, c1);
            hbf[(dd * 64 + e) * HST + (np >> 3) * 8 + ((np & 7) & 3) * 2 + ((np & 7) >> 2)]
                = pack_bf16(h0, h1);
            int tt = dd ? (TX - 1 - t) : t;
            *(float2*)(g_a + ((size_t)(b0 + e) * TX + tt) * 64 + dd * 32 + 2 * np)
                = make_float2(h0, h1);
        }
        __syncthreads();
        buf ^= 1;
    }
}

// ============================================================================
// Decoder v6: gate-interleaved mma fused with in-register LSTM cell.
// Column q = n*4 + gate; after mma, shfl_xor(1) assembles full gate sets,
// cell computed in registers (cc in regs), shfl_xor(2) gathers 4 n per elem
// for coalesced float4 ss writes (ss stride 68). zsd used only for G reduce.
// 3 barriers per step.
// ============================================================================
#define DBE 16
#define DEC_THREADS 512
#define SABST 34
#define EAST 11
#define W1ST 68
#define SSST 68
#define INSP_STRIDE 140

// layout in u32 units
#define OFF_SAB   0
#define SZ_SAB    (DBE * 32 * SABST)
#define OFF_EA    (OFF_SAB + SZ_SAB)
#define SZ_EA_AL  5284
#define OFF_W1A   (OFF_EA + SZ_EA_AL)
#define OFF_W1S   (OFF_W1A + 640)
#define OFF_B1S   (OFF_W1S + 680)
#define OFF_W2S   (OFF_B1S + 16)
#define OFF_BOS   (OFF_W2S + 16)
#define OFF_SS    (OFF_BOS + 64)
#define OFF_INSP  (OFF_SS + DBE * SSST)
#define OFF_ZSD   (OFF_INSP + DBE * INSP_STRIDE)
#define OFF_ALPH  (OFF_ZSD + DBE * GP)
#define DEC_UNITS (OFF_ALPH + DBE * 32)
#define DEC_SMEM_BYTES (DEC_UNITS * 4)

__global__ __launch_bounds__(DEC_THREADS, 1)
void decoder_kernel(const float* __restrict__ W1, const float* __restrict__ b1,
                    const float* __restrict__ W2, const float* __restrict__ b2,
                    const float* __restrict__ W_ih_p, const float* __restrict__ W_hh_p,
                    const float* __restrict__ b_p,
                    const float* __restrict__ Wo, const float* __restrict__ bo,
                    float* __restrict__ out)
{
    const int b0 = blockIdx.x * DBE;
    const int tid = threadIdx.x;
    const unsigned FULL = 0xffffffffu;

    extern __shared__ unsigned smw[];
    unsigned* sab = smw + OFF_SAB;
    float* ea   = (float*)(smw + OFF_EA);
    float* W1a  = (float*)(smw + OFF_W1A);
    float* W1s  = (float*)(smw + OFF_W1S);
    float* b1s  = (float*)(smw + OFF_B1S);
    float* W2s  = (float*)(smw + OFF_W2S);
    float* bos  = (float*)(smw + OFF_BOS);
    float* ss   = (float*)(smw + OFF_SS);
    unsigned* insp = smw + OFF_INSP;
    float* zsd  = (float*)(smw + OFF_ZSD);
    float* alph = (float*)(smw + OFF_ALPH);

    const int warp = tid >> 5, lane = tid & 31;
    const int g = lane >> 2, tg = lane & 3;

    // ---- gate-interleaved Wcat B-fragments: column q = n*4 + gate ----
    unsigned Bw[64];
    #pragma unroll
    for (int nt = 0; nt < 2; nt++) {
        int q  = warp * 16 + nt * 8 + g;
        int rr = (q & 3) * 64 + (q >> 2);     // original W row
        #pragma unroll
        for (int c = 0; c < 8; c++) {
            Bw[(nt * 16 + c) * 2 + 0] = cvt_tf32(W_ih_p[rr * 64 + c * 8 + tg]);
            Bw[(nt * 16 + c) * 2 + 1] = cvt_tf32(W_ih_p[rr * 64 + c * 8 + tg + 4]);
        }
        #pragma unroll
        for (int c = 0; c < 8; c++) {
            Bw[(nt * 16 + (8 + c)) * 2 + 0] = cvt_tf32(W_hh_p[rr * 64 + c * 8 + tg]);
            Bw[(nt * 16 + (8 + c)) * 2 + 1] = cvt_tf32(W_hh_p[rr * 64 + c * 8 + tg + 4]);
        }
    }
    // per-lane column biases (cols q0 = warp*16+nt*8+2tg, q0+1)
    float bcol[2][2];
    #pragma unroll
    for (int nt = 0; nt < 2; nt++) {
        int q0 = warp * 16 + nt * 8 + 2 * tg;
        bcol[nt][0] = b_p[(q0 & 3) * 64 + (q0 >> 2)];
        bcol[nt][1] = b_p[((q0 + 1) & 3) * 64 + ((q0 + 1) >> 2)];
    }
    float ccr[2] = {0.0f, 0.0f};   // cell state for this lane's 2 cells

    const int wm = tid & 63, wkh = (tid >> 6) & 3, eh = tid >> 8;
    float wreg[16];
    #pragma unroll
    for (int kk = 0; kk < 16; kk++) wreg[kk] = Wo[wm * 64 + wkh * 16 + kk];

    for (int i = tid; i < 640; i += DEC_THREADS) {
        int j = i / 64, d = i % 64;
        W1a[i]            = W1[j * 128 + d];
        W1s[j * W1ST + d] = W1[j * 128 + 64 + d];
    }
    if (tid < 10) { b1s[tid] = b1[tid]; W2s[tid] = W2[tid]; }
    if (tid < MV) bos[tid] = bo[tid];
    for (int i = tid; i < DBE * SSST; i += DEC_THREADS) ss[i] = 0.0f;
    const float b2v = b2[0];

    // zero pad rows 30,31 of sab
    for (int i = tid; i < DBE * 2 * SABST; i += DEC_THREADS) {
        int e = i / (2 * SABST), r = i % (2 * SABST);
        sab[(e * 32 + 30) * SABST + r] = 0u;
    }
    // load a tile as bf16x2
    for (int i = tid; i < DBE * TX * 16; i += DEC_THREADS) {
        int e = i / (TX * 16);
        int r = i % (TX * 16);
        int tx = r / 16, d4 = r % 16;
        float4 v = *(const float4*)(g_a + ((size_t)(b0 + e) * TX + tx) * (2 * NA) + d4 * 4);
        sab[(e * 32 + tx) * SABST + 2 * d4]     = pack_bf16(v.x, v.y);
        sab[(e * 32 + tx) * SABST + 2 * d4 + 1] = pack_bf16(v.z, v.w);
    }
    __syncthreads();

    // Ea precompute
    if (tid < DBE * TX) {
        int e = tid / TX, tx = tid % TX;
        float acc[10];
        #pragma unroll
        for (int j = 0; j < 10; j++) acc[j] = 0.0f;
        #pragma unroll 4
        for (int d2 = 0; d2 < 32; d2++) {
            unsigned av = sab[(e * 32 + tx) * SABST + d2];
            float f0 = __uint_as_float(av << 16);
            float f1 = __uint_as_float(av & 0xffff0000u);
            #pragma unroll
            for (int j = 0; j < 10; j++)
                acc[j] += f0 * W1a[j * 64 + 2 * d2] + f1 * W1a[j * 64 + 2 * d2 + 1];
        }
        #pragma unroll
        for (int j = 0; j < 10; j++) ea[(e * TX + tx) * EAST + j] = acc[j];
    }
    __syncthreads();

    for (int t = 0; t < TY; t++) {
        // ---- A+B+C: warp e = attention for element e (warp-local) ----
        {
            const int e = warp;
            float accA = 0.0f;
            if (lane < 20) {
                int j = lane >> 1, half = lane & 1;
                const float4* sp = (const float4*)&ss[e * SSST + half * 32];
                const float4* wp = (const float4*)&W1s[j * W1ST + half * 32];
                #pragma unroll
                for (int q = 0; q < 8; q++) {
                    float4 sv = sp[q], wv = wp[q];
                    accA += sv.x * wv.x + sv.y * wv.y + sv.z * wv.z + sv.w * wv.w;
                }
            }
            accA += __shfl_xor_sync(FULL, accA, 1);
            if (lane < 20) accA += b1s[lane >> 1];

            int txc = (lane < TX) ? lane : 0;
            float acc = b2v;
            #pragma unroll
            for (int j = 0; j < 10; j++) {
                float esj = __shfl_sync(FULL, accA, 2 * j);
                acc += tanhapx(ea[(e * TX + txc) * EAST + j] + esj) * W2s[j];
            }
            float en = (lane < TX) ? fmaxf(acc, 0.0f) : -1e30f;

            float mx = en;
            #pragma unroll
            for (int o = 16; o; o >>= 1) mx = fmaxf(mx, __shfl_xor_sync(FULL, mx, o));
            float ex = (lane < TX) ? __expf(en - mx) : 0.0f;
            float sum = ex;
            #pragma unroll
            for (int o = 16; o; o >>= 1) sum += __shfl_xor_sync(FULL, sum, o);
            alph[e * 32 + lane] = ex * __fdividef(1.0f, sum);
        }
        __syncwarp();

        // ---- D: context pair-per-thread -> insp (warp-local alph/insp rows) ----
        {
            const int e = tid >> 5, d2 = tid & 31;
            const float4* ap = (const float4*)&alph[e * 32];
            float ctx0 = 0.0f, ctx1 = 0.0f;
            #pragma unroll
            for (int c = 0; c < 8; c++) {
                float4 a4 = ap[c];
                unsigned v0 = sab[(e * 32 + 4 * c + 0) * SABST + d2];
                unsigned v1 = sab[(e * 32 + 4 * c + 1) * SABST + d2];
                unsigned v2 = sab[(e * 32 + 4 * c + 2) * SABST + d2];
                unsigned v3 = sab[(e * 32 + 4 * c + 3) * SABST + d2];
                ctx0 += a4.x * __uint_as_float(v0 << 16)
                      + a4.y * __uint_as_float(v1 << 16)
                      + a4.z * __uint_as_float(v2 << 16)
                      + a4.w * __uint_as_float(v3 << 16);
                ctx1 += a4.x * __uint_as_float(v0 & 0xffff0000u)
                      + a4.y * __uint_as_float(v1 & 0xffff0000u)
                      + a4.z * __uint_as_float(v2 & 0xffff0000u)
                      + a4.w * __uint_as_float(v3 & 0xffff0000u);
            }
            int d0 = 2 * d2;
            int c0 = d0 >> 3, jj0 = d0 & 7;
            int p0 = (jj0 & 3) * 2 + (jj0 >> 2);
            int p1 = ((jj0 + 1) & 3) * 2 + ((jj0 + 1) >> 2);
            insp[e * INSP_STRIDE + c0 * 8 + p0] = cvt_tf32(ctx0);
            insp[e * INSP_STRIDE + c0 * 8 + p1] = cvt_tf32(ctx1);
            float2 sv = *(const float2*)&ss[e * SSST + d0];
            insp[e * INSP_STRIDE + (8 + c0) * 8 + p0] = cvt_tf32(sv.x);
            insp[e * INSP_STRIDE + (8 + c0) * 8 + p1] = cvt_tf32(sv.y);
        }
        __syncthreads();

        // ---- E+F fused: gate-interleaved mma + in-register cell ----
        {
            float dd[2][4];
            #pragma unroll
            for (int nt = 0; nt < 2; nt++)
                #pragma unroll
                for (int r = 0; r < 4; r++) dd[nt][r] = 0.0f;
            #pragma unroll
            for (int c = 0; c < 16; c++) {
                uint2 va = *(uint2*)&insp[g * INSP_STRIDE + c * 8 + 2 * tg];
                uint2 vb = *(uint2*)&insp[(g + 8) * INSP_STRIDE + c * 8 + 2 * tg];
                unsigned a[4] = {va.x, vb.x, va.y, vb.y};
                mma_tf32(dd[0], a, Bw[(0 * 16 + c) * 2], Bw[(0 * 16 + c) * 2 + 1]);
                mma_tf32(dd[1], a, Bw[(1 * 16 + c) * 2], Bw[(1 * 16 + c) * 2 + 1]);
            }
            // bias + cell in registers
            float hh[2];
            #pragma unroll
            for (int nt = 0; nt < 2; nt++) {
                dd[nt][0] += bcol[nt][0]; dd[nt][1] += bcol[nt][1];
                dd[nt][2] += bcol[nt][0]; dd[nt][3] += bcol[nt][1];
                float ex0 = __shfl_xor_sync(FULL, dd[nt][0], 1);
                float ex1 = __shfl_xor_sync(FULL, dd[nt][1], 1);
                float ex2 = __shfl_xor_sync(FULL, dd[nt][2], 1);
                float ex3 = __shfl_xor_sync(FULL, dd[nt][3], 1);
                bool odd = (tg & 1);
                // even lane: row g cell (own zi,zf; partner zg,zo)
                // odd  lane: row g+8 cell (partner zi,zf; own zg,zo)
                float zi = odd ? ex2        : dd[nt][0];
                float zf = odd ? ex3        : dd[nt][1];
                float zg = odd ? dd[nt][2]  : ex0;
                float zo = odd ? dd[nt][3]  : ex1;
                float c = sigapx(zf) * ccr[nt] + sigapx(zi) * tanhapx(zg);
                float h = sigapx(zo) * tanhapx(c);
                ccr[nt] = c;
                hh[nt] = h;
            }
            // gather 4 n-values per elem, coalesced float4 ss write
            float r0 = __shfl_xor_sync(FULL, hh[0], 2);
            float r1 = __shfl_xor_sync(FULL, hh[1], 2);
            if (tg < 2) {
                int e = g + 8 * (tg & 1);
                *(float4*)&ss[e * SSST + warp * 4] = make_float4(hh[0], r0, hh[1], r1);
            }
        }
        __syncthreads();

        // ---- G: out partials via float4 ss reads ----
        {
            #pragma unroll
            for (int ei = 0; ei < 8; ei++) {
                int e = eh * 8 + ei;
                const float4* sp = (const float4*)&ss[e * SSST + wkh * 16];
                float p = 0.0f;
                #pragma unroll
                for (int q = 0; q < 4; q++) {
                    float4 sv = sp[q];
                    p += sv.x * wreg[4 * q]     + sv.y * wreg[4 * q + 1]
                       + sv.z * wreg[4 * q + 2] + sv.w * wreg[4 * q + 3];
                }
                zsd[(wkh * DBE + e) * 64 + wm] = p;
            }
        }
        __syncthreads();
        for (int i = tid; i < DBE * MV; i += DEC_THREADS) {
            int e = i >> 6, m = i & 63;
            float o = bos[m]
                    + zsd[(0 * DBE + e) * 64 + m] + zsd[(1 * DBE + e) * 64 + m]
                    + zsd[(2 * DBE + e) * 64 + m] + zsd[(3 * DBE + e) * 64 + m];
            out[((size_t)(b0 + e) * TY + t) * MV + m] = o;
        }
        __syncthreads();
    }
}

// ============================================================================
extern "C" void kernel_launch(void* const* d_in, const int* in_sizes, int n_in,
                              void* d_out, int out_size)
{
    const float* X      = (const float*)d_in[0];
    const float* W_ih_f = (const float*)d_in[1];
    const float* W_hh_f = (const float*)d_in[2];
    const float* b_f    = (const float*)d_in[3];
    const float* W_ih_r = (const float*)d_in[4];
    const float* W_hh_r = (const float*)d_in[5];
    const float* b_r    = (const float*)d_in[6];
    const float* W1     = (const float*)d_in[7];
    const float* b1     = (const float*)d_in[8];
    const float* W2     = (const float*)d_in[9];
    const float* b2     = (const float*)d_in[10];
    const float* W_ih_p = (const float*)d_in[11];
    const float* W_hh_p = (const float*)d_in[12];
    const float* b_p    = (const float*)d_in[13];
    const float* Wo     = (const float*)d_in[14];
    const float* bo     = (const float*)d_in[15];
    float* out = (float*)d_out;

    cudaFuncSetAttribute(encoder_fused,  cudaFuncAttributeMaxDynamicSharedMemorySize, ENC_SMEM_BYTES);
    cudaFuncSetAttribute(decoder_kernel, cudaFuncAttributeMaxDynamicSharedMemorySize, DEC_SMEM_BYTES);

    encoder_fused<<<B_TOT / EBE, ENC_THREADS, ENC_SMEM_BYTES>>>(
        X, W_ih_f, W_hh_f, b_f, W_ih_r, W_hh_r, b_r);

    decoder_kernel<<<B_TOT / DBE, DEC_THREADS, DEC_SMEM_BYTES>>>(W1, b1, W2, b2,
                                                                 W_ih_p, W_hh_p, b_p, Wo, bo, out);
}

// round 11
// speedup vs baseline: 3.8996x; 1.0474x over previous
#include <cuda_runtime.h>
#include <cuda_bf16.h>
#include <math.h>

#define B_TOT 16384
#define TX 30
#define TY 10
#define NA 32
#define NS 64
#define HV 128
#define MV 64
#define GE 128   // 4*NA
#define GP 256   // 4*NS

__device__ __align__(16) float g_a[(size_t)B_TOT * TX * (2 * NA)];   // 126 MB

__device__ __forceinline__ float tanhapx(float x) {
    float y;
    asm("tanh.approx.f32 %0, %1;" : "=f"(y) : "f"(x));
    return y;
}
__device__ __forceinline__ float sigapx(float x) {
    return fmaf(tanhapx(0.5f * x), 0.5f, 0.5f);
}
__device__ __forceinline__ unsigned cvt_tf32(float x) {
    unsigned u;
    asm("cvt.rna.tf32.f32 %0, %1;" : "=r"(u) : "f"(x));
    return u;
}
__device__ __forceinline__ unsigned pack_bf16(float a, float b) {
    __nv_bfloat162 h = __floats2bfloat162_rn(a, b);
    return *(unsigned*)&h;
}
__device__ __forceinline__ void mma_tf32(float* d, const unsigned* a, unsigned b0, unsigned b1) {
    asm("mma.sync.aligned.m16n8k8.row.col.f32.tf32.tf32.f32 "
        "{%0,%1,%2,%3}, {%4,%5,%6,%7}, {%8,%9}, {%0,%1,%2,%3};"
        : "+f"(d[0]), "+f"(d[1]), "+f"(d[2]), "+f"(d[3])
        : "r"(a[0]), "r"(a[1]), "r"(a[2]), "r"(a[3]), "r"(b0), "r"(b1));
}
__device__ __forceinline__ void mma_bf16(float* d, unsigned a0, unsigned a1,
                                         unsigned a2, unsigned a3,
                                         unsigned b0, unsigned b1) {
    asm("mma.sync.aligned.m16n8k16.row.col.f32.bf16.bf16.f32 "
        "{%0,%1,%2,%3}, {%4,%5,%6,%7}, {%8,%9}, {%0,%1,%2,%3};"
        : "+f"(d[0]), "+f"(d[1]), "+f"(d[2]), "+f"(d[3])
        : "r"(a0), "r"(a1), "r"(a2), "r"(a3), "r"(b0), "r"(b1));
}

// ============================================================================
// Fused encoder (identical to R10)
// ============================================================================
#define EBE 64
#define ENC_THREADS 512
#define XST 68
#define HST 20
#define ZST 260
#define ENC_SMEM_BYTES ((2*2*64*XST + 2*64*HST) * 4 + (64*ZST + 2*64*32 + 256) * 4)

__global__ __launch_bounds__(ENC_THREADS, 1)
void encoder_fused(const float* __restrict__ X,
                   const float* __restrict__ W_ih_f, const float* __restrict__ W_hh_f,
                   const float* __restrict__ b_f,
                   const float* __restrict__ W_ih_r, const float* __restrict__ W_hh_r,
                   const float* __restrict__ b_r)
{
    const int b0  = blockIdx.x * EBE;
    const int tid = threadIdx.x;
    const int warp = tid >> 5, lane = tid & 31;
    const int g = lane >> 2, tg = lane & 3;
    const int dir = warp >> 3;
    const int wl  = warp & 7;

    extern __shared__ unsigned smu[];
    unsigned* xs  = smu;
    unsigned* hbf = xs + 2 * 2 * 64 * XST;
    float* zs  = (float*)(hbf + 2 * 64 * HST);
    float* cst = zs + 64 * ZST;
    float* bs  = cst + 2 * 64 * 32;

    const float* Wi = dir ? W_ih_r : W_ih_f;
    const float* Wh = dir ? W_hh_r : W_hh_f;

    unsigned Bx[2][8][2], Bh[2][2][2];
    #pragma unroll
    for (int nt = 0; nt < 2; nt++) {
        int n = wl * 16 + nt * 8 + g;
        #pragma unroll
        for (int c = 0; c < 8; c++) {
            Bx[nt][c][0] = pack_bf16(Wi[n * 128 + c * 16 + 2 * tg],
                                     Wi[n * 128 + c * 16 + 2 * tg + 1]);
            Bx[nt][c][1] = pack_bf16(Wi[n * 128 + c * 16 + 8 + 2 * tg],
                                     Wi[n * 128 + c * 16 + 8 + 2 * tg + 1]);
        }
        #pragma unroll
        for (int c = 0; c < 2; c++) {
            Bh[nt][c][0] = pack_bf16(Wh[n * 32 + c * 16 + 2 * tg],
                                     Wh[n * 32 + c * 16 + 2 * tg + 1]);
            Bh[nt][c][1] = pack_bf16(Wh[n * 32 + c * 16 + 8 + 2 * tg],
                                     Wh[n * 32 + c * 16 + 8 + 2 * tg + 1]);
        }
    }

    for (int i = tid; i < 256; i += ENC_THREADS) bs[i] = (i < 128) ? b_f[i] : b_r[i - 128];
    for (int i = tid; i < 2 * 64 * HST; i += ENC_THREADS) hbf[i] = 0u;
    for (int i = tid; i < 2 * 64 * 32; i += ENC_THREADS) cst[i] = 0.0f;

    #pragma unroll
    for (int ii = 0; ii < 8; ii++) {
        int flat = tid + ii * ENC_THREADS;
        int dd = flat >> 11, r = flat & 2047;
        int row = r >> 5, q = r & 31;
        int ts = dd ? (TX - 1) : 0;
        float4 v = *(const float4*)(X + ((size_t)(b0 + row) * TX + ts) * HV + q * 4);
        int c = q >> 2, jj0 = (q & 3) * 2;
        int p0 = (jj0 & 3) * 2 + (jj0 >> 2);
        int p1 = ((jj0 + 1) & 3) * 2 + ((jj0 + 1) >> 2);
        unsigned* dst = &xs[((0 * 2 + dd) * 64 + row) * XST + c * 8];
        dst[p0] = pack_bf16(v.x, v.y);
        dst[p1] = pack_bf16(v.z, v.w);
    }
    __syncthreads();

    int buf = 0;
    for (int t = 0; t < TX; t++) {
        float4 xpre[8];
        #pragma unroll
        for (int ii = 0; ii < 8; ii++) {
            int flat = tid + ii * ENC_THREADS;
            int dd = flat >> 11, r = flat & 2047;
            int row = r >> 5, q = r & 31;
            int ts = dd ? max(TX - 2 - t, 0) : min(t + 1, TX - 1);
            xpre[ii] = *(const float4*)(X + ((size_t)(b0 + row) * TX + ts) * HV + q * 4);
        }

        float d[4][2][4];
        #pragma unroll
        for (int mi = 0; mi < 4; mi++)
            #pragma unroll
            for (int nt = 0; nt < 2; nt++)
                #pragma unroll
                for (int r = 0; r < 4; r++) d[mi][nt][r] = 0.0f;

        const unsigned* xbase = &xs[((buf * 2 + dir) * 64) * XST];
        #pragma unroll
        for (int c = 0; c < 8; c++) {
            unsigned a[4][4];
            #pragma unroll
            for (int mi = 0; mi < 4; mi++) {
                uint2 lo = *(uint2*)&xbase[(mi * 16 + g) * XST + c * 8 + 2 * tg];
                uint2 hi = *(uint2*)&xbase[(mi * 16 + 8 + g) * XST + c * 8 + 2 * tg];
                a[mi][0] = lo.x; a[mi][1] = hi.x; a[mi][2] = lo.y; a[mi][3] = hi.y;
            }
            #pragma unroll
            for (int mi = 0; mi < 4; mi++) {
                mma_bf16(d[mi][0], a[mi][0], a[mi][1], a[mi][2], a[mi][3],
                         Bx[0][c][0], Bx[0][c][1]);
                mma_bf16(d[mi][1], a[mi][0], a[mi][1], a[mi][2], a[mi][3],
                         Bx[1][c][0], Bx[1][c][1]);
            }
        }
        const unsigned* hbase = &hbf[(dir * 64) * HST];
        #pragma unroll
        for (int c = 0; c < 2; c++) {
            unsigned a[4][4];
            #pragma unroll
            for (int mi = 0; mi < 4; mi++) {
                uint2 lo = *(uint2*)&hbase[(mi * 16 + g) * HST + c * 8 + 2 * tg];
                uint2 hi = *(uint2*)&hbase[(mi * 16 + 8 + g) * HST + c * 8 + 2 * tg];
                a[mi][0] = lo.x; a[mi][1] = hi.x; a[mi][2] = lo.y; a[mi][3] = hi.y;
            }
            #pragma unroll
            for (int mi = 0; mi < 4; mi++) {
                mma_bf16(d[mi][0], a[mi][0], a[mi][1], a[mi][2], a[mi][3],
                         Bh[0][c][0], Bh[0][c][1]);
                mma_bf16(d[mi][1], a[mi][0], a[mi][1], a[mi][2], a[mi][3],
                         Bh[1][c][0], Bh[1][c][1]);
            }
        }

        #pragma unroll
        for (int mi = 0; mi < 4; mi++)
            #pragma unroll
            for (int nt = 0; nt < 2; nt++) {
                int col = dir * 128 + wl * 16 + nt * 8 + 2 * tg;
                *(float2*)&zs[(mi * 16 + g) * ZST + col] =
                    make_float2(d[mi][nt][0], d[mi][nt][1]);
                *(float2*)&zs[(mi * 16 + 8 + g) * ZST + col] =
                    make_float2(d[mi][nt][2], d[mi][nt][3]);
            }
        __syncthreads();

        #pragma unroll
        for (int ii = 0; ii < 8; ii++) {
            int flat = tid + ii * ENC_THREADS;
            int dd = flat >> 11, r = flat & 2047;
            int row = r >> 5, q = r & 31;
            int c = q >> 2, jj0 = (q & 3) * 2;
            int p0 = (jj0 & 3) * 2 + (jj0 >> 2);
            int p1 = ((jj0 + 1) & 3) * 2 + ((jj0 + 1) >> 2);
            unsigned* dst = &xs[(((buf ^ 1) * 2 + dd) * 64 + row) * XST + c * 8];
            dst[p0] = pack_bf16(xpre[ii].x, xpre[ii].y);
            dst[p1] = pack_bf16(xpre[ii].z, xpre[ii].w);
        }

        #pragma unroll
        for (int ii = 0; ii < 4; ii++) {
            int flat = tid + ii * ENC_THREADS;
            int e = flat >> 5, r = flat & 31;
            int dd = r >> 4, np = r & 15;
            int base = dd * 128 + 2 * np;
            float2 zi = *(float2*)&zs[e * ZST + base];
            float2 zf = *(float2*)&zs[e * ZST + base + 32];
            float2 zg = *(float2*)&zs[e * ZST + base + 64];
            float2 zo = *(float2*)&zs[e * ZST + base + 96];
            zi.x += bs[base];      zi.y += bs[base + 1];
            zf.x += bs[base + 32]; zf.y += bs[base + 33];
            zg.x += bs[base + 64]; zg.y += bs[base + 65];
            zo.x += bs[base + 96]; zo.y += bs[base + 97];
            float2 cold = *(float2*)&cst[dd * 2048 + e * 32 + 2 * np];
            float c0 = sigapx(zf.x) * cold.x + sigapx(zi.x) * tanhapx(zg.x);
            float c1 = sigapx(zf.y) * cold.y + sigapx(zi.y) * tanhapx(zg.y);
            float h0 = sigapx(zo.x) * tanhapx(c0);
            float h1 = sigapx(zo.y) * tanhapx(c1);
            *(float2*)&cst[dd * 2048 + e * 32 + 2 * np] = make_float2(c0, c1);
            hbf[(dd * 64 + e) * HST + (np >> 3) * 8 + ((np & 7) & 3) * 2 + ((np & 7) >> 2)]
                = pack_bf16(h0, h1);
            int tt = dd ? (TX - 1 - t) : t;
            *(float2*)(g_a + ((size_t)(b0 + e) * TX + tt) * 64 + dd * 32 + 2 * np)
                = make_float2(h0, h1);
        }
        __syncthreads();
        buf ^= 1;
    }
}

// ============================================================================
// Decoder v7: R10 + (a) INSP_STRIDE 136 (conflict-optimal E reads),
// (b) zsd double-buffered by step parity -> trailing barrier removed.
// 3 barriers/step: after D (insp all-to-all), after EF (ss all-to-all),
// after G partials (zsd all-to-all). Next-step WAR on ss/alph/insp is
// covered by those same barriers (A/D touch only warp-own rows).
// ============================================================================
#define DBE 16
#define DEC_THREADS 512
#define SABST 34
#define EAST 11
#define W1ST 68
#define SSST 68
#define INSP_STRIDE 136   // ≡8 mod 32: E's uint2 reads hit each bank exactly 2x

// layout in u32 units
#define OFF_SAB   0
#define SZ_SAB    (DBE * 32 * SABST)
#define OFF_EA    (OFF_SAB + SZ_SAB)
#define SZ_EA_AL  5284
#define OFF_W1A   (OFF_EA + SZ_EA_AL)
#define OFF_W1S   (OFF_W1A + 640)
#define OFF_B1S   (OFF_W1S + 680)
#define OFF_W2S   (OFF_B1S + 16)
#define OFF_BOS   (OFF_W2S + 16)
#define OFF_SS    (OFF_BOS + 64)
#define OFF_INSP  (OFF_SS + DBE * SSST)
#define OFF_ZSD   (OFF_INSP + DBE * INSP_STRIDE)
#define OFF_ALPH  (OFF_ZSD + 2 * DBE * GP)     // double-buffered zsd
#define DEC_UNITS (OFF_ALPH + DBE * 32)
#define DEC_SMEM_BYTES (DEC_UNITS * 4)

__global__ __launch_bounds__(DEC_THREADS, 1)
void decoder_kernel(const float* __restrict__ W1, const float* __restrict__ b1,
                    const float* __restrict__ W2, const float* __restrict__ b2,
                    const float* __restrict__ W_ih_p, const float* __restrict__ W_hh_p,
                    const float* __restrict__ b_p,
                    const float* __restrict__ Wo, const float* __restrict__ bo,
                    float* __restrict__ out)
{
    const int b0 = blockIdx.x * DBE;
    const int tid = threadIdx.x;
    const unsigned FULL = 0xffffffffu;

    extern __shared__ unsigned smw[];
    unsigned* sab = smw + OFF_SAB;
    float* ea   = (float*)(smw + OFF_EA);
    float* W1a  = (float*)(smw + OFF_W1A);
    float* W1s  = (float*)(smw + OFF_W1S);
    float* b1s  = (float*)(smw + OFF_B1S);
    float* W2s  = (float*)(smw + OFF_W2S);
    float* bos  = (float*)(smw + OFF_BOS);
    float* ss   = (float*)(smw + OFF_SS);
    unsigned* insp = smw + OFF_INSP;
    float* zsd  = (float*)(smw + OFF_ZSD);
    float* alph = (float*)(smw + OFF_ALPH);

    const int warp = tid >> 5, lane = tid & 31;
    const int g = lane >> 2, tg = lane & 3;

    // gate-interleaved Wcat B-fragments: column q = n*4 + gate
    unsigned Bw[64];
    #pragma unroll
    for (int nt = 0; nt < 2; nt++) {
        int q  = warp * 16 + nt * 8 + g;
        int rr = (q & 3) * 64 + (q >> 2);
        #pragma unroll
        for (int c = 0; c < 8; c++) {
            Bw[(nt * 16 + c) * 2 + 0] = cvt_tf32(W_ih_p[rr * 64 + c * 8 + tg]);
            Bw[(nt * 16 + c) * 2 + 1] = cvt_tf32(W_ih_p[rr * 64 + c * 8 + tg + 4]);
        }
        #pragma unroll
        for (int c = 0; c < 8; c++) {
            Bw[(nt * 16 + (8 + c)) * 2 + 0] = cvt_tf32(W_hh_p[rr * 64 + c * 8 + tg]);
            Bw[(nt * 16 + (8 + c)) * 2 + 1] = cvt_tf32(W_hh_p[rr * 64 + c * 8 + tg + 4]);
        }
    }
    float bcol[2][2];
    #pragma unroll
    for (int nt = 0; nt < 2; nt++) {
        int q0 = warp * 16 + nt * 8 + 2 * tg;
        bcol[nt][0] = b_p[(q0 & 3) * 64 + (q0 >> 2)];
        bcol[nt][1] = b_p[((q0 + 1) & 3) * 64 + ((q0 + 1) >> 2)];
    }
    float ccr[2] = {0.0f, 0.0f};

    const int wm = tid & 63, wkh = (tid >> 6) & 3, eh = tid >> 8;
    float wreg[16];
    #pragma unroll
    for (int kk = 0; kk < 16; kk++) wreg[kk] = Wo[wm * 64 + wkh * 16 + kk];

    for (int i = tid; i < 640; i += DEC_THREADS) {
        int j = i / 64, d = i % 64;
        W1a[i]            = W1[j * 128 + d];
        W1s[j * W1ST + d] = W1[j * 128 + 64 + d];
    }
    if (tid < 10) { b1s[tid] = b1[tid]; W2s[tid] = W2[tid]; }
    if (tid < MV) bos[tid] = bo[tid];
    for (int i = tid; i < DBE * SSST; i += DEC_THREADS) ss[i] = 0.0f;
    const float b2v = b2[0];

    for (int i = tid; i < DBE * 2 * SABST; i += DEC_THREADS) {
        int e = i / (2 * SABST), r = i % (2 * SABST);
        sab[(e * 32 + 30) * SABST + r] = 0u;
    }
    for (int i = tid; i < DBE * TX * 16; i += DEC_THREADS) {
        int e = i / (TX * 16);
        int r = i % (TX * 16);
        int tx = r / 16, d4 = r % 16;
        float4 v = *(const float4*)(g_a + ((size_t)(b0 + e) * TX + tx) * (2 * NA) + d4 * 4);
        sab[(e * 32 + tx) * SABST + 2 * d4]     = pack_bf16(v.x, v.y);
        sab[(e * 32 + tx) * SABST + 2 * d4 + 1] = pack_bf16(v.z, v.w);
    }
    __syncthreads();

    if (tid < DBE * TX) {
        int e = tid / TX, tx = tid % TX;
        float acc[10];
        #pragma unroll
        for (int j = 0; j < 10; j++) acc[j] = 0.0f;
        #pragma unroll 4
        for (int d2 = 0; d2 < 32; d2++) {
            unsigned av = sab[(e * 32 + tx) * SABST + d2];
            float f0 = __uint_as_float(av << 16);
            float f1 = __uint_as_float(av & 0xffff0000u);
            #pragma unroll
            for (int j = 0; j < 10; j++)
                acc[j] += f0 * W1a[j * 64 + 2 * d2] + f1 * W1a[j * 64 + 2 * d2 + 1];
        }
        #pragma unroll
        for (int j = 0; j < 10; j++) ea[(e * TX + tx) * EAST + j] = acc[j];
    }
    __syncthreads();

    for (int t = 0; t < TY; t++) {
        float* zb = zsd + (t & 1) * (DBE * GP);   // parity buffer

        // ---- A+B+C: warp e = attention for element e (warp-local) ----
        {
            const int e = warp;
            float accA = 0.0f;
            if (lane < 20) {
                int j = lane >> 1, half = lane & 1;
                const float4* sp = (const float4*)&ss[e * SSST + half * 32];
                const float4* wp = (const float4*)&W1s[j * W1ST + half * 32];
                #pragma unroll
                for (int q = 0; q < 8; q++) {
                    float4 sv = sp[q], wv = wp[q];
                    accA += sv.x * wv.x + sv.y * wv.y + sv.z * wv.z + sv.w * wv.w;
                }
            }
            accA += __shfl_xor_sync(FULL, accA, 1);
            if (lane < 20) accA += b1s[lane >> 1];

            int txc = (lane < TX) ? lane : 0;
            float acc = b2v;
            #pragma unroll
            for (int j = 0; j < 10; j++) {
                float esj = __shfl_sync(FULL, accA, 2 * j);
                acc += tanhapx(ea[(e * TX + txc) * EAST + j] + esj) * W2s[j];
            }
            float en = (lane < TX) ? fmaxf(acc, 0.0f) : -1e30f;

            float mx = en;
            #pragma unroll
            for (int o = 16; o; o >>= 1) mx = fmaxf(mx, __shfl_xor_sync(FULL, mx, o));
            float ex = (lane < TX) ? __expf(en - mx) : 0.0f;
            float sum = ex;
            #pragma unroll
            for (int o = 16; o; o >>= 1) sum += __shfl_xor_sync(FULL, sum, o);
            alph[e * 32 + lane] = ex * __fdividef(1.0f, sum);
        }
        __syncwarp();

        // ---- D: context pair-per-thread -> insp (warp-local rows) ----
        {
            const int e = tid >> 5, d2 = tid & 31;
            const float4* ap = (const float4*)&alph[e * 32];
            float ctx0 = 0.0f, ctx1 = 0.0f;
            #pragma unroll
            for (int c = 0; c < 8; c++) {
                float4 a4 = ap[c];
                unsigned v0 = sab[(e * 32 + 4 * c + 0) * SABST + d2];
                unsigned v1 = sab[(e * 32 + 4 * c + 1) * SABST + d2];
                unsigned v2 = sab[(e * 32 + 4 * c + 2) * SABST + d2];
                unsigned v3 = sab[(e * 32 + 4 * c + 3) * SABST + d2];
                ctx0 += a4.x * __uint_as_float(v0 << 16)
                      + a4.y * __uint_as_float(v1 << 16)
                      + a4.z * __uint_as_float(v2 << 16)
                      + a4.w * __uint_as_float(v3 << 16);
                ctx1 += a4.x * __uint_as_float(v0 & 0xffff0000u)
                      + a4.y * __uint_as_float(v1 & 0xffff0000u)
                      + a4.z * __uint_as_float(v2 & 0xffff0000u)
                      + a4.w * __uint_as_float(v3 & 0xffff0000u);
            }
            int d0 = 2 * d2;
            int c0 = d0 >> 3, jj0 = d0 & 7;
            int p0 = (jj0 & 3) * 2 + (jj0 >> 2);
            int p1 = ((jj0 + 1) & 3) * 2 + ((jj0 + 1) >> 2);
            insp[e * INSP_STRIDE + c0 * 8 + p0] = cvt_tf32(ctx0);
            insp[e * INSP_STRIDE + c0 * 8 + p1] = cvt_tf32(ctx1);
            float2 sv = *(const float2*)&ss[e * SSST + d0];
            insp[e * INSP_STRIDE + (8 + c0) * 8 + p0] = cvt_tf32(sv.x);
            insp[e * INSP_STRIDE + (8 + c0) * 8 + p1] = cvt_tf32(sv.y);
        }
        __syncthreads();

        // ---- E+F fused: gate-interleaved mma + in-register cell ----
        {
            float dd[2][4];
            #pragma unroll
            for (int nt = 0; nt < 2; nt++)
                #pragma unroll
                for (int r = 0; r < 4; r++) dd[nt][r] = 0.0f;
            #pragma unroll
            for (int c = 0; c < 16; c++) {
                uint2 va = *(uint2*)&insp[g * INSP_STRIDE + c * 8 + 2 * tg];
                uint2 vb = *(uint2*)&insp[(g + 8) * INSP_STRIDE + c * 8 + 2 * tg];
                unsigned a[4] = {va.x, vb.x, va.y, vb.y};
                mma_tf32(dd[0], a, Bw[(0 * 16 + c) * 2], Bw[(0 * 16 + c) * 2 + 1]);
                mma_tf32(dd[1], a, Bw[(1 * 16 + c) * 2], Bw[(1 * 16 + c) * 2 + 1]);
            }
            float hh[2];
            #pragma unroll
            for (int nt = 0; nt < 2; nt++) {
                dd[nt][0] += bcol[nt][0]; dd[nt][1] += bcol[nt][1];
                dd[nt][2] += bcol[nt][0]; dd[nt][3] += bcol[nt][1];
                float ex0 = __shfl_xor_sync(FULL, dd[nt][0], 1);
                float ex1 = __shfl_xor_sync(FULL, dd[nt][1], 1);
                float ex2 = __shfl_xor_sync(FULL, dd[nt][2], 1);
                float ex3 = __shfl_xor_sync(FULL, dd[nt][3], 1);
                bool odd = (tg & 1);
                float zi = odd ? ex2        : dd[nt][0];
                float zf = odd ? ex3        : dd[nt][1];
                float zg = odd ? dd[nt][2]  : ex0;
                float zo = odd ? dd[nt][3]  : ex1;
                float c = sigapx(zf) * ccr[nt] + sigapx(zi) * tanhapx(zg);
                float h = sigapx(zo) * tanhapx(c);
                ccr[nt] = c;
                hh[nt] = h;
            }
            float r0 = __shfl_xor_sync(FULL, hh[0], 2);
            float r1 = __shfl_xor_sync(FULL, hh[1], 2);
            if (tg < 2) {
                int e = g + 8 * (tg & 1);
                *(float4*)&ss[e * SSST + warp * 4] = make_float4(hh[0], r0, hh[1], r1);
            }
        }
        __syncthreads();

        // ---- G: out partials via broadcast float4 ss reads (parity zsd) ----
        {
            #pragma unroll
            for (int ei = 0; ei < 8; ei++) {
                int e = eh * 8 + ei;
                const float4* sp = (const float4*)&ss[e * SSST + wkh * 16];
                float p = 0.0f;
                #pragma unroll
                for (int q = 0; q < 4; q++) {
                    float4 sv = sp[q];
                    p += sv.x * wreg[4 * q]     + sv.y * wreg[4 * q + 1]
                       + sv.z * wreg[4 * q + 2] + sv.w * wreg[4 * q + 3];
                }
                zb[(wkh * DBE + e) * 64 + wm] = p;
            }
        }
        __syncthreads();
        // out-reduce reads this parity's buffer; next step's G writes the
        // OTHER buffer, so no trailing barrier is needed.
        #pragma unroll
        for (int it = 0; it < 2; it++) {
            int i = tid + it * DEC_THREADS;
            int e = i >> 6, m = i & 63;
            float o = bos[m]
                    + zb[(0 * DBE + e) * 64 + m] + zb[(1 * DBE + e) * 64 + m]
                    + zb[(2 * DBE + e) * 64 + m] + zb[(3 * DBE + e) * 64 + m];
            out[((size_t)(b0 + e) * TY + t) * MV + m] = o;
        }
    }
}

// ============================================================================
extern "C" void kernel_launch(void* const* d_in, const int* in_sizes, int n_in,
                              void* d_out, int out_size)
{
    const float* X      = (const float*)d_in[0];
    const float* W_ih_f = (const float*)d_in[1];
    const float* W_hh_f = (const float*)d_in[2];
    const float* b_f    = (const float*)d_in[3];
    const float* W_ih_r = (const float*)d_in[4];
    const float* W_hh_r = (const float*)d_in[5];
    const float* b_r    = (const float*)d_in[6];
    const float* W1     = (const float*)d_in[7];
    const float* b1     = (const float*)d_in[8];
    const float* W2     = (const float*)d_in[9];
    const float* b2     = (const float*)d_in[10];
    const float* W_ih_p = (const float*)d_in[11];
    const float* W_hh_p = (const float*)d_in[12];
    const float* b_p    = (const float*)d_in[13];
    const float* Wo     = (const float*)d_in[14];
    const float* bo     = (const float*)d_in[15];
    float* out = (float*)d_out;

    cudaFuncSetAttribute(encoder_fused,  cudaFuncAttributeMaxDynamicSharedMemorySize, ENC_SMEM_BYTES);
    cudaFuncSetAttribute(decoder_kernel, cudaFuncAttributeMaxDynamicSharedMemorySize, DEC_SMEM_BYTES);

    encoder_fused<<<B_TOT / EBE, ENC_THREADS, ENC_SMEM_BYTES>>>(
        X, W_ih_f, W_hh_f, b_f, W_ih_r, W_hh_r, b_r);

    decoder_kernel<<<B_TOT / DBE, DEC_THREADS, DEC_SMEM_BYTES>>>(W1, b1, W2, b2,
                                                                 W_ih_p, W_hh_p, b_p, Wo, bo, out);
}

// round 12
// speedup vs baseline: 4.2981x; 1.1022x over previous
#include <cuda_runtime.h>
#include <cuda_bf16.h>
#include <math.h>

#define B_TOT 16384
#define TX 30
#define TY 10
#define NA 32
#define NS 64
#define HV 128
#define MV 64
#define GE 128   // 4*NA
#define GP 256   // 4*NS

__device__ __align__(16) float g_a[(size_t)B_TOT * TX * (2 * NA)];   // 126 MB

__device__ __forceinline__ float tanhapx(float x) {
    float y;
    asm("tanh.approx.f32 %0, %1;" : "=f"(y) : "f"(x));
    return y;
}
__device__ __forceinline__ float sigapx(float x) {
    return fmaf(tanhapx(0.5f * x), 0.5f, 0.5f);
}
__device__ __forceinline__ unsigned cvt_tf32(float x) {
    unsigned u;
    asm("cvt.rna.tf32.f32 %0, %1;" : "=r"(u) : "f"(x));
    return u;
}
__device__ __forceinline__ unsigned pack_bf16(float a, float b) {
    __nv_bfloat162 h = __floats2bfloat162_rn(a, b);
    return *(unsigned*)&h;
}
__device__ __forceinline__ void mma_tf32(float* d, const unsigned* a, unsigned b0, unsigned b1) {
    asm("mma.sync.aligned.m16n8k8.row.col.f32.tf32.tf32.f32 "
        "{%0,%1,%2,%3}, {%4,%5,%6,%7}, {%8,%9}, {%0,%1,%2,%3};"
        : "+f"(d[0]), "+f"(d[1]), "+f"(d[2]), "+f"(d[3])
        : "r"(a[0]), "r"(a[1]), "r"(a[2]), "r"(a[3]), "r"(b0), "r"(b1));
}
__device__ __forceinline__ void mma_bf16(float* d, unsigned a0, unsigned a1,
                                         unsigned a2, unsigned a3,
                                         unsigned b0, unsigned b1) {
    asm("mma.sync.aligned.m16n8k16.row.col.f32.bf16.bf16.f32 "
        "{%0,%1,%2,%3}, {%4,%5,%6,%7}, {%8,%9}, {%0,%1,%2,%3};"
        : "+f"(d[0]), "+f"(d[1]), "+f"(d[2]), "+f"(d[3])
        : "r"(a0), "r"(a1), "r"(a2), "r"(a3), "r"(b0), "r"(b1));
}

// ============================================================================
// Fused encoder: R11 structure + dir-local named barriers.
// Warps 0-7 = dir0, warps 8-15 = dir1; all shared state (xs/zs/cst/hbf) is
// dir-indexed disjoint, so each dir syncs only its own 256 threads
// (bar.sync 1+dir), letting the two recurrences slip independently.
// ============================================================================
#define EBE 64
#define ENC_THREADS 512
#define XST 68
#define HST 20
#define ZST 260
#define ENC_SMEM_BYTES ((2*2*64*XST + 2*64*HST) * 4 + (64*ZST + 2*64*32 + 256) * 4)

#define BARD(d) asm volatile("bar.sync %0, %1;" :: "r"(1 + (d)), "r"(256) : "memory")

__global__ __launch_bounds__(ENC_THREADS, 1)
void encoder_fused(const float* __restrict__ X,
                   const float* __restrict__ W_ih_f, const float* __restrict__ W_hh_f,
                   const float* __restrict__ b_f,
                   const float* __restrict__ W_ih_r, const float* __restrict__ W_hh_r,
                   const float* __restrict__ b_r)
{
    const int b0  = blockIdx.x * EBE;
    const int tid = threadIdx.x;
    const int warp = tid >> 5, lane = tid & 31;
    const int g = lane >> 2, tg = lane & 3;
    const int dir = warp >> 3;
    const int wl  = warp & 7;
    const int wtid = tid & 255;          // thread id within dir group

    extern __shared__ unsigned smu[];
    unsigned* xs  = smu;
    unsigned* hbf = xs + 2 * 2 * 64 * XST;
    float* zs  = (float*)(hbf + 2 * 64 * HST);
    float* cst = zs + 64 * ZST;
    float* bs  = cst + 2 * 64 * 32;

    const float* Wi = dir ? W_ih_r : W_ih_f;
    const float* Wh = dir ? W_hh_r : W_hh_f;

    unsigned Bx[2][8][2], Bh[2][2][2];
    #pragma unroll
    for (int nt = 0; nt < 2; nt++) {
        int n = wl * 16 + nt * 8 + g;
        #pragma unroll
        for (int c = 0; c < 8; c++) {
            Bx[nt][c][0] = pack_bf16(Wi[n * 128 + c * 16 + 2 * tg],
                                     Wi[n * 128 + c * 16 + 2 * tg + 1]);
            Bx[nt][c][1] = pack_bf16(Wi[n * 128 + c * 16 + 8 + 2 * tg],
                                     Wi[n * 128 + c * 16 + 8 + 2 * tg + 1]);
        }
        #pragma unroll
        for (int c = 0; c < 2; c++) {
            Bh[nt][c][0] = pack_bf16(Wh[n * 32 + c * 16 + 2 * tg],
                                     Wh[n * 32 + c * 16 + 2 * tg + 1]);
            Bh[nt][c][1] = pack_bf16(Wh[n * 32 + c * 16 + 8 + 2 * tg],
                                     Wh[n * 32 + c * 16 + 8 + 2 * tg + 1]);
        }
    }

    for (int i = tid; i < 256; i += ENC_THREADS) bs[i] = (i < 128) ? b_f[i] : b_r[i - 128];
    for (int i = tid; i < 2 * 64 * HST; i += ENC_THREADS) hbf[i] = 0u;
    for (int i = tid; i < 2 * 64 * 32; i += ENC_THREADS) cst[i] = 0.0f;

    #pragma unroll
    for (int ii = 0; ii < 8; ii++) {
        int flat = tid + ii * ENC_THREADS;
        int dd = flat >> 11, r = flat & 2047;
        int row = r >> 5, q = r & 31;
        int ts = dd ? (TX - 1) : 0;
        float4 v = *(const float4*)(X + ((size_t)(b0 + row) * TX + ts) * HV + q * 4);
        int c = q >> 2, jj0 = (q & 3) * 2;
        int p0 = (jj0 & 3) * 2 + (jj0 >> 2);
        int p1 = ((jj0 + 1) & 3) * 2 + ((jj0 + 1) >> 2);
        unsigned* dst = &xs[((0 * 2 + dd) * 64 + row) * XST + c * 8];
        dst[p0] = pack_bf16(v.x, v.y);
        dst[p1] = pack_bf16(v.z, v.w);
    }
    __syncthreads();

    int buf = 0;
    for (int t = 0; t < TX; t++) {
        // prefetch own dir's x(t+1)
        float4 xpre[8];
        const int tsn = dir ? max(TX - 2 - t, 0) : min(t + 1, TX - 1);
        #pragma unroll
        for (int ii = 0; ii < 8; ii++) {
            int flat = wtid + ii * 256;
            int row = flat >> 5, q = flat & 31;
            xpre[ii] = *(const float4*)(X + ((size_t)(b0 + row) * TX + tsn) * HV + q * 4);
        }

        float d[4][2][4];
        #pragma unroll
        for (int mi = 0; mi < 4; mi++)
            #pragma unroll
            for (int nt = 0; nt < 2; nt++)
                #pragma unroll
                for (int r = 0; r < 4; r++) d[mi][nt][r] = 0.0f;

        const unsigned* xbase = &xs[((buf * 2 + dir) * 64) * XST];
        #pragma unroll
        for (int c = 0; c < 8; c++) {
            unsigned a[4][4];
            #pragma unroll
            for (int mi = 0; mi < 4; mi++) {
                uint2 lo = *(uint2*)&xbase[(mi * 16 + g) * XST + c * 8 + 2 * tg];
                uint2 hi = *(uint2*)&xbase[(mi * 16 + 8 + g) * XST + c * 8 + 2 * tg];
                a[mi][0] = lo.x; a[mi][1] = hi.x; a[mi][2] = lo.y; a[mi][3] = hi.y;
            }
            #pragma unroll
            for (int mi = 0; mi < 4; mi++) {
                mma_bf16(d[mi][0], a[mi][0], a[mi][1], a[mi][2], a[mi][3],
                         Bx[0][c][0], Bx[0][c][1]);
                mma_bf16(d[mi][1], a[mi][0], a[mi][1], a[mi][2], a[mi][3],
                         Bx[1][c][0], Bx[1][c][1]);
            }
        }
        const unsigned* hbase = &hbf[(dir * 64) * HST];
        #pragma unroll
        for (int c = 0; c < 2; c++) {
            unsigned a[4][4];
            #pragma unroll
            for (int mi = 0; mi < 4; mi++) {
                uint2 lo = *(uint2*)&hbase[(mi * 16 + g) * HST + c * 8 + 2 * tg];
                uint2 hi = *(uint2*)&hbase[(mi * 16 + 8 + g) * HST + c * 8 + 2 * tg];
                a[mi][0] = lo.x; a[mi][1] = hi.x; a[mi][2] = lo.y; a[mi][3] = hi.y;
            }
            #pragma unroll
            for (int mi = 0; mi < 4; mi++) {
                mma_bf16(d[mi][0], a[mi][0], a[mi][1], a[mi][2], a[mi][3],
                         Bh[0][c][0], Bh[0][c][1]);
                mma_bf16(d[mi][1], a[mi][0], a[mi][1], a[mi][2], a[mi][3],
                         Bh[1][c][0], Bh[1][c][1]);
            }
        }

        #pragma unroll
        for (int mi = 0; mi < 4; mi++)
            #pragma unroll
            for (int nt = 0; nt < 2; nt++) {
                int col = dir * 128 + wl * 16 + nt * 8 + 2 * tg;
                *(float2*)&zs[(mi * 16 + g) * ZST + col] =
                    make_float2(d[mi][nt][0], d[mi][nt][1]);
                *(float2*)&zs[(mi * 16 + 8 + g) * ZST + col] =
                    make_float2(d[mi][nt][2], d[mi][nt][3]);
            }
        BARD(dir);

        // store prefetched x into other buffer (own dir)
        #pragma unroll
        for (int ii = 0; ii < 8; ii++) {
            int flat = wtid + ii * 256;
            int row = flat >> 5, q = flat & 31;
            int c = q >> 2, jj0 = (q & 3) * 2;
            int p0 = (jj0 & 3) * 2 + (jj0 >> 2);
            int p1 = ((jj0 + 1) & 3) * 2 + ((jj0 + 1) >> 2);
            unsigned* dst = &xs[(((buf ^ 1) * 2 + dir) * 64 + row) * XST + c * 8];
            dst[p0] = pack_bf16(xpre[ii].x, xpre[ii].y);
            dst[p1] = pack_bf16(xpre[ii].z, xpre[ii].w);
        }

        // LSTM cell for own dir: 64 elems x 16 npairs
        #pragma unroll
        for (int ii = 0; ii < 4; ii++) {
            int flat = wtid + ii * 256;
            int e = flat >> 4, np = flat & 15;
            int base = dir * 128 + 2 * np;
            float2 zi = *(float2*)&zs[e * ZST + base];
            float2 zf = *(float2*)&zs[e * ZST + base + 32];
            float2 zg = *(float2*)&zs[e * ZST + base + 64];
            float2 zo = *(float2*)&zs[e * ZST + base + 96];
            zi.x += bs[base];      zi.y += bs[base + 1];
            zf.x += bs[base + 32]; zf.y += bs[base + 33];
            zg.x += bs[base + 64]; zg.y += bs[base + 65];
            zo.x += bs[base + 96]; zo.y += bs[base + 97];
            float2 cold = *(float2*)&cst[dir * 2048 + e * 32 + 2 * np];
            float c0 = sigapx(zf.x) * cold.x + sigapx(zi.x) * tanhapx(zg.x);
            float c1 = sigapx(zf.y) * cold.y + sigapx(zi.y) * tanhapx(zg.y);
            float h0 = sigapx(zo.x) * tanhapx(c0);
            float h1 = sigapx(zo.y) * tanhapx(c1);
            *(float2*)&cst[dir * 2048 + e * 32 + 2 * np] = make_float2(c0, c1);
            hbf[(dir * 64 + e) * HST + (np >> 3) * 8 + ((np & 7) & 3) * 2 + ((np & 7) >> 2)]
                = pack_bf16(h0, h1);
            int tt = dir ? (TX - 1 - t) : t;
            *(float2*)(g_a + ((size_t)(b0 + e) * TX + tt) * 64 + dir * 32 + 2 * np)
                = make_float2(h0, h1);
        }
        BARD(dir);
        buf ^= 1;
    }
}

// ============================================================================
// Decoder v8: output projection via tf32 mma (warps 0-7), G/out-reduce gone.
// EF writes tf32 s-copy into parity-buffered sscopy (double-buffered because
// EF's cross-warp s-writes would race its own mma's s-reads single-buffered).
// 2 barriers/step: post-D (insp ctx), post-EF (ss + sscopy).
// ============================================================================
#define DBE 16
#define DEC_THREADS 512
#define SABST 34
#define EAST 11
#define W1ST 68
#define SSST 68
#define INSPST 72    // ctx-only rows; 72 mod 32 = 8 -> conflict-optimal uint2
#define SCST 72      // sscopy row stride

// layout in u32 units
#define OFF_SAB   0
#define SZ_SAB    (DBE * 32 * SABST)
#define OFF_EA    (OFF_SAB + SZ_SAB)
#define SZ_EA_AL  5284
#define OFF_W1A   (OFF_EA + SZ_EA_AL)
#define OFF_W1S   (OFF_W1A + 640)
#define OFF_B1S   (OFF_W1S + 680)
#define OFF_W2S   (OFF_B1S + 16)
#define OFF_SS    (OFF_W2S + 16)
#define OFF_INSP  (OFF_SS + DBE * SSST)
#define OFF_SC    (OFF_INSP + DBE * INSPST)
#define OFF_ALPH  (OFF_SC + 2 * DBE * SCST)
#define DEC_UNITS (OFF_ALPH + DBE * 32)
#define DEC_SMEM_BYTES (DEC_UNITS * 4)

__global__ __launch_bounds__(DEC_THREADS, 1)
void decoder_kernel(const float* __restrict__ W1, const float* __restrict__ b1,
                    const float* __restrict__ W2, const float* __restrict__ b2,
                    const float* __restrict__ W_ih_p, const float* __restrict__ W_hh_p,
                    const float* __restrict__ b_p,
                    const float* __restrict__ Wo, const float* __restrict__ bo,
                    float* __restrict__ out)
{
    const int b0 = blockIdx.x * DBE;
    const int tid = threadIdx.x;
    const unsigned FULL = 0xffffffffu;

    extern __shared__ unsigned smw[];
    unsigned* sab = smw + OFF_SAB;
    float* ea   = (float*)(smw + OFF_EA);
    float* W1a  = (float*)(smw + OFF_W1A);
    float* W1s  = (float*)(smw + OFF_W1S);
    float* b1s  = (float*)(smw + OFF_B1S);
    float* W2s  = (float*)(smw + OFF_W2S);
    float* ss   = (float*)(smw + OFF_SS);
    unsigned* insp = smw + OFF_INSP;
    unsigned* scb  = smw + OFF_SC;
    float* alph = (float*)(smw + OFF_ALPH);

    const int warp = tid >> 5, lane = tid & 31;
    const int g = lane >> 2, tg = lane & 3;

    // gate-interleaved Wcat B-fragments: column q = n*4 + gate
    unsigned Bw[64];
    #pragma unroll
    for (int nt = 0; nt < 2; nt++) {
        int q  = warp * 16 + nt * 8 + g;
        int rr = (q & 3) * 64 + (q >> 2);
        #pragma unroll
        for (int c = 0; c < 8; c++) {
            Bw[(nt * 16 + c) * 2 + 0] = cvt_tf32(W_ih_p[rr * 64 + c * 8 + tg]);
            Bw[(nt * 16 + c) * 2 + 1] = cvt_tf32(W_ih_p[rr * 64 + c * 8 + tg + 4]);
        }
        #pragma unroll
        for (int c = 0; c < 8; c++) {
            Bw[(nt * 16 + (8 + c)) * 2 + 0] = cvt_tf32(W_hh_p[rr * 64 + c * 8 + tg]);
            Bw[(nt * 16 + (8 + c)) * 2 + 1] = cvt_tf32(W_hh_p[rr * 64 + c * 8 + tg + 4]);
        }
    }
    float bcol[2][2];
    #pragma unroll
    for (int nt = 0; nt < 2; nt++) {
        int q0 = warp * 16 + nt * 8 + 2 * tg;
        bcol[nt][0] = b_p[(q0 & 3) * 64 + (q0 >> 2)];
        bcol[nt][1] = b_p[((q0 + 1) & 3) * 64 + ((q0 + 1) >> 2)];
    }
    float ccr[2] = {0.0f, 0.0f};

    // Wo B-fragments for the out-proj mma (used by warps 0-7; loaded by all)
    unsigned Bo[16];
    {
        int n = (warp & 7) * 8 + g;
        #pragma unroll
        for (int c = 0; c < 8; c++) {
            Bo[c * 2 + 0] = cvt_tf32(Wo[n * 64 + c * 8 + tg]);
            Bo[c * 2 + 1] = cvt_tf32(Wo[n * 64 + c * 8 + tg + 4]);
        }
    }
    const int m0 = (warp & 7) * 8 + 2 * tg;
    const float bo0 = bo[m0], bo1 = bo[m0 + 1];

    for (int i = tid; i < 640; i += DEC_THREADS) {
        int j = i / 64, d = i % 64;
        W1a[i]            = W1[j * 128 + d];
        W1s[j * W1ST + d] = W1[j * 128 + 64 + d];
    }
    if (tid < 10) { b1s[tid] = b1[tid]; W2s[tid] = W2[tid]; }
    for (int i = tid; i < DBE * SSST; i += DEC_THREADS) ss[i] = 0.0f;
    for (int i = tid; i < 2 * DBE * SCST; i += DEC_THREADS) scb[i] = 0u;
    const float b2v = b2[0];

    for (int i = tid; i < DBE * 2 * SABST; i += DEC_THREADS) {
        int e = i / (2 * SABST), r = i % (2 * SABST);
        sab[(e * 32 + 30) * SABST + r] = 0u;
    }
    for (int i = tid; i < DBE * TX * 16; i += DEC_THREADS) {
        int e = i / (TX * 16);
        int r = i % (TX * 16);
        int tx = r / 16, d4 = r % 16;
        float4 v = *(const float4*)(g_a + ((size_t)(b0 + e) * TX + tx) * (2 * NA) + d4 * 4);
        sab[(e * 32 + tx) * SABST + 2 * d4]     = pack_bf16(v.x, v.y);
        sab[(e * 32 + tx) * SABST + 2 * d4 + 1] = pack_bf16(v.z, v.w);
    }
    __syncthreads();

    if (tid < DBE * TX) {
        int e = tid / TX, tx = tid % TX;
        float acc[10];
        #pragma unroll
        for (int j = 0; j < 10; j++) acc[j] = 0.0f;
        #pragma unroll 4
        for (int d2 = 0; d2 < 32; d2++) {
            unsigned av = sab[(e * 32 + tx) * SABST + d2];
            float f0 = __uint_as_float(av << 16);
            float f1 = __uint_as_float(av & 0xffff0000u);
            #pragma unroll
            for (int j = 0; j < 10; j++)
                acc[j] += f0 * W1a[j * 64 + 2 * d2] + f1 * W1a[j * 64 + 2 * d2 + 1];
        }
        #pragma unroll
        for (int j = 0; j < 10; j++) ea[(e * TX + tx) * EAST + j] = acc[j];
    }
    __syncthreads();

    for (int t = 0; t < TY; t++) {
        const unsigned* scr = scb + (t & 1) * (DBE * SCST);        // s_t (mma read)
        unsigned* scw = scb + ((t + 1) & 1) * (DBE * SCST);        // s_{t+1} (EF write)

        // ---- A+B+C: warp e = attention for element e (warp-local) ----
        {
            const int e = warp;
            float accA = 0.0f;
            if (lane < 20) {
                int j = lane >> 1, half = lane & 1;
                const float4* sp = (const float4*)&ss[e * SSST + half * 32];
                const float4* wp = (const float4*)&W1s[j * W1ST + half * 32];
                #pragma unroll
                for (int q = 0; q < 8; q++) {
                    float4 sv = sp[q], wv = wp[q];
                    accA += sv.x * wv.x + sv.y * wv.y + sv.z * wv.z + sv.w * wv.w;
                }
            }
            accA += __shfl_xor_sync(FULL, accA, 1);
            if (lane < 20) accA += b1s[lane >> 1];

            int txc = (lane < TX) ? lane : 0;
            float acc = b2v;
            #pragma unroll
            for (int j = 0; j < 10; j++) {
                float esj = __shfl_sync(FULL, accA, 2 * j);
                acc += tanhapx(ea[(e * TX + txc) * EAST + j] + esj) * W2s[j];
            }
            float en = (lane < TX) ? fmaxf(acc, 0.0f) : -1e30f;

            float mx = en;
            #pragma unroll
            for (int o = 16; o; o >>= 1) mx = fmaxf(mx, __shfl_xor_sync(FULL, mx, o));
            float ex = (lane < TX) ? __expf(en - mx) : 0.0f;
            float sum = ex;
            #pragma unroll
            for (int o = 16; o; o >>= 1) sum += __shfl_xor_sync(FULL, sum, o);
            alph[e * 32 + lane] = ex * __fdividef(1.0f, sum);
        }
        __syncwarp();

        // ---- D: context pair-per-thread -> insp ctx (warp-local rows) ----
        {
            const int e = tid >> 5, d2 = tid & 31;
            const float4* ap = (const float4*)&alph[e * 32];
            float ctx0 = 0.0f, ctx1 = 0.0f;
            #pragma unroll
            for (int c = 0; c < 8; c++) {
                float4 a4 = ap[c];
                unsigned v0 = sab[(e * 32 + 4 * c + 0) * SABST + d2];
                unsigned v1 = sab[(e * 32 + 4 * c + 1) * SABST + d2];
                unsigned v2 = sab[(e * 32 + 4 * c + 2) * SABST + d2];
                unsigned v3 = sab[(e * 32 + 4 * c + 3) * SABST + d2];
                ctx0 += a4.x * __uint_as_float(v0 << 16)
                      + a4.y * __uint_as_float(v1 << 16)
                      + a4.z * __uint_as_float(v2 << 16)
                      + a4.w * __uint_as_float(v3 << 16);
                ctx1 += a4.x * __uint_as_float(v0 & 0xffff0000u)
                      + a4.y * __uint_as_float(v1 & 0xffff0000u)
                      + a4.z * __uint_as_float(v2 & 0xffff0000u)
                      + a4.w * __uint_as_float(v3 & 0xffff0000u);
            }
            int d0 = 2 * d2;
            int c0 = d0 >> 3, jj0 = d0 & 7;
            int p0 = (jj0 & 3) * 2 + (jj0 >> 2);
            int p1 = ((jj0 + 1) & 3) * 2 + ((jj0 + 1) >> 2);
            insp[e * INSPST + c0 * 8 + p0] = cvt_tf32(ctx0);
            insp[e * INSPST + c0 * 8 + p1] = cvt_tf32(ctx1);
        }
        __syncthreads();

        // ---- E+F fused: gate mma (ctx from insp, s from scr) + reg cell ----
        {
            float dd[2][4];
            #pragma unroll
            for (int nt = 0; nt < 2; nt++)
                #pragma unroll
                for (int r = 0; r < 4; r++) dd[nt][r] = 0.0f;
            #pragma unroll
            for (int c = 0; c < 8; c++) {   // ctx half
                uint2 va = *(uint2*)&insp[g * INSPST + c * 8 + 2 * tg];
                uint2 vb = *(uint2*)&insp[(g + 8) * INSPST + c * 8 + 2 * tg];
                unsigned a[4] = {va.x, vb.x, va.y, vb.y};
                mma_tf32(dd[0], a, Bw[(0 * 16 + c) * 2], Bw[(0 * 16 + c) * 2 + 1]);
                mma_tf32(dd[1], a, Bw[(1 * 16 + c) * 2], Bw[(1 * 16 + c) * 2 + 1]);
            }
            #pragma unroll
            for (int c = 0; c < 8; c++) {   // s half (parity read buffer)
                uint2 va = *(uint2*)&scr[g * SCST + c * 8 + 2 * tg];
                uint2 vb = *(uint2*)&scr[(g + 8) * SCST + c * 8 + 2 * tg];
                unsigned a[4] = {va.x, vb.x, va.y, vb.y};
                mma_tf32(dd[0], a, Bw[(0 * 16 + 8 + c) * 2], Bw[(0 * 16 + 8 + c) * 2 + 1]);
                mma_tf32(dd[1], a, Bw[(1 * 16 + 8 + c) * 2], Bw[(1 * 16 + 8 + c) * 2 + 1]);
            }
            float hh[2];
            #pragma unroll
            for (int nt = 0; nt < 2; nt++) {
                dd[nt][0] += bcol[nt][0]; dd[nt][1] += bcol[nt][1];
                dd[nt][2] += bcol[nt][0]; dd[nt][3] += bcol[nt][1];
                float ex0 = __shfl_xor_sync(FULL, dd[nt][0], 1);
                float ex1 = __shfl_xor_sync(FULL, dd[nt][1], 1);
                float ex2 = __shfl_xor_sync(FULL, dd[nt][2], 1);
                float ex3 = __shfl_xor_sync(FULL, dd[nt][3], 1);
                bool odd = (tg & 1);
                float zi = odd ? ex2        : dd[nt][0];
                float zf = odd ? ex3        : dd[nt][1];
                float zg = odd ? dd[nt][2]  : ex0;
                float zo = odd ? dd[nt][3]  : ex1;
                float c = sigapx(zf) * ccr[nt] + sigapx(zi) * tanhapx(zg);
                float h = sigapx(zo) * tanhapx(c);
                ccr[nt] = c;
                hh[nt] = h;
            }
            float r0 = __shfl_xor_sync(FULL, hh[0], 2);
            float r1 = __shfl_xor_sync(FULL, hh[1], 2);
            if (tg < 2) {
                int e = g + 8 * (tg & 1);
                // fp32 ss for phase A
                *(float4*)&ss[e * SSST + warp * 4] = make_float4(hh[0], r0, hh[1], r1);
                // tf32 permuted s-copy for gate mma (next step) + out mma
                unsigned* sc = &scw[e * SCST + (warp >> 1) * 8 + (warp & 1)];
                sc[0] = cvt_tf32(hh[0]);
                sc[2] = cvt_tf32(r0);
                sc[4] = cvt_tf32(hh[1]);
                sc[6] = cvt_tf32(r1);
            }
        }
        __syncthreads();

        // ---- OUT: warps 0-7 compute out[16,64] = s_{t+1} @ Wo^T + bo ----
        if (warp < 8) {
            float dd[4] = {0.0f, 0.0f, 0.0f, 0.0f};
            #pragma unroll
            for (int c = 0; c < 8; c++) {
                uint2 va = *(uint2*)&scw[g * SCST + c * 8 + 2 * tg];
                uint2 vb = *(uint2*)&scw[(g + 8) * SCST + c * 8 + 2 * tg];
                unsigned a[4] = {va.x, vb.x, va.y, vb.y};
                mma_tf32(dd, a, Bo[c * 2], Bo[c * 2 + 1]);
            }
            *(float2*)(out + ((size_t)(b0 + g) * TY + t) * MV + m0)
                = make_float2(dd[0] + bo0, dd[1] + bo1);
            *(float2*)(out + ((size_t)(b0 + g + 8) * TY + t) * MV + m0)
                = make_float2(dd[2] + bo0, dd[3] + bo1);
        }
        // no trailing barrier: next D writes insp ctx (disjoint from scw/ss
        // reads here); next EF waits on the post-D barrier which orders it
        // after this OUT.
    }
}

// ============================================================================
extern "C" void kernel_launch(void* const* d_in, const int* in_sizes, int n_in,
                              void* d_out, int out_size)
{
    const float* X      = (const float*)d_in[0];
    const float* W_ih_f = (const float*)d_in[1];
    const float* W_hh_f = (const float*)d_in[2];
    const float* b_f    = (const float*)d_in[3];
    const float* W_ih_r = (const float*)d_in[4];
    const float* W_hh_r = (const float*)d_in[5];
    const float* b_r    = (const float*)d_in[6];
    const float* W1     = (const float*)d_in[7];
    const float* b1     = (const float*)d_in[8];
    const float* W2     = (const float*)d_in[9];
    const float* b2     = (const float*)d_in[10];
    const float* W_ih_p = (const float*)d_in[11];
    const float* W_hh_p = (const float*)d_in[12];
    const float* b_p    = (const float*)d_in[13];
    const float* Wo     = (const float*)d_in[14];
    const float* bo     = (const float*)d_in[15];
    float* out = (float*)d_out;

    cudaFuncSetAttribute(encoder_fused,  cudaFuncAttributeMaxDynamicSharedMemorySize, ENC_SMEM_BYTES);
    cudaFuncSetAttribute(decoder_kernel, cudaFuncAttributeMaxDynamicSharedMemorySize, DEC_SMEM_BYTES);

    encoder_fused<<<B_TOT / EBE, ENC_THREADS, ENC_SMEM_BYTES>>>(
        X, W_ih_f, W_hh_f, b_f, W_ih_r, W_hh_r, b_r);

    decoder_kernel<<<B_TOT / DBE, DEC_THREADS, DEC_SMEM_BYTES>>>(W1, b1, W2, b2,
                                                                 W_ih_p, W_hh_p, b_p, Wo, bo, out);
}

// round 13
// speedup vs baseline: 4.3313x; 1.0077x over previous
#include <cuda_runtime.h>
#include <cuda_bf16.h>
#include <math.h>

#define B_TOT 16384
#define TX 30
#define TY 10
#define NA 32
#define NS 64
#define HV 128
#define MV 64
#define GE 128   // 4*NA
#define GP 256   // 4*NS

__device__ __align__(16) float g_a[(size_t)B_TOT * TX * (2 * NA)];   // 126 MB

__device__ __forceinline__ float tanhapx(float x) {
    float y;
    asm("tanh.approx.f32 %0, %1;" : "=f"(y) : "f"(x));
    return y;
}
__device__ __forceinline__ float sigapx(float x) {
    return fmaf(tanhapx(0.5f * x), 0.5f, 0.5f);
}
__device__ __forceinline__ unsigned cvt_tf32(float x) {
    unsigned u;
    asm("cvt.rna.tf32.f32 %0, %1;" : "=r"(u) : "f"(x));
    return u;
}
__device__ __forceinline__ unsigned pack_bf16(float a, float b) {
    __nv_bfloat162 h = __floats2bfloat162_rn(a, b);
    return *(unsigned*)&h;
}
__device__ __forceinline__ void mma_tf32(float* d, const unsigned* a, unsigned b0, unsigned b1) {
    asm("mma.sync.aligned.m16n8k8.row.col.f32.tf32.tf32.f32 "
        "{%0,%1,%2,%3}, {%4,%5,%6,%7}, {%8,%9}, {%0,%1,%2,%3};"
        : "+f"(d[0]), "+f"(d[1]), "+f"(d[2]), "+f"(d[3])
        : "r"(a[0]), "r"(a[1]), "r"(a[2]), "r"(a[3]), "r"(b0), "r"(b1));
}
__device__ __forceinline__ void mma_bf16(float* d, unsigned a0, unsigned a1,
                                         unsigned a2, unsigned a3,
                                         unsigned b0, unsigned b1) {
    asm("mma.sync.aligned.m16n8k16.row.col.f32.bf16.bf16.f32 "
        "{%0,%1,%2,%3}, {%4,%5,%6,%7}, {%8,%9}, {%0,%1,%2,%3};"
        : "+f"(d[0]), "+f"(d[1]), "+f"(d[2]), "+f"(d[3])
        : "r"(a0), "r"(a1), "r"(a2), "r"(a3), "r"(b0), "r"(b1));
}

// ============================================================================
// Encoder v3: gate-interleaved weight columns (q = n*4 + gate) + in-register
// LSTM cell (c state in regs, biases in regs). The z smem exchange and cst
// buffer are gone; only hbf (bf16 h fragments, parity double-buffered)
// remains. ONE dir-local barrier per step.
// ============================================================================
#define EBE 64
#define ENC_THREADS 512
#define XST 68
#define HST 20
#define ENC_SMEM_BYTES ((2*2*64*XST + 2*2*64*HST) * 4)

#define BARD(d) asm volatile("bar.sync %0, %1;" :: "r"(1 + (d)), "r"(256) : "memory")

__global__ __launch_bounds__(ENC_THREADS, 1)
void encoder_fused(const float* __restrict__ X,
                   const float* __restrict__ W_ih_f, const float* __restrict__ W_hh_f,
                   const float* __restrict__ b_f,
                   const float* __restrict__ W_ih_r, const float* __restrict__ W_hh_r,
                   const float* __restrict__ b_r)
{
    const int b0  = blockIdx.x * EBE;
    const int tid = threadIdx.x;
    const int warp = tid >> 5, lane = tid & 31;
    const int g = lane >> 2, tg = lane & 3;
    const int dir = warp >> 3;
    const int wl  = warp & 7;
    const int wtid = tid & 255;

    extern __shared__ unsigned smu[];
    unsigned* xs  = smu;                          // [buf][dir][64][XST]
    unsigned* hbf = xs + 2 * 2 * 64 * XST;        // [par][dir][64][HST]

    const float* Wi = dir ? W_ih_r : W_ih_f;
    const float* Wh = dir ? W_hh_r : W_hh_f;
    const float* bb = dir ? b_r    : b_f;

    // gate-interleaved B fragments: warp col q = wl*16 + nt*8 + g,
    // original weight row rr = (q&3)*NA + (q>>2)
    unsigned Bx[2][8][2], Bh[2][2][2];
    #pragma unroll
    for (int nt = 0; nt < 2; nt++) {
        int q  = wl * 16 + nt * 8 + g;
        int rr = (q & 3) * NA + (q >> 2);
        #pragma unroll
        for (int c = 0; c < 8; c++) {
            Bx[nt][c][0] = pack_bf16(Wi[rr * 128 + c * 16 + 2 * tg],
                                     Wi[rr * 128 + c * 16 + 2 * tg + 1]);
            Bx[nt][c][1] = pack_bf16(Wi[rr * 128 + c * 16 + 8 + 2 * tg],
                                     Wi[rr * 128 + c * 16 + 8 + 2 * tg + 1]);
        }
        #pragma unroll
        for (int c = 0; c < 2; c++) {
            Bh[nt][c][0] = pack_bf16(Wh[rr * 32 + c * 16 + 2 * tg],
                                     Wh[rr * 32 + c * 16 + 2 * tg + 1]);
            Bh[nt][c][1] = pack_bf16(Wh[rr * 32 + c * 16 + 8 + 2 * tg],
                                     Wh[rr * 32 + c * 16 + 8 + 2 * tg + 1]);
        }
    }
    // per-lane column biases: cols q0 = wl*16+nt*8+2tg, q0+1
    float bcol[2][2];
    #pragma unroll
    for (int nt = 0; nt < 2; nt++) {
        int q0 = wl * 16 + nt * 8 + 2 * tg;
        bcol[nt][0] = bb[(q0 & 3) * NA + (q0 >> 2)];
        bcol[nt][1] = bb[((q0 + 1) & 3) * NA + ((q0 + 1) >> 2)];
    }
    float ccr[8];
    #pragma unroll
    for (int i = 0; i < 8; i++) ccr[i] = 0.0f;

    // init hbf (both parities) to zero; load initial x tiles (both dirs)
    for (int i = tid; i < 2 * 2 * 64 * HST; i += ENC_THREADS) hbf[i] = 0u;
    #pragma unroll
    for (int ii = 0; ii < 8; ii++) {
        int flat = tid + ii * ENC_THREADS;
        int dd = flat >> 11, r = flat & 2047;
        int row = r >> 5, q = r & 31;
        int ts = dd ? (TX - 1) : 0;
        float4 v = *(const float4*)(X + ((size_t)(b0 + row) * TX + ts) * HV + q * 4);
        int c = q >> 2, jj0 = (q & 3) * 2;
        int p0 = (jj0 & 3) * 2 + (jj0 >> 2);
        int p1 = ((jj0 + 1) & 3) * 2 + ((jj0 + 1) >> 2);
        unsigned* dst = &xs[((0 * 2 + dd) * 64 + row) * XST + c * 8];
        dst[p0] = pack_bf16(v.x, v.y);
        dst[p1] = pack_bf16(v.z, v.w);
    }
    __syncthreads();

    // hbf n-pair placement for this warp (n0 = wl*4)
    const int hc  = wl >> 2;
    const int hjj = (wl & 3) * 2;
    const int hp0 = (hjj & 3) * 2 + (hjj >> 2);
    const int hp1 = ((hjj + 1) & 3) * 2 + ((hjj + 1) >> 2);

    int buf = 0;
    for (int t = 0; t < TX; t++) {
        const int par = t & 1;
        const int tt  = dir ? (TX - 1 - t) : t;

        // prefetch own dir's x(t+1)
        float4 xpre[8];
        const int tsn = dir ? max(TX - 2 - t, 0) : min(t + 1, TX - 1);
        #pragma unroll
        for (int ii = 0; ii < 8; ii++) {
            int flat = wtid + ii * 256;
            int row = flat >> 5, q = flat & 31;
            xpre[ii] = *(const float4*)(X + ((size_t)(b0 + row) * TX + tsn) * HV + q * 4);
        }

        // process rows in two halves (keeps accumulator live-set small)
        #pragma unroll
        for (int half = 0; half < 2; half++) {
            float d[2][2][4];
            #pragma unroll
            for (int mi = 0; mi < 2; mi++)
                #pragma unroll
                for (int nt = 0; nt < 2; nt++)
                    #pragma unroll
                    for (int r = 0; r < 4; r++) d[mi][nt][r] = 0.0f;

            const unsigned* xbase = &xs[((buf * 2 + dir) * 64 + half * 32) * XST];
            #pragma unroll
            for (int c = 0; c < 8; c++) {
                unsigned a[2][4];
                #pragma unroll
                for (int mi = 0; mi < 2; mi++) {
                    uint2 lo = *(uint2*)&xbase[(mi * 16 + g) * XST + c * 8 + 2 * tg];
                    uint2 hi = *(uint2*)&xbase[(mi * 16 + 8 + g) * XST + c * 8 + 2 * tg];
                    a[mi][0] = lo.x; a[mi][1] = hi.x; a[mi][2] = lo.y; a[mi][3] = hi.y;
                }
                #pragma unroll
                for (int mi = 0; mi < 2; mi++) {
                    mma_bf16(d[mi][0], a[mi][0], a[mi][1], a[mi][2], a[mi][3],
                             Bx[0][c][0], Bx[0][c][1]);
                    mma_bf16(d[mi][1], a[mi][0], a[mi][1], a[mi][2], a[mi][3],
                             Bx[1][c][0], Bx[1][c][1]);
                }
            }
            const unsigned* hbase = &hbf[((par * 2 + dir) * 64 + half * 32) * HST];
            #pragma unroll
            for (int c = 0; c < 2; c++) {
                unsigned a[2][4];
                #pragma unroll
                for (int mi = 0; mi < 2; mi++) {
                    uint2 lo = *(uint2*)&hbase[(mi * 16 + g) * HST + c * 8 + 2 * tg];
                    uint2 hi = *(uint2*)&hbase[(mi * 16 + 8 + g) * HST + c * 8 + 2 * tg];
                    a[mi][0] = lo.x; a[mi][1] = hi.x; a[mi][2] = lo.y; a[mi][3] = hi.y;
                }
                #pragma unroll
                for (int mi = 0; mi < 2; mi++) {
                    mma_bf16(d[mi][0], a[mi][0], a[mi][1], a[mi][2], a[mi][3],
                             Bh[0][c][0], Bh[0][c][1]);
                    mma_bf16(d[mi][1], a[mi][0], a[mi][1], a[mi][2], a[mi][3],
                             Bh[1][c][0], Bh[1][c][1]);
                }
            }

            // in-register cell: 4 cells per lane this half
            #pragma unroll
            for (int mi = 0; mi < 2; mi++) {
                float hh[2];
                #pragma unroll
                for (int nt = 0; nt < 2; nt++) {
                    d[mi][nt][0] += bcol[nt][0]; d[mi][nt][1] += bcol[nt][1];
                    d[mi][nt][2] += bcol[nt][0]; d[mi][nt][3] += bcol[nt][1];
                    float ex0 = __shfl_xor_sync(0xffffffffu, d[mi][nt][0], 1);
                    float ex1 = __shfl_xor_sync(0xffffffffu, d[mi][nt][1], 1);
                    float ex2 = __shfl_xor_sync(0xffffffffu, d[mi][nt][2], 1);
                    float ex3 = __shfl_xor_sync(0xffffffffu, d[mi][nt][3], 1);
                    bool odd = (tg & 1);
                    float zi = odd ? ex2       : d[mi][nt][0];
                    float zf = odd ? ex3       : d[mi][nt][1];
                    float zg = odd ? d[mi][nt][2] : ex0;
                    float zo = odd ? d[mi][nt][3] : ex1;
                    int ci = half * 4 + mi * 2 + nt;
                    float c = sigapx(zf) * ccr[ci] + sigapx(zi) * tanhapx(zg);
                    float h = sigapx(zo) * tanhapx(c);
                    ccr[ci] = c;
                    hh[nt] = h;
                }
                // gather 4 n per row, write g_a (float4) + hbf (2 bf16 pairs)
                float r0 = __shfl_xor_sync(0xffffffffu, hh[0], 2);
                float r1 = __shfl_xor_sync(0xffffffffu, hh[1], 2);
                if (tg < 2) {
                    int row = half * 32 + mi * 16 + g + 8 * (tg & 1);
                    *(float4*)(g_a + ((size_t)(b0 + row) * TX + tt) * 64 + dir * 32 + wl * 4)
                        = make_float4(hh[0], r0, hh[1], r1);
                    unsigned* hd = &hbf[(((par ^ 1) * 2 + dir) * 64 + row) * HST + hc * 8];
                    hd[hp0] = pack_bf16(hh[0], r0);
                    hd[hp1] = pack_bf16(hh[1], r1);
                }
            }
        }

        // store prefetched x into other buffer (own dir)
        #pragma unroll
        for (int ii = 0; ii < 8; ii++) {
            int flat = wtid + ii * 256;
            int row = flat >> 5, q = flat & 31;
            int c = q >> 2, jj0 = (q & 3) * 2;
            int p0 = (jj0 & 3) * 2 + (jj0 >> 2);
            int p1 = ((jj0 + 1) & 3) * 2 + ((jj0 + 1) >> 2);
            unsigned* dst = &xs[(((buf ^ 1) * 2 + dir) * 64 + row) * XST + c * 8];
            dst[p0] = pack_bf16(xpre[ii].x, xpre[ii].y);
            dst[p1] = pack_bf16(xpre[ii].z, xpre[ii].w);
        }

        BARD(dir);
        buf ^= 1;
    }
}

// ============================================================================
// Decoder v8 (byte-identical to R12)
// ============================================================================
#define DBE 16
#define DEC_THREADS 512
#define SABST 34
#define EAST 11
#define W1ST 68
#define SSST 68
#define INSPST 72
#define SCST 72

#define OFF_SAB   0
#define SZ_SAB    (DBE * 32 * SABST)
#define OFF_EA    (OFF_SAB + SZ_SAB)
#define SZ_EA_AL  5284
#define OFF_W1A   (OFF_EA + SZ_EA_AL)
#define OFF_W1S   (OFF_W1A + 640)
#define OFF_B1S   (OFF_W1S + 680)
#define OFF_W2S   (OFF_B1S + 16)
#define OFF_SS    (OFF_W2S + 16)
#define OFF_INSP  (OFF_SS + DBE * SSST)
#define OFF_SC    (OFF_INSP + DBE * INSPST)
#define OFF_ALPH  (OFF_SC + 2 * DBE * SCST)
#define DEC_UNITS (OFF_ALPH + DBE * 32)
#define DEC_SMEM_BYTES (DEC_UNITS * 4)

__global__ __launch_bounds__(DEC_THREADS, 1)
void decoder_kernel(const float* __restrict__ W1, const float* __restrict__ b1,
                    const float* __restrict__ W2, const float* __restrict__ b2,
                    const float* __restrict__ W_ih_p, const float* __restrict__ W_hh_p,
                    const float* __restrict__ b_p,
                    const float* __restrict__ Wo, const float* __restrict__ bo,
                    float* __restrict__ out)
{
    const int b0 = blockIdx.x * DBE;
    const int tid = threadIdx.x;
    const unsigned FULL = 0xffffffffu;

    extern __shared__ unsigned smw[];
    unsigned* sab = smw + OFF_SAB;
    float* ea   = (float*)(smw + OFF_EA);
    float* W1a  = (float*)(smw + OFF_W1A);
    float* W1s  = (float*)(smw + OFF_W1S);
    float* b1s  = (float*)(smw + OFF_B1S);
    float* W2s  = (float*)(smw + OFF_W2S);
    float* ss   = (float*)(smw + OFF_SS);
    unsigned* insp = smw + OFF_INSP;
    unsigned* scb  = smw + OFF_SC;
    float* alph = (float*)(smw + OFF_ALPH);

    const int warp = tid >> 5, lane = tid & 31;
    const int g = lane >> 2, tg = lane & 3;

    unsigned Bw[64];
    #pragma unroll
    for (int nt = 0; nt < 2; nt++) {
        int q  = warp * 16 + nt * 8 + g;
        int rr = (q & 3) * 64 + (q >> 2);
        #pragma unroll
        for (int c = 0; c < 8; c++) {
            Bw[(nt * 16 + c) * 2 + 0] = cvt_tf32(W_ih_p[rr * 64 + c * 8 + tg]);
            Bw[(nt * 16 + c) * 2 + 1] = cvt_tf32(W_ih_p[rr * 64 + c * 8 + tg + 4]);
        }
        #pragma unroll
        for (int c = 0; c < 8; c++) {
            Bw[(nt * 16 + (8 + c)) * 2 + 0] = cvt_tf32(W_hh_p[rr * 64 + c * 8 + tg]);
            Bw[(nt * 16 + (8 + c)) * 2 + 1] = cvt_tf32(W_hh_p[rr * 64 + c * 8 + tg + 4]);
        }
    }
    float bcol[2][2];
    #pragma unroll
    for (int nt = 0; nt < 2; nt++) {
        int q0 = warp * 16 + nt * 8 + 2 * tg;
        bcol[nt][0] = b_p[(q0 & 3) * 64 + (q0 >> 2)];
        bcol[nt][1] = b_p[((q0 + 1) & 3) * 64 + ((q0 + 1) >> 2)];
    }
    float ccr[2] = {0.0f, 0.0f};

    unsigned Bo[16];
    {
        int n = (warp & 7) * 8 + g;
        #pragma unroll
        for (int c = 0; c < 8; c++) {
            Bo[c * 2 + 0] = cvt_tf32(Wo[n * 64 + c * 8 + tg]);
            Bo[c * 2 + 1] = cvt_tf32(Wo[n * 64 + c * 8 + tg + 4]);
        }
    }
    const int m0 = (warp & 7) * 8 + 2 * tg;
    const float bo0 = bo[m0], bo1 = bo[m0 + 1];

    for (int i = tid; i < 640; i += DEC_THREADS) {
        int j = i / 64, d = i % 64;
        W1a[i]            = W1[j * 128 + d];
        W1s[j * W1ST + d] = W1[j * 128 + 64 + d];
    }
    if (tid < 10) { b1s[tid] = b1[tid]; W2s[tid] = W2[tid]; }
    for (int i = tid; i < DBE * SSST; i += DEC_THREADS) ss[i] = 0.0f;
    for (int i = tid; i < 2 * DBE * SCST; i += DEC_THREADS) scb[i] = 0u;
    const float b2v = b2[0];

    for (int i = tid; i < DBE * 2 * SABST; i += DEC_THREADS) {
        int e = i / (2 * SABST), r = i % (2 * SABST);
        sab[(e * 32 + 30) * SABST + r] = 0u;
    }
    for (int i = tid; i < DBE * TX * 16; i += DEC_THREADS) {
        int e = i / (TX * 16);
        int r = i % (TX * 16);
        int tx = r / 16, d4 = r % 16;
        float4 v = *(const float4*)(g_a + ((size_t)(b0 + e) * TX + tx) * (2 * NA) + d4 * 4);
        sab[(e * 32 + tx) * SABST + 2 * d4]     = pack_bf16(v.x, v.y);
        sab[(e * 32 + tx) * SABST + 2 * d4 + 1] = pack_bf16(v.z, v.w);
    }
    __syncthreads();

    if (tid < DBE * TX) {
        int e = tid / TX, tx = tid % TX;
        float acc[10];
        #pragma unroll
        for (int j = 0; j < 10; j++) acc[j] = 0.0f;
        #pragma unroll 4
        for (int d2 = 0; d2 < 32; d2++) {
            unsigned av = sab[(e * 32 + tx) * SABST + d2];
            float f0 = __uint_as_float(av << 16);
            float f1 = __uint_as_float(av & 0xffff0000u);
            #pragma unroll
            for (int j = 0; j < 10; j++)
                acc[j] += f0 * W1a[j * 64 + 2 * d2] + f1 * W1a[j * 64 + 2 * d2 + 1];
        }
        #pragma unroll
        for (int j = 0; j < 10; j++) ea[(e * TX + tx) * EAST + j] = acc[j];
    }
    __syncthreads();

    for (int t = 0; t < TY; t++) {
        const unsigned* scr = scb + (t & 1) * (DBE * SCST);
        unsigned* scw = scb + ((t + 1) & 1) * (DBE * SCST);

        {
            const int e = warp;
            float accA = 0.0f;
            if (lane < 20) {
                int j = lane >> 1, half = lane & 1;
                const float4* sp = (const float4*)&ss[e * SSST + half * 32];
                const float4* wp = (const float4*)&W1s[j * W1ST + half * 32];
                #pragma unroll
                for (int q = 0; q < 8; q++) {
                    float4 sv = sp[q], wv = wp[q];
                    accA += sv.x * wv.x + sv.y * wv.y + sv.z * wv.z + sv.w * wv.w;
                }
            }
            accA += __shfl_xor_sync(FULL, accA, 1);
            if (lane < 20) accA += b1s[lane >> 1];

            int txc = (lane < TX) ? lane : 0;
            float acc = b2v;
            #pragma unroll
            for (int j = 0; j < 10; j++) {
                float esj = __shfl_sync(FULL, accA, 2 * j);
                acc += tanhapx(ea[(e * TX + txc) * EAST + j] + esj) * W2s[j];
            }
            float en = (lane < TX) ? fmaxf(acc, 0.0f) : -1e30f;

            float mx = en;
            #pragma unroll
            for (int o = 16; o; o >>= 1) mx = fmaxf(mx, __shfl_xor_sync(FULL, mx, o));
            float ex = (lane < TX) ? __expf(en - mx) : 0.0f;
            float sum = ex;
            #pragma unroll
            for (int o = 16; o; o >>= 1) sum += __shfl_xor_sync(FULL, sum, o);
            alph[e * 32 + lane] = ex * __fdividef(1.0f, sum);
        }
        __syncwarp();

        {
            const int e = tid >> 5, d2 = tid & 31;
            const float4* ap = (const float4*)&alph[e * 32];
            float ctx0 = 0.0f, ctx1 = 0.0f;
            #pragma unroll
            for (int c = 0; c < 8; c++) {
                float4 a4 = ap[c];
                unsigned v0 = sab[(e * 32 + 4 * c + 0) * SABST + d2];
                unsigned v1 = sab[(e * 32 + 4 * c + 1) * SABST + d2];
                unsigned v2 = sab[(e * 32 + 4 * c + 2) * SABST + d2];
                unsigned v3 = sab[(e * 32 + 4 * c + 3) * SABST + d2];
                ctx0 += a4.x * __uint_as_float(v0 << 16)
                      + a4.y * __uint_as_float(v1 << 16)
                      + a4.z * __uint_as_float(v2 << 16)
                      + a4.w * __uint_as_float(v3 << 16);
                ctx1 += a4.x * __uint_as_float(v0 & 0xffff0000u)
                      + a4.y * __uint_as_float(v1 & 0xffff0000u)
                      + a4.z * __uint_as_float(v2 & 0xffff0000u)
                      + a4.w * __uint_as_float(v3 & 0xffff0000u);
            }
            int d0 = 2 * d2;
            int c0 = d0 >> 3, jj0 = d0 & 7;
            int p0 = (jj0 & 3) * 2 + (jj0 >> 2);
            int p1 = ((jj0 + 1) & 3) * 2 + ((jj0 + 1) >> 2);
            insp[e * INSPST + c0 * 8 + p0] = cvt_tf32(ctx0);
            insp[e * INSPST + c0 * 8 + p1] = cvt_tf32(ctx1);
        }
        __syncthreads();

        {
            float dd[2][4];
            #pragma unroll
            for (int nt = 0; nt < 2; nt++)
                #pragma unroll
                for (int r = 0; r < 4; r++) dd[nt][r] = 0.0f;
            #pragma unroll
            for (int c = 0; c < 8; c++) {
                uint2 va = *(uint2*)&insp[g * INSPST + c * 8 + 2 * tg];
                uint2 vb = *(uint2*)&insp[(g + 8) * INSPST + c * 8 + 2 * tg];
                unsigned a[4] = {va.x, vb.x, va.y, vb.y};
                mma_tf32(dd[0], a, Bw[(0 * 16 + c) * 2], Bw[(0 * 16 + c) * 2 + 1]);
                mma_tf32(dd[1], a, Bw[(1 * 16 + c) * 2], Bw[(1 * 16 + c) * 2 + 1]);
            }
            #pragma unroll
            for (int c = 0; c < 8; c++) {
                uint2 va = *(uint2*)&scr[g * SCST + c * 8 + 2 * tg];
                uint2 vb = *(uint2*)&scr[(g + 8) * SCST + c * 8 + 2 * tg];
                unsigned a[4] = {va.x, vb.x, va.y, vb.y};
                mma_tf32(dd[0], a, Bw[(0 * 16 + 8 + c) * 2], Bw[(0 * 16 + 8 + c) * 2 + 1]);
                mma_tf32(dd[1], a, Bw[(1 * 16 + 8 + c) * 2], Bw[(1 * 16 + 8 + c) * 2 + 1]);
            }
            float hh[2];
            #pragma unroll
            for (int nt = 0; nt < 2; nt++) {
                dd[nt][0] += bcol[nt][0]; dd[nt][1] += bcol[nt][1];
                dd[nt][2] += bcol[nt][0]; dd[nt][3] += bcol[nt][1];
                float ex0 = __shfl_xor_sync(FULL, dd[nt][0], 1);
                float ex1 = __shfl_xor_sync(FULL, dd[nt][1], 1);
                float ex2 = __shfl_xor_sync(FULL, dd[nt][2], 1);
                float ex3 = __shfl_xor_sync(FULL, dd[nt][3], 1);
                bool odd = (tg & 1);
                float zi = odd ? ex2        : dd[nt][0];
                float zf = odd ? ex3        : dd[nt][1];
                float zg = odd ? dd[nt][2]  : ex0;
                float zo = odd ? dd[nt][3]  : ex1;
                float c = sigapx(zf) * ccr[nt] + sigapx(zi) * tanhapx(zg);
                float h = sigapx(zo) * tanhapx(c);
                ccr[nt] = c;
                hh[nt] = h;
            }
            float r0 = __shfl_xor_sync(FULL, hh[0], 2);
            float r1 = __shfl_xor_sync(FULL, hh[1], 2);
            if (tg < 2) {
                int e = g + 8 * (tg & 1);
                *(float4*)&ss[e * SSST + warp * 4] = make_float4(hh[0], r0, hh[1], r1);
                unsigned* sc = &scw[e * SCST + (warp >> 1) * 8 + (warp & 1)];
                sc[0] = cvt_tf32(hh[0]);
                sc[2] = cvt_tf32(r0);
                sc[4] = cvt_tf32(hh[1]);
                sc[6] = cvt_tf32(r1);
            }
        }
        __syncthreads();

        if (warp < 8) {
            float dd[4] = {0.0f, 0.0f, 0.0f, 0.0f};
            #pragma unroll
            for (int c = 0; c < 8; c++) {
                uint2 va = *(uint2*)&scw[g * SCST + c * 8 + 2 * tg];
                uint2 vb = *(uint2*)&scw[(g + 8) * SCST + c * 8 + 2 * tg];
                unsigned a[4] = {va.x, vb.x, va.y, vb.y};
                mma_tf32(dd, a, Bo[c * 2], Bo[c * 2 + 1]);
            }
            *(float2*)(out + ((size_t)(b0 + g) * TY + t) * MV + m0)
                = make_float2(dd[0] + bo0, dd[1] + bo1);
            *(float2*)(out + ((size_t)(b0 + g + 8) * TY + t) * MV + m0)
                = make_float2(dd[2] + bo0, dd[3] + bo1);
        }
    }
}

// ============================================================================
extern "C" void kernel_launch(void* const* d_in, const int* in_sizes, int n_in,
                              void* d_out, int out_size)
{
    const float* X      = (const float*)d_in[0];
    const float* W_ih_f = (const float*)d_in[1];
    const float* W_hh_f = (const float*)d_in[2];
    const float* b_f    = (const float*)d_in[3];
    const float* W_ih_r = (const float*)d_in[4];
    const float* W_hh_r = (const float*)d_in[5];
    const float* b_r    = (const float*)d_in[6];
    const float* W1     = (const float*)d_in[7];
    const float* b1     = (const float*)d_in[8];
    const float* W2     = (const float*)d_in[9];
    const float* b2     = (const float*)d_in[10];
    const float* W_ih_p = (const float*)d_in[11];
    const float* W_hh_p = (const float*)d_in[12];
    const float* b_p    = (const float*)d_in[13];
    const float* Wo     = (const float*)d_in[14];
    const float* bo     = (const float*)d_in[15];
    float* out = (float*)d_out;

    cudaFuncSetAttribute(encoder_fused,  cudaFuncAttributeMaxDynamicSharedMemorySize, ENC_SMEM_BYTES);
    cudaFuncSetAttribute(decoder_kernel, cudaFuncAttributeMaxDynamicSharedMemorySize, DEC_SMEM_BYTES);

    encoder_fused<<<B_TOT / EBE, ENC_THREADS, ENC_SMEM_BYTES>>>(
        X, W_ih_f, W_hh_f, b_f, W_ih_r, W_hh_r, b_r);

    decoder_kernel<<<B_TOT / DBE, DEC_THREADS, DEC_SMEM_BYTES>>>(W1, b1, W2, b2,
                                                                 W_ih_p, W_hh_p, b_p, Wo, bo, out);
}

// round 14
// speedup vs baseline: 4.6754x; 1.0794x over previous
#include <cuda_runtime.h>
#include <cuda_bf16.h>
#include <math.h>

#define B_TOT 16384
#define TX 30
#define TY 10
#define NA 32
#define NS 64
#define HV 128
#define MV 64
#define GE 128   // 4*NA
#define GP 256   // 4*NS

__device__ __align__(16) float g_a[(size_t)B_TOT * TX * (2 * NA)];   // 126 MB
__device__ int g_flag[256];

__device__ __forceinline__ float tanhapx(float x) {
    float y;
    asm("tanh.approx.f32 %0, %1;" : "=f"(y) : "f"(x));
    return y;
}
__device__ __forceinline__ float sigapx(float x) {
    return fmaf(tanhapx(0.5f * x), 0.5f, 0.5f);
}
__device__ __forceinline__ unsigned cvt_tf32(float x) {
    unsigned u;
    asm("cvt.rna.tf32.f32 %0, %1;" : "=r"(u) : "f"(x));
    return u;
}
__device__ __forceinline__ unsigned pack_bf16(float a, float b) {
    __nv_bfloat162 h = __floats2bfloat162_rn(a, b);
    return *(unsigned*)&h;
}
__device__ __forceinline__ void mma_tf32(float* d, const unsigned* a, unsigned b0, unsigned b1) {
    asm("mma.sync.aligned.m16n8k8.row.col.f32.tf32.tf32.f32 "
        "{%0,%1,%2,%3}, {%4,%5,%6,%7}, {%8,%9}, {%0,%1,%2,%3};"
        : "+f"(d[0]), "+f"(d[1]), "+f"(d[2]), "+f"(d[3])
        : "r"(a[0]), "r"(a[1]), "r"(a[2]), "r"(a[3]), "r"(b0), "r"(b1));
}
__device__ __forceinline__ void mma_bf16(float* d, unsigned a0, unsigned a1,
                                         unsigned a2, unsigned a3,
                                         unsigned b0, unsigned b1) {
    asm("mma.sync.aligned.m16n8k16.row.col.f32.bf16.bf16.f32 "
        "{%0,%1,%2,%3}, {%4,%5,%6,%7}, {%8,%9}, {%0,%1,%2,%3};"
        : "+f"(d[0]), "+f"(d[1]), "+f"(d[2]), "+f"(d[3])
        : "r"(a0), "r"(a1), "r"(a2), "r"(a3), "r"(b0), "r"(b1));
}

__global__ void clear_flags_kernel() { g_flag[threadIdx.x] = 0; }

// ============================================================================
// Encoder v3 (R13) + PDL trigger + completion flag per chunk.
// ============================================================================
#define EBE 64
#define ENC_THREADS 512
#define XST 68
#define HST 20
#define ENC_SMEM_BYTES ((2*2*64*XST + 2*2*64*HST) * 4)

#define BARD(d) asm volatile("bar.sync %0, %1;" :: "r"(1 + (d)), "r"(256) : "memory")

__global__ __launch_bounds__(ENC_THREADS, 1)
void encoder_fused(const float* __restrict__ X,
                   const float* __restrict__ W_ih_f, const float* __restrict__ W_hh_f,
                   const float* __restrict__ b_f,
                   const float* __restrict__ W_ih_r, const float* __restrict__ W_hh_r,
                   const float* __restrict__ b_r)
{
    cudaTriggerProgrammaticLaunchCompletion();

    const int b0  = blockIdx.x * EBE;
    const int tid = threadIdx.x;
    const int warp = tid >> 5, lane = tid & 31;
    const int g = lane >> 2, tg = lane & 3;
    const int dir = warp >> 3;
    const int wl  = warp & 7;
    const int wtid = tid & 255;

    extern __shared__ unsigned smu[];
    unsigned* xs  = smu;
    unsigned* hbf = xs + 2 * 2 * 64 * XST;

    const float* Wi = dir ? W_ih_r : W_ih_f;
    const float* Wh = dir ? W_hh_r : W_hh_f;
    const float* bb = dir ? b_r    : b_f;

    unsigned Bx[2][8][2], Bh[2][2][2];
    #pragma unroll
    for (int nt = 0; nt < 2; nt++) {
        int q  = wl * 16 + nt * 8 + g;
        int rr = (q & 3) * NA + (q >> 2);
        #pragma unroll
        for (int c = 0; c < 8; c++) {
            Bx[nt][c][0] = pack_bf16(Wi[rr * 128 + c * 16 + 2 * tg],
                                     Wi[rr * 128 + c * 16 + 2 * tg + 1]);
            Bx[nt][c][1] = pack_bf16(Wi[rr * 128 + c * 16 + 8 + 2 * tg],
                                     Wi[rr * 128 + c * 16 + 8 + 2 * tg + 1]);
        }
        #pragma unroll
        for (int c = 0; c < 2; c++) {
            Bh[nt][c][0] = pack_bf16(Wh[rr * 32 + c * 16 + 2 * tg],
                                     Wh[rr * 32 + c * 16 + 2 * tg + 1]);
            Bh[nt][c][1] = pack_bf16(Wh[rr * 32 + c * 16 + 8 + 2 * tg],
                                     Wh[rr * 32 + c * 16 + 8 + 2 * tg + 1]);
        }
    }
    float bcol[2][2];
    #pragma unroll
    for (int nt = 0; nt < 2; nt++) {
        int q0 = wl * 16 + nt * 8 + 2 * tg;
        bcol[nt][0] = bb[(q0 & 3) * NA + (q0 >> 2)];
        bcol[nt][1] = bb[((q0 + 1) & 3) * NA + ((q0 + 1) >> 2)];
    }
    float ccr[8];
    #pragma unroll
    for (int i = 0; i < 8; i++) ccr[i] = 0.0f;

    for (int i = tid; i < 2 * 2 * 64 * HST; i += ENC_THREADS) hbf[i] = 0u;
    #pragma unroll
    for (int ii = 0; ii < 8; ii++) {
        int flat = tid + ii * ENC_THREADS;
        int dd = flat >> 11, r = flat & 2047;
        int row = r >> 5, q = r & 31;
        int ts = dd ? (TX - 1) : 0;
        float4 v = *(const float4*)(X + ((size_t)(b0 + row) * TX + ts) * HV + q * 4);
        int c = q >> 2, jj0 = (q & 3) * 2;
        int p0 = (jj0 & 3) * 2 + (jj0 >> 2);
        int p1 = ((jj0 + 1) & 3) * 2 + ((jj0 + 1) >> 2);
        unsigned* dst = &xs[((0 * 2 + dd) * 64 + row) * XST + c * 8];
        dst[p0] = pack_bf16(v.x, v.y);
        dst[p1] = pack_bf16(v.z, v.w);
    }
    __syncthreads();

    const int hc  = wl >> 2;
    const int hjj = (wl & 3) * 2;
    const int hp0 = (hjj & 3) * 2 + (hjj >> 2);
    const int hp1 = ((hjj + 1) & 3) * 2 + ((hjj + 1) >> 2);

    int buf = 0;
    for (int t = 0; t < TX; t++) {
        const int par = t & 1;
        const int tt  = dir ? (TX - 1 - t) : t;

        float4 xpre[8];
        const int tsn = dir ? max(TX - 2 - t, 0) : min(t + 1, TX - 1);
        #pragma unroll
        for (int ii = 0; ii < 8; ii++) {
            int flat = wtid + ii * 256;
            int row = flat >> 5, q = flat & 31;
            xpre[ii] = *(const float4*)(X + ((size_t)(b0 + row) * TX + tsn) * HV + q * 4);
        }

        #pragma unroll
        for (int half = 0; half < 2; half++) {
            float d[2][2][4];
            #pragma unroll
            for (int mi = 0; mi < 2; mi++)
                #pragma unroll
                for (int nt = 0; nt < 2; nt++)
                    #pragma unroll
                    for (int r = 0; r < 4; r++) d[mi][nt][r] = 0.0f;

            const unsigned* xbase = &xs[((buf * 2 + dir) * 64 + half * 32) * XST];
            #pragma unroll
            for (int c = 0; c < 8; c++) {
                unsigned a[2][4];
                #pragma unroll
                for (int mi = 0; mi < 2; mi++) {
                    uint2 lo = *(uint2*)&xbase[(mi * 16 + g) * XST + c * 8 + 2 * tg];
                    uint2 hi = *(uint2*)&xbase[(mi * 16 + 8 + g) * XST + c * 8 + 2 * tg];
                    a[mi][0] = lo.x; a[mi][1] = hi.x; a[mi][2] = lo.y; a[mi][3] = hi.y;
                }
                #pragma unroll
                for (int mi = 0; mi < 2; mi++) {
                    mma_bf16(d[mi][0], a[mi][0], a[mi][1], a[mi][2], a[mi][3],
                             Bx[0][c][0], Bx[0][c][1]);
                    mma_bf16(d[mi][1], a[mi][0], a[mi][1], a[mi][2], a[mi][3],
                             Bx[1][c][0], Bx[1][c][1]);
                }
            }
            const unsigned* hbase = &hbf[((par * 2 + dir) * 64 + half * 32) * HST];
            #pragma unroll
            for (int c = 0; c < 2; c++) {
                unsigned a[2][4];
                #pragma unroll
                for (int mi = 0; mi < 2; mi++) {
                    uint2 lo = *(uint2*)&hbase[(mi * 16 + g) * HST + c * 8 + 2 * tg];
                    uint2 hi = *(uint2*)&hbase[(mi * 16 + 8 + g) * HST + c * 8 + 2 * tg];
                    a[mi][0] = lo.x; a[mi][1] = hi.x; a[mi][2] = lo.y; a[mi][3] = hi.y;
                }
                #pragma unroll
                for (int mi = 0; mi < 2; mi++) {
                    mma_bf16(d[mi][0], a[mi][0], a[mi][1], a[mi][2], a[mi][3],
                             Bh[0][c][0], Bh[0][c][1]);
                    mma_bf16(d[mi][1], a[mi][0], a[mi][1], a[mi][2], a[mi][3],
                             Bh[1][c][0], Bh[1][c][1]);
                }
            }

            #pragma unroll
            for (int mi = 0; mi < 2; mi++) {
                float hh[2];
                #pragma unroll
                for (int nt = 0; nt < 2; nt++) {
                    d[mi][nt][0] += bcol[nt][0]; d[mi][nt][1] += bcol[nt][1];
                    d[mi][nt][2] += bcol[nt][0]; d[mi][nt][3] += bcol[nt][1];
                    float ex0 = __shfl_xor_sync(0xffffffffu, d[mi][nt][0], 1);
                    float ex1 = __shfl_xor_sync(0xffffffffu, d[mi][nt][1], 1);
                    float ex2 = __shfl_xor_sync(0xffffffffu, d[mi][nt][2], 1);
                    float ex3 = __shfl_xor_sync(0xffffffffu, d[mi][nt][3], 1);
                    bool odd = (tg & 1);
                    float zi = odd ? ex2       : d[mi][nt][0];
                    float zf = odd ? ex3       : d[mi][nt][1];
                    float zg = odd ? d[mi][nt][2] : ex0;
                    float zo = odd ? d[mi][nt][3] : ex1;
                    int ci = half * 4 + mi * 2 + nt;
                    float c = sigapx(zf) * ccr[ci] + sigapx(zi) * tanhapx(zg);
                    float h = sigapx(zo) * tanhapx(c);
                    ccr[ci] = c;
                    hh[nt] = h;
                }
                float r0 = __shfl_xor_sync(0xffffffffu, hh[0], 2);
                float r1 = __shfl_xor_sync(0xffffffffu, hh[1], 2);
                if (tg < 2) {
                    int row = half * 32 + mi * 16 + g + 8 * (tg & 1);
                    *(float4*)(g_a + ((size_t)(b0 + row) * TX + tt) * 64 + dir * 32 + wl * 4)
                        = make_float4(hh[0], r0, hh[1], r1);
                    unsigned* hd = &hbf[(((par ^ 1) * 2 + dir) * 64 + row) * HST + hc * 8];
                    hd[hp0] = pack_bf16(hh[0], r0);
                    hd[hp1] = pack_bf16(hh[1], r1);
                }
            }
        }

        #pragma unroll
        for (int ii = 0; ii < 8; ii++) {
            int flat = wtid + ii * 256;
            int row = flat >> 5, q = flat & 31;
            int c = q >> 2, jj0 = (q & 3) * 2;
            int p0 = (jj0 & 3) * 2 + (jj0 >> 2);
            int p1 = ((jj0 + 1) & 3) * 2 + ((jj0 + 1) >> 2);
            unsigned* dst = &xs[(((buf ^ 1) * 2 + dir) * 64 + row) * XST + c * 8];
            dst[p0] = pack_bf16(xpre[ii].x, xpre[ii].y);
            dst[p1] = pack_bf16(xpre[ii].z, xpre[ii].w);
        }

        BARD(dir);
        buf ^= 1;
    }

    // chunk complete: publish flag (cumulative fence after block-wide sync)
    __syncthreads();
    if (tid == 0) {
        __threadfence();
        asm volatile("st.release.gpu.global.s32 [%0], %1;"
                     :: "l"(&g_flag[blockIdx.x]), "r"(1) : "memory");
    }
}

// ============================================================================
// Decoder v9: R13 + acquire-spin on encoder chunk flag + softmax max-skip
// (en = b2 + sum(tanh*W2) is bounded by ~2, so exp cannot overflow).
// ============================================================================
#define DBE 16
#define DEC_THREADS 512
#define SABST 34
#define EAST 11
#define W1ST 68
#define SSST 68
#define INSPST 72
#define SCST 72

#define OFF_SAB   0
#define SZ_SAB    (DBE * 32 * SABST)
#define OFF_EA    (OFF_SAB + SZ_SAB)
#define SZ_EA_AL  5284
#define OFF_W1A   (OFF_EA + SZ_EA_AL)
#define OFF_W1S   (OFF_W1A + 640)
#define OFF_B1S   (OFF_W1S + 680)
#define OFF_W2S   (OFF_B1S + 16)
#define OFF_SS    (OFF_W2S + 16)
#define OFF_INSP  (OFF_SS + DBE * SSST)
#define OFF_SC    (OFF_INSP + DBE * INSPST)
#define OFF_ALPH  (OFF_SC + 2 * DBE * SCST)
#define DEC_UNITS (OFF_ALPH + DBE * 32)
#define DEC_SMEM_BYTES (DEC_UNITS * 4)

__global__ __launch_bounds__(DEC_THREADS, 1)
void decoder_kernel(const float* __restrict__ W1, const float* __restrict__ b1,
                    const float* __restrict__ W2, const float* __restrict__ b2,
                    const float* __restrict__ W_ih_p, const float* __restrict__ W_hh_p,
                    const float* __restrict__ b_p,
                    const float* __restrict__ Wo, const float* __restrict__ bo,
                    float* __restrict__ out)
{
    const int b0 = blockIdx.x * DBE;
    const int tid = threadIdx.x;
    const unsigned FULL = 0xffffffffu;

    extern __shared__ unsigned smw[];
    unsigned* sab = smw + OFF_SAB;
    float* ea   = (float*)(smw + OFF_EA);
    float* W1a  = (float*)(smw + OFF_W1A);
    float* W1s  = (float*)(smw + OFF_W1S);
    float* b1s  = (float*)(smw + OFF_B1S);
    float* W2s  = (float*)(smw + OFF_W2S);
    float* ss   = (float*)(smw + OFF_SS);
    unsigned* insp = smw + OFF_INSP;
    unsigned* scb  = smw + OFF_SC;
    float* alph = (float*)(smw + OFF_ALPH);

    const int warp = tid >> 5, lane = tid & 31;
    const int g = lane >> 2, tg = lane & 3;

    unsigned Bw[64];
    #pragma unroll
    for (int nt = 0; nt < 2; nt++) {
        int q  = warp * 16 + nt * 8 + g;
        int rr = (q & 3) * 64 + (q >> 2);
        #pragma unroll
        for (int c = 0; c < 8; c++) {
            Bw[(nt * 16 + c) * 2 + 0] = cvt_tf32(W_ih_p[rr * 64 + c * 8 + tg]);
            Bw[(nt * 16 + c) * 2 + 1] = cvt_tf32(W_ih_p[rr * 64 + c * 8 + tg + 4]);
        }
        #pragma unroll
        for (int c = 0; c < 8; c++) {
            Bw[(nt * 16 + (8 + c)) * 2 + 0] = cvt_tf32(W_hh_p[rr * 64 + c * 8 + tg]);
            Bw[(nt * 16 + (8 + c)) * 2 + 1] = cvt_tf32(W_hh_p[rr * 64 + c * 8 + tg + 4]);
        }
    }
    float bcol[2][2];
    #pragma unroll
    for (int nt = 0; nt < 2; nt++) {
        int q0 = warp * 16 + nt * 8 + 2 * tg;
        bcol[nt][0] = b_p[(q0 & 3) * 64 + (q0 >> 2)];
        bcol[nt][1] = b_p[((q0 + 1) & 3) * 64 + ((q0 + 1) >> 2)];
    }
    float ccr[2] = {0.0f, 0.0f};

    unsigned Bo[16];
    {
        int n = (warp & 7) * 8 + g;
        #pragma unroll
        for (int c = 0; c < 8; c++) {
            Bo[c * 2 + 0] = cvt_tf32(Wo[n * 64 + c * 8 + tg]);
            Bo[c * 2 + 1] = cvt_tf32(Wo[n * 64 + c * 8 + tg + 4]);
        }
    }
    const int m0 = (warp & 7) * 8 + 2 * tg;
    const float bo0 = bo[m0], bo1 = bo[m0 + 1];

    for (int i = tid; i < 640; i += DEC_THREADS) {
        int j = i / 64, d = i % 64;
        W1a[i]            = W1[j * 128 + d];
        W1s[j * W1ST + d] = W1[j * 128 + 64 + d];
    }
    if (tid < 10) { b1s[tid] = b1[tid]; W2s[tid] = W2[tid]; }
    for (int i = tid; i < DBE * SSST; i += DEC_THREADS) ss[i] = 0.0f;
    for (int i = tid; i < 2 * DBE * SCST; i += DEC_THREADS) scb[i] = 0u;
    const float b2v = b2[0];

    for (int i = tid; i < DBE * 2 * SABST; i += DEC_THREADS) {
        int e = i / (2 * SABST), r = i % (2 * SABST);
        sab[(e * 32 + 30) * SABST + r] = 0u;
    }

    // wait for our encoder chunk (16 elems sit inside chunk blockIdx.x>>2)
    if (tid == 0) {
        int v;
        do {
            asm volatile("ld.acquire.gpu.global.s32 %0, [%1];"
                         : "=r"(v) : "l"(&g_flag[blockIdx.x >> 2]) : "memory");
            if (!v) __nanosleep(128);
        } while (!v);
    }
    __syncthreads();

    for (int i = tid; i < DBE * TX * 16; i += DEC_THREADS) {
        int e = i / (TX * 16);
        int r = i % (TX * 16);
        int tx = r / 16, d4 = r % 16;
        float4 v = *(const float4*)(g_a + ((size_t)(b0 + e) * TX + tx) * (2 * NA) + d4 * 4);
        sab[(e * 32 + tx) * SABST + 2 * d4]     = pack_bf16(v.x, v.y);
        sab[(e * 32 + tx) * SABST + 2 * d4 + 1] = pack_bf16(v.z, v.w);
    }
    __syncthreads();

    if (tid < DBE * TX) {
        int e = tid / TX, tx = tid % TX;
        float acc[10];
        #pragma unroll
        for (int j = 0; j < 10; j++) acc[j] = 0.0f;
        #pragma unroll 4
        for (int d2 = 0; d2 < 32; d2++) {
            unsigned av = sab[(e * 32 + tx) * SABST + d2];
            float f0 = __uint_as_float(av << 16);
            float f1 = __uint_as_float(av & 0xffff0000u);
            #pragma unroll
            for (int j = 0; j < 10; j++)
                acc[j] += f0 * W1a[j * 64 + 2 * d2] + f1 * W1a[j * 64 + 2 * d2 + 1];
        }
        #pragma unroll
        for (int j = 0; j < 10; j++) ea[(e * TX + tx) * EAST + j] = acc[j];
    }
    __syncthreads();

    for (int t = 0; t < TY; t++) {
        const unsigned* scr = scb + (t & 1) * (DBE * SCST);
        unsigned* scw = scb + ((t + 1) & 1) * (DBE * SCST);

        {
            const int e = warp;
            float accA = 0.0f;
            if (lane < 20) {
                int j = lane >> 1, half = lane & 1;
                const float4* sp = (const float4*)&ss[e * SSST + half * 32];
                const float4* wp = (const float4*)&W1s[j * W1ST + half * 32];
                #pragma unroll
                for (int q = 0; q < 8; q++) {
                    float4 sv = sp[q], wv = wp[q];
                    accA += sv.x * wv.x + sv.y * wv.y + sv.z * wv.z + sv.w * wv.w;
                }
            }
            accA += __shfl_xor_sync(FULL, accA, 1);
            if (lane < 20) accA += b1s[lane >> 1];

            int txc = (lane < TX) ? lane : 0;
            float acc = b2v;
            #pragma unroll
            for (int j = 0; j < 10; j++) {
                float esj = __shfl_sync(FULL, accA, 2 * j);
                acc += tanhapx(ea[(e * TX + txc) * EAST + j] + esj) * W2s[j];
            }
            // en = relu(acc) is bounded (~|b2|+10*max|W2|): exp cannot
            // overflow, so skip the max-subtraction entirely.
            float en = fmaxf(acc, 0.0f);
            float ex = (lane < TX) ? __expf(en) : 0.0f;
            float sum = ex;
            #pragma unroll
            for (int o = 16; o; o >>= 1) sum += __shfl_xor_sync(FULL, sum, o);
            alph[e * 32 + lane] = ex * __fdividef(1.0f, sum);
        }
        __syncwarp();

        {
            const int e = tid >> 5, d2 = tid & 31;
            const float4* ap = (const float4*)&alph[e * 32];
            float ctx0 = 0.0f, ctx1 = 0.0f;
            #pragma unroll
            for (int c = 0; c < 8; c++) {
                float4 a4 = ap[c];
                unsigned v0 = sab[(e * 32 + 4 * c + 0) * SABST + d2];
                unsigned v1 = sab[(e * 32 + 4 * c + 1) * SABST + d2];
                unsigned v2 = sab[(e * 32 + 4 * c + 2) * SABST + d2];
                unsigned v3 = sab[(e * 32 + 4 * c + 3) * SABST + d2];
                ctx0 += a4.x * __uint_as_float(v0 << 16)
                      + a4.y * __uint_as_float(v1 << 16)
                      + a4.z * __uint_as_float(v2 << 16)
                      + a4.w * __uint_as_float(v3 << 16);
                ctx1 += a4.x * __uint_as_float(v0 & 0xffff0000u)
                      + a4.y * __uint_as_float(v1 & 0xffff0000u)
                      + a4.z * __uint_as_float(v2 & 0xffff0000u)
                      + a4.w * __uint_as_float(v3 & 0xffff0000u);
            }
            int d0 = 2 * d2;
            int c0 = d0 >> 3, jj0 = d0 & 7;
            int p0 = (jj0 & 3) * 2 + (jj0 >> 2);
            int p1 = ((jj0 + 1) & 3) * 2 + ((jj0 + 1) >> 2);
            insp[e * INSPST + c0 * 8 + p0] = cvt_tf32(ctx0);
            insp[e * INSPST + c0 * 8 + p1] = cvt_tf32(ctx1);
        }
        __syncthreads();

        {
            float dd[2][4];
            #pragma unroll
            for (int nt = 0; nt < 2; nt++)
                #pragma unroll
                for (int r = 0; r < 4; r++) dd[nt][r] = 0.0f;
            #pragma unroll
            for (int c = 0; c < 8; c++) {
                uint2 va = *(uint2*)&insp[g * INSPST + c * 8 + 2 * tg];
                uint2 vb = *(uint2*)&insp[(g + 8) * INSPST + c * 8 + 2 * tg];
                unsigned a[4] = {va.x, vb.x, va.y, vb.y};
                mma_tf32(dd[0], a, Bw[(0 * 16 + c) * 2], Bw[(0 * 16 + c) * 2 + 1]);
                mma_tf32(dd[1], a, Bw[(1 * 16 + c) * 2], Bw[(1 * 16 + c) * 2 + 1]);
            }
            #pragma unroll
            for (int c = 0; c < 8; c++) {
                uint2 va = *(uint2*)&scr[g * SCST + c * 8 + 2 * tg];
                uint2 vb = *(uint2*)&scr[(g + 8) * SCST + c * 8 + 2 * tg];
                unsigned a[4] = {va.x, vb.x, va.y, vb.y};
                mma_tf32(dd[0], a, Bw[(0 * 16 + 8 + c) * 2], Bw[(0 * 16 + 8 + c) * 2 + 1]);
                mma_tf32(dd[1], a, Bw[(1 * 16 + 8 + c) * 2], Bw[(1 * 16 + 8 + c) * 2 + 1]);
            }
            float hh[2];
            #pragma unroll
            for (int nt = 0; nt < 2; nt++) {
                dd[nt][0] += bcol[nt][0]; dd[nt][1] += bcol[nt][1];
                dd[nt][2] += bcol[nt][0]; dd[nt][3] += bcol[nt][1];
                float ex0 = __shfl_xor_sync(FULL, dd[nt][0], 1);
                float ex1 = __shfl_xor_sync(FULL, dd[nt][1], 1);
                float ex2 = __shfl_xor_sync(FULL, dd[nt][2], 1);
                float ex3 = __shfl_xor_sync(FULL, dd[nt][3], 1);
                bool odd = (tg & 1);
                float zi = odd ? ex2        : dd[nt][0];
                float zf = odd ? ex3        : dd[nt][1];
                float zg = odd ? dd[nt][2]  : ex0;
                float zo = odd ? dd[nt][3]  : ex1;
                float c = sigapx(zf) * ccr[nt] + sigapx(zi) * tanhapx(zg);
                float h = sigapx(zo) * tanhapx(c);
                ccr[nt] = c;
                hh[nt] = h;
            }
            float r0 = __shfl_xor_sync(FULL, hh[0], 2);
            float r1 = __shfl_xor_sync(FULL, hh[1], 2);
            if (tg < 2) {
                int e = g + 8 * (tg & 1);
                *(float4*)&ss[e * SSST + warp * 4] = make_float4(hh[0], r0, hh[1], r1);
                unsigned* sc = &scw[e * SCST + (warp >> 1) * 8 + (warp & 1)];
                sc[0] = cvt_tf32(hh[0]);
                sc[2] = cvt_tf32(r0);
                sc[4] = cvt_tf32(hh[1]);
                sc[6] = cvt_tf32(r1);
            }
        }
        __syncthreads();

        if (warp < 8) {
            float dd[4] = {0.0f, 0.0f, 0.0f, 0.0f};
            #pragma unroll
            for (int c = 0; c < 8; c++) {
                uint2 va = *(uint2*)&scw[g * SCST + c * 8 + 2 * tg];
                uint2 vb = *(uint2*)&scw[(g + 8) * SCST + c * 8 + 2 * tg];
                unsigned a[4] = {va.x, vb.x, va.y, vb.y};
                mma_tf32(dd, a, Bo[c * 2], Bo[c * 2 + 1]);
            }
            *(float2*)(out + ((size_t)(b0 + g) * TY + t) * MV + m0)
                = make_float2(dd[0] + bo0, dd[1] + bo1);
            *(float2*)(out + ((size_t)(b0 + g + 8) * TY + t) * MV + m0)
                = make_float2(dd[2] + bo0, dd[3] + bo1);
        }
    }
}

// ============================================================================
extern "C" void kernel_launch(void* const* d_in, const int* in_sizes, int n_in,
                              void* d_out, int out_size)
{
    const float* X      = (const float*)d_in[0];
    const float* W_ih_f = (const float*)d_in[1];
    const float* W_hh_f = (const float*)d_in[2];
    const float* b_f    = (const float*)d_in[3];
    const float* W_ih_r = (const float*)d_in[4];
    const float* W_hh_r = (const float*)d_in[5];
    const float* b_r    = (const float*)d_in[6];
    const float* W1     = (const float*)d_in[7];
    const float* b1     = (const float*)d_in[8];
    const float* W2     = (const float*)d_in[9];
    const float* b2     = (const float*)d_in[10];
    const float* W_ih_p = (const float*)d_in[11];
    const float* W_hh_p = (const float*)d_in[12];
    const float* b_p    = (const float*)d_in[13];
    const float* Wo     = (const float*)d_in[14];
    const float* bo     = (const float*)d_in[15];
    float* out = (float*)d_out;

    cudaFuncSetAttribute(encoder_fused,  cudaFuncAttributeMaxDynamicSharedMemorySize, ENC_SMEM_BYTES);
    cudaFuncSetAttribute(decoder_kernel, cudaFuncAttributeMaxDynamicSharedMemorySize, DEC_SMEM_BYTES);

    clear_flags_kernel<<<1, 256>>>();

    encoder_fused<<<B_TOT / EBE, ENC_THREADS, ENC_SMEM_BYTES>>>(
        X, W_ih_f, W_hh_f, b_f, W_ih_r, W_hh_r, b_r);

    // decoder: PDL secondary — may launch while encoder drains; per-chunk
    // flags gate the g_a reads.
    cudaLaunchConfig_t cfg = {};
    cfg.gridDim = dim3(B_TOT / DBE, 1, 1);
    cfg.blockDim = dim3(DEC_THREADS, 1, 1);
    cfg.dynamicSmemBytes = DEC_SMEM_BYTES;
    cfg.stream = 0;
    cudaLaunchAttribute attr[1];
    attr[0].id = cudaLaunchAttributeProgrammaticStreamSerialization;
    attr[0].val.programmaticStreamSerializationAllowed = 1;
    cfg.attrs = attr;
    cfg.numAttrs = 1;
    cudaLaunchKernelEx(&cfg, decoder_kernel, W1, b1, W2, b2,
                       W_ih_p, W_hh_p, b_p, Wo, bo, out);
}

// round 15
// speedup vs baseline: 4.6915x; 1.0034x over previous
#include <cuda_runtime.h>
#include <cuda_bf16.h>
#include <math.h>

#define B_TOT 16384
#define TX 30
#define TY 10
#define NA 32
#define NS 64
#define HV 128
#define MV 64
#define GE 128   // 4*NA
#define GP 256   // 4*NS

__device__ __align__(16) float g_a[(size_t)B_TOT * TX * (2 * NA)];   // 126 MB
__device__ int g_flag[256];

__device__ __forceinline__ float tanhapx(float x) {
    float y;
    asm("tanh.approx.f32 %0, %1;" : "=f"(y) : "f"(x));
    return y;
}
__device__ __forceinline__ float sigapx(float x) {
    return fmaf(tanhapx(0.5f * x), 0.5f, 0.5f);
}
__device__ __forceinline__ unsigned cvt_tf32(float x) {
    unsigned u;
    asm("cvt.rna.tf32.f32 %0, %1;" : "=r"(u) : "f"(x));
    return u;
}
__device__ __forceinline__ unsigned pack_bf16(float a, float b) {
    __nv_bfloat162 h = __floats2bfloat162_rn(a, b);
    return *(unsigned*)&h;
}
__device__ __forceinline__ void mma_tf32(float* d, const unsigned* a, unsigned b0, unsigned b1) {
    asm("mma.sync.aligned.m16n8k8.row.col.f32.tf32.tf32.f32 "
        "{%0,%1,%2,%3}, {%4,%5,%6,%7}, {%8,%9}, {%0,%1,%2,%3};"
        : "+f"(d[0]), "+f"(d[1]), "+f"(d[2]), "+f"(d[3])
        : "r"(a[0]), "r"(a[1]), "r"(a[2]), "r"(a[3]), "r"(b0), "r"(b1));
}
__device__ __forceinline__ void mma_bf16(float* d, unsigned a0, unsigned a1,
                                         unsigned a2, unsigned a3,
                                         unsigned b0, unsigned b1) {
    asm("mma.sync.aligned.m16n8k16.row.col.f32.bf16.bf16.f32 "
        "{%0,%1,%2,%3}, {%4,%5,%6,%7}, {%8,%9}, {%0,%1,%2,%3};"
        : "+f"(d[0]), "+f"(d[1]), "+f"(d[2]), "+f"(d[3])
        : "r"(a0), "r"(a1), "r"(a2), "r"(a3), "r"(b0), "r"(b1));
}

__global__ void clear_flags_kernel() { g_flag[threadIdx.x] = 0; }

// ============================================================================
// Encoder v3 + PDL trigger + completion flags (identical to R14)
// ============================================================================
#define EBE 64
#define ENC_THREADS 512
#define XST 68
#define HST 20
#define ENC_SMEM_BYTES ((2*2*64*XST + 2*2*64*HST) * 4)

#define BARD(d) asm volatile("bar.sync %0, %1;" :: "r"(1 + (d)), "r"(256) : "memory")

__global__ __launch_bounds__(ENC_THREADS, 1)
void encoder_fused(const float* __restrict__ X,
                   const float* __restrict__ W_ih_f, const float* __restrict__ W_hh_f,
                   const float* __restrict__ b_f,
                   const float* __restrict__ W_ih_r, const float* __restrict__ W_hh_r,
                   const float* __restrict__ b_r)
{
    cudaTriggerProgrammaticLaunchCompletion();

    const int b0  = blockIdx.x * EBE;
    const int tid = threadIdx.x;
    const int warp = tid >> 5, lane = tid & 31;
    const int g = lane >> 2, tg = lane & 3;
    const int dir = warp >> 3;
    const int wl  = warp & 7;
    const int wtid = tid & 255;

    extern __shared__ unsigned smu[];
    unsigned* xs  = smu;
    unsigned* hbf = xs + 2 * 2 * 64 * XST;

    const float* Wi = dir ? W_ih_r : W_ih_f;
    const float* Wh = dir ? W_hh_r : W_hh_f;
    const float* bb = dir ? b_r    : b_f;

    unsigned Bx[2][8][2], Bh[2][2][2];
    #pragma unroll
    for (int nt = 0; nt < 2; nt++) {
        int q  = wl * 16 + nt * 8 + g;
        int rr = (q & 3) * NA + (q >> 2);
        #pragma unroll
        for (int c = 0; c < 8; c++) {
            Bx[nt][c][0] = pack_bf16(Wi[rr * 128 + c * 16 + 2 * tg],
                                     Wi[rr * 128 + c * 16 + 2 * tg + 1]);
            Bx[nt][c][1] = pack_bf16(Wi[rr * 128 + c * 16 + 8 + 2 * tg],
                                     Wi[rr * 128 + c * 16 + 8 + 2 * tg + 1]);
        }
        #pragma unroll
        for (int c = 0; c < 2; c++) {
            Bh[nt][c][0] = pack_bf16(Wh[rr * 32 + c * 16 + 2 * tg],
                                     Wh[rr * 32 + c * 16 + 2 * tg + 1]);
            Bh[nt][c][1] = pack_bf16(Wh[rr * 32 + c * 16 + 8 + 2 * tg],
                                     Wh[rr * 32 + c * 16 + 8 + 2 * tg + 1]);
        }
    }
    float bcol[2][2];
    #pragma unroll
    for (int nt = 0; nt < 2; nt++) {
        int q0 = wl * 16 + nt * 8 + 2 * tg;
        bcol[nt][0] = bb[(q0 & 3) * NA + (q0 >> 2)];
        bcol[nt][1] = bb[((q0 + 1) & 3) * NA + ((q0 + 1) >> 2)];
    }
    float ccr[8];
    #pragma unroll
    for (int i = 0; i < 8; i++) ccr[i] = 0.0f;

    for (int i = tid; i < 2 * 2 * 64 * HST; i += ENC_THREADS) hbf[i] = 0u;
    #pragma unroll
    for (int ii = 0; ii < 8; ii++) {
        int flat = tid + ii * ENC_THREADS;
        int dd = flat >> 11, r = flat & 2047;
        int row = r >> 5, q = r & 31;
        int ts = dd ? (TX - 1) : 0;
        float4 v = *(const float4*)(X + ((size_t)(b0 + row) * TX + ts) * HV + q * 4);
        int c = q >> 2, jj0 = (q & 3) * 2;
        int p0 = (jj0 & 3) * 2 + (jj0 >> 2);
        int p1 = ((jj0 + 1) & 3) * 2 + ((jj0 + 1) >> 2);
        unsigned* dst = &xs[((0 * 2 + dd) * 64 + row) * XST + c * 8];
        dst[p0] = pack_bf16(v.x, v.y);
        dst[p1] = pack_bf16(v.z, v.w);
    }
    __syncthreads();

    const int hc  = wl >> 2;
    const int hjj = (wl & 3) * 2;
    const int hp0 = (hjj & 3) * 2 + (hjj >> 2);
    const int hp1 = ((hjj + 1) & 3) * 2 + ((hjj + 1) >> 2);

    int buf = 0;
    for (int t = 0; t < TX; t++) {
        const int par = t & 1;
        const int tt  = dir ? (TX - 1 - t) : t;

        float4 xpre[8];
        const int tsn = dir ? max(TX - 2 - t, 0) : min(t + 1, TX - 1);
        #pragma unroll
        for (int ii = 0; ii < 8; ii++) {
            int flat = wtid + ii * 256;
            int row = flat >> 5, q = flat & 31;
            xpre[ii] = *(const float4*)(X + ((size_t)(b0 + row) * TX + tsn) * HV + q * 4);
        }

        #pragma unroll
        for (int half = 0; half < 2; half++) {
            float d[2][2][4];
            #pragma unroll
            for (int mi = 0; mi < 2; mi++)
                #pragma unroll
                for (int nt = 0; nt < 2; nt++)
                    #pragma unroll
                    for (int r = 0; r < 4; r++) d[mi][nt][r] = 0.0f;

            const unsigned* xbase = &xs[((buf * 2 + dir) * 64 + half * 32) * XST];
            #pragma unroll
            for (int c = 0; c < 8; c++) {
                unsigned a[2][4];
                #pragma unroll
                for (int mi = 0; mi < 2; mi++) {
                    uint2 lo = *(uint2*)&xbase[(mi * 16 + g) * XST + c * 8 + 2 * tg];
                    uint2 hi = *(uint2*)&xbase[(mi * 16 + 8 + g) * XST + c * 8 + 2 * tg];
                    a[mi][0] = lo.x; a[mi][1] = hi.x; a[mi][2] = lo.y; a[mi][3] = hi.y;
                }
                #pragma unroll
                for (int mi = 0; mi < 2; mi++) {
                    mma_bf16(d[mi][0], a[mi][0], a[mi][1], a[mi][2], a[mi][3],
                             Bx[0][c][0], Bx[0][c][1]);
                    mma_bf16(d[mi][1], a[mi][0], a[mi][1], a[mi][2], a[mi][3],
                             Bx[1][c][0], Bx[1][c][1]);
                }
            }
            const unsigned* hbase = &hbf[((par * 2 + dir) * 64 + half * 32) * HST];
            #pragma unroll
            for (int c = 0; c < 2; c++) {
                unsigned a[2][4];
                #pragma unroll
                for (int mi = 0; mi < 2; mi++) {
                    uint2 lo = *(uint2*)&hbase[(mi * 16 + g) * HST + c * 8 + 2 * tg];
                    uint2 hi = *(uint2*)&hbase[(mi * 16 + 8 + g) * HST + c * 8 + 2 * tg];
                    a[mi][0] = lo.x; a[mi][1] = hi.x; a[mi][2] = lo.y; a[mi][3] = hi.y;
                }
                #pragma unroll
                for (int mi = 0; mi < 2; mi++) {
                    mma_bf16(d[mi][0], a[mi][0], a[mi][1], a[mi][2], a[mi][3],
                             Bh[0][c][0], Bh[0][c][1]);
                    mma_bf16(d[mi][1], a[mi][0], a[mi][1], a[mi][2], a[mi][3],
                             Bh[1][c][0], Bh[1][c][1]);
                }
            }

            #pragma unroll
            for (int mi = 0; mi < 2; mi++) {
                float hh[2];
                #pragma unroll
                for (int nt = 0; nt < 2; nt++) {
                    d[mi][nt][0] += bcol[nt][0]; d[mi][nt][1] += bcol[nt][1];
                    d[mi][nt][2] += bcol[nt][0]; d[mi][nt][3] += bcol[nt][1];
                    float ex0 = __shfl_xor_sync(0xffffffffu, d[mi][nt][0], 1);
                    float ex1 = __shfl_xor_sync(0xffffffffu, d[mi][nt][1], 1);
                    float ex2 = __shfl_xor_sync(0xffffffffu, d[mi][nt][2], 1);
                    float ex3 = __shfl_xor_sync(0xffffffffu, d[mi][nt][3], 1);
                    bool odd = (tg & 1);
                    float zi = odd ? ex2       : d[mi][nt][0];
                    float zf = odd ? ex3       : d[mi][nt][1];
                    float zg = odd ? d[mi][nt][2] : ex0;
                    float zo = odd ? d[mi][nt][3] : ex1;
                    int ci = half * 4 + mi * 2 + nt;
                    float c = sigapx(zf) * ccr[ci] + sigapx(zi) * tanhapx(zg);
                    float h = sigapx(zo) * tanhapx(c);
                    ccr[ci] = c;
                    hh[nt] = h;
                }
                float r0 = __shfl_xor_sync(0xffffffffu, hh[0], 2);
                float r1 = __shfl_xor_sync(0xffffffffu, hh[1], 2);
                if (tg < 2) {
                    int row = half * 32 + mi * 16 + g + 8 * (tg & 1);
                    *(float4*)(g_a + ((size_t)(b0 + row) * TX + tt) * 64 + dir * 32 + wl * 4)
                        = make_float4(hh[0], r0, hh[1], r1);
                    unsigned* hd = &hbf[(((par ^ 1) * 2 + dir) * 64 + row) * HST + hc * 8];
                    hd[hp0] = pack_bf16(hh[0], r0);
                    hd[hp1] = pack_bf16(hh[1], r1);
                }
            }
        }

        #pragma unroll
        for (int ii = 0; ii < 8; ii++) {
            int flat = wtid + ii * 256;
            int row = flat >> 5, q = flat & 31;
            int c = q >> 2, jj0 = (q & 3) * 2;
            int p0 = (jj0 & 3) * 2 + (jj0 >> 2);
            int p1 = ((jj0 + 1) & 3) * 2 + ((jj0 + 1) >> 2);
            unsigned* dst = &xs[(((buf ^ 1) * 2 + dir) * 64 + row) * XST + c * 8];
            dst[p0] = pack_bf16(xpre[ii].x, xpre[ii].y);
            dst[p1] = pack_bf16(xpre[ii].z, xpre[ii].w);
        }

        BARD(dir);
        buf ^= 1;
    }

    __syncthreads();
    if (tid == 0) {
        __threadfence();
        asm volatile("st.release.gpu.global.s32 [%0], %1;"
                     :: "l"(&g_flag[blockIdx.x]), "r"(1) : "memory");
    }
}

// ============================================================================
// Decoder v10: R14 + latency-chain restructuring:
//  A: 2-way split dot; B: batched shfl/load/tanh then split reduction;
//  D: 4-way split ctx accumulators.
// ============================================================================
#define DBE 16
#define DEC_THREADS 512
#define SABST 34
#define EAST 11
#define W1ST 68
#define SSST 68
#define INSPST 72
#define SCST 72

#define OFF_SAB   0
#define SZ_SAB    (DBE * 32 * SABST)
#define OFF_EA    (OFF_SAB + SZ_SAB)
#define SZ_EA_AL  5284
#define OFF_W1A   (OFF_EA + SZ_EA_AL)
#define OFF_W1S   (OFF_W1A + 640)
#define OFF_B1S   (OFF_W1S + 680)
#define OFF_W2S   (OFF_B1S + 16)
#define OFF_SS    (OFF_W2S + 16)
#define OFF_INSP  (OFF_SS + DBE * SSST)
#define OFF_SC    (OFF_INSP + DBE * INSPST)
#define OFF_ALPH  (OFF_SC + 2 * DBE * SCST)
#define DEC_UNITS (OFF_ALPH + DBE * 32)
#define DEC_SMEM_BYTES (DEC_UNITS * 4)

__global__ __launch_bounds__(DEC_THREADS, 1)
void decoder_kernel(const float* __restrict__ W1, const float* __restrict__ b1,
                    const float* __restrict__ W2, const float* __restrict__ b2,
                    const float* __restrict__ W_ih_p, const float* __restrict__ W_hh_p,
                    const float* __restrict__ b_p,
                    const float* __restrict__ Wo, const float* __restrict__ bo,
                    float* __restrict__ out)
{
    const int b0 = blockIdx.x * DBE;
    const int tid = threadIdx.x;
    const unsigned FULL = 0xffffffffu;

    extern __shared__ unsigned smw[];
    unsigned* sab = smw + OFF_SAB;
    float* ea   = (float*)(smw + OFF_EA);
    float* W1a  = (float*)(smw + OFF_W1A);
    float* W1s  = (float*)(smw + OFF_W1S);
    float* b1s  = (float*)(smw + OFF_B1S);
    float* W2s  = (float*)(smw + OFF_W2S);
    float* ss   = (float*)(smw + OFF_SS);
    unsigned* insp = smw + OFF_INSP;
    unsigned* scb  = smw + OFF_SC;
    float* alph = (float*)(smw + OFF_ALPH);

    const int warp = tid >> 5, lane = tid & 31;
    const int g = lane >> 2, tg = lane & 3;

    unsigned Bw[64];
    #pragma unroll
    for (int nt = 0; nt < 2; nt++) {
        int q  = warp * 16 + nt * 8 + g;
        int rr = (q & 3) * 64 + (q >> 2);
        #pragma unroll
        for (int c = 0; c < 8; c++) {
            Bw[(nt * 16 + c) * 2 + 0] = cvt_tf32(W_ih_p[rr * 64 + c * 8 + tg]);
            Bw[(nt * 16 + c) * 2 + 1] = cvt_tf32(W_ih_p[rr * 64 + c * 8 + tg + 4]);
        }
        #pragma unroll
        for (int c = 0; c < 8; c++) {
            Bw[(nt * 16 + (8 + c)) * 2 + 0] = cvt_tf32(W_hh_p[rr * 64 + c * 8 + tg]);
            Bw[(nt * 16 + (8 + c)) * 2 + 1] = cvt_tf32(W_hh_p[rr * 64 + c * 8 + tg + 4]);
        }
    }
    float bcol[2][2];
    #pragma unroll
    for (int nt = 0; nt < 2; nt++) {
        int q0 = warp * 16 + nt * 8 + 2 * tg;
        bcol[nt][0] = b_p[(q0 & 3) * 64 + (q0 >> 2)];
        bcol[nt][1] = b_p[((q0 + 1) & 3) * 64 + ((q0 + 1) >> 2)];
    }
    float ccr[2] = {0.0f, 0.0f};

    unsigned Bo[16];
    {
        int n = (warp & 7) * 8 + g;
        #pragma unroll
        for (int c = 0; c < 8; c++) {
            Bo[c * 2 + 0] = cvt_tf32(Wo[n * 64 + c * 8 + tg]);
            Bo[c * 2 + 1] = cvt_tf32(Wo[n * 64 + c * 8 + tg + 4]);
        }
    }
    const int m0 = (warp & 7) * 8 + 2 * tg;
    const float bo0 = bo[m0], bo1 = bo[m0 + 1];

    for (int i = tid; i < 640; i += DEC_THREADS) {
        int j = i / 64, d = i % 64;
        W1a[i]            = W1[j * 128 + d];
        W1s[j * W1ST + d] = W1[j * 128 + 64 + d];
    }
    if (tid < 10) { b1s[tid] = b1[tid]; W2s[tid] = W2[tid]; }
    for (int i = tid; i < DBE * SSST; i += DEC_THREADS) ss[i] = 0.0f;
    for (int i = tid; i < 2 * DBE * SCST; i += DEC_THREADS) scb[i] = 0u;
    const float b2v = b2[0];

    for (int i = tid; i < DBE * 2 * SABST; i += DEC_THREADS) {
        int e = i / (2 * SABST), r = i % (2 * SABST);
        sab[(e * 32 + 30) * SABST + r] = 0u;
    }

    if (tid == 0) {
        int v;
        do {
            asm volatile("ld.acquire.gpu.global.s32 %0, [%1];"
                         : "=r"(v) : "l"(&g_flag[blockIdx.x >> 2]) : "memory");
            if (!v) __nanosleep(128);
        } while (!v);
    }
    __syncthreads();

    for (int i = tid; i < DBE * TX * 16; i += DEC_THREADS) {
        int e = i / (TX * 16);
        int r = i % (TX * 16);
        int tx = r / 16, d4 = r % 16;
        float4 v = *(const float4*)(g_a + ((size_t)(b0 + e) * TX + tx) * (2 * NA) + d4 * 4);
        sab[(e * 32 + tx) * SABST + 2 * d4]     = pack_bf16(v.x, v.y);
        sab[(e * 32 + tx) * SABST + 2 * d4 + 1] = pack_bf16(v.z, v.w);
    }
    __syncthreads();

    if (tid < DBE * TX) {
        int e = tid / TX, tx = tid % TX;
        float acc[10];
        #pragma unroll
        for (int j = 0; j < 10; j++) acc[j] = 0.0f;
        #pragma unroll 4
        for (int d2 = 0; d2 < 32; d2++) {
            unsigned av = sab[(e * 32 + tx) * SABST + d2];
            float f0 = __uint_as_float(av << 16);
            float f1 = __uint_as_float(av & 0xffff0000u);
            #pragma unroll
            for (int j = 0; j < 10; j++)
                acc[j] += f0 * W1a[j * 64 + 2 * d2] + f1 * W1a[j * 64 + 2 * d2 + 1];
        }
        #pragma unroll
        for (int j = 0; j < 10; j++) ea[(e * TX + tx) * EAST + j] = acc[j];
    }
    __syncthreads();

    for (int t = 0; t < TY; t++) {
        const unsigned* scr = scb + (t & 1) * (DBE * SCST);
        unsigned* scw = scb + ((t + 1) & 1) * (DBE * SCST);

        // ---- A+B+C: warp e = attention (ILP-restructured) ----
        {
            const int e = warp;
            // A: 2-way split dot
            float accA = 0.0f;
            if (lane < 20) {
                int j = lane >> 1, half = lane & 1;
                const float4* sp = (const float4*)&ss[e * SSST + half * 32];
                const float4* wp = (const float4*)&W1s[j * W1ST + half * 32];
                float a0 = 0.0f, a1 = 0.0f;
                #pragma unroll
                for (int q = 0; q < 8; q += 2) {
                    float4 s0 = sp[q],     w0 = wp[q];
                    float4 s1 = sp[q + 1], w1 = wp[q + 1];
                    a0 += s0.x * w0.x + s0.y * w0.y + s0.z * w0.z + s0.w * w0.w;
                    a1 += s1.x * w1.x + s1.y * w1.y + s1.z * w1.z + s1.w * w1.w;
                }
                accA = a0 + a1;
            }
            accA += __shfl_xor_sync(FULL, accA, 1);
            if (lane < 20) accA += b1s[lane >> 1];

            // B: batch shfls + loads + tanhs, then split reduction
            int txc = (lane < TX) ? lane : 0;
            float esj[10], eav[10], th[10];
            #pragma unroll
            for (int j = 0; j < 10; j++) esj[j] = __shfl_sync(FULL, accA, 2 * j);
            #pragma unroll
            for (int j = 0; j < 10; j++) eav[j] = ea[(e * TX + txc) * EAST + j];
            #pragma unroll
            for (int j = 0; j < 10; j++) th[j] = tanhapx(eav[j] + esj[j]);
            float s0 = b2v, s1 = 0.0f;
            #pragma unroll
            for (int j = 0; j < 10; j += 2) {
                s0 += th[j]     * W2s[j];
                s1 += th[j + 1] * W2s[j + 1];
            }
            float en = fmaxf(s0 + s1, 0.0f);
            float ex = (lane < TX) ? __expf(en) : 0.0f;
            float sum = ex;
            #pragma unroll
            for (int o = 16; o; o >>= 1) sum += __shfl_xor_sync(FULL, sum, o);
            alph[e * 32 + lane] = ex * __fdividef(1.0f, sum);
        }
        __syncwarp();

        // ---- D: 4-way split ctx accumulators ----
        {
            const int e = tid >> 5, d2 = tid & 31;
            const float4* ap = (const float4*)&alph[e * 32];
            float c0a = 0.0f, c0b = 0.0f, c1a = 0.0f, c1b = 0.0f;
            #pragma unroll
            for (int c = 0; c < 4; c++) {          // tx rows 0..15
                float4 a4 = ap[c];
                unsigned v0 = sab[(e * 32 + 4 * c + 0) * SABST + d2];
                unsigned v1 = sab[(e * 32 + 4 * c + 1) * SABST + d2];
                unsigned v2 = sab[(e * 32 + 4 * c + 2) * SABST + d2];
                unsigned v3 = sab[(e * 32 + 4 * c + 3) * SABST + d2];
                c0a += a4.x * __uint_as_float(v0 << 16)
                     + a4.y * __uint_as_float(v1 << 16)
                     + a4.z * __uint_as_float(v2 << 16)
                     + a4.w * __uint_as_float(v3 << 16);
                c1a += a4.x * __uint_as_float(v0 & 0xffff0000u)
                     + a4.y * __uint_as_float(v1 & 0xffff0000u)
                     + a4.z * __uint_as_float(v2 & 0xffff0000u)
                     + a4.w * __uint_as_float(v3 & 0xffff0000u);
            }
            #pragma unroll
            for (int c = 4; c < 8; c++) {          // tx rows 16..31
                float4 a4 = ap[c];
                unsigned v0 = sab[(e * 32 + 4 * c + 0) * SABST + d2];
                unsigned v1 = sab[(e * 32 + 4 * c + 1) * SABST + d2];
                unsigned v2 = sab[(e * 32 + 4 * c + 2) * SABST + d2];
                unsigned v3 = sab[(e * 32 + 4 * c + 3) * SABST + d2];
                c0b += a4.x * __uint_as_float(v0 << 16)
                     + a4.y * __uint_as_float(v1 << 16)
                     + a4.z * __uint_as_float(v2 << 16)
                     + a4.w * __uint_as_float(v3 << 16);
                c1b += a4.x * __uint_as_float(v0 & 0xffff0000u)
                     + a4.y * __uint_as_float(v1 & 0xffff0000u)
                     + a4.z * __uint_as_float(v2 & 0xffff0000u)
                     + a4.w * __uint_as_float(v3 & 0xffff0000u);
            }
            float ctx0 = c0a + c0b, ctx1 = c1a + c1b;
            int d0 = 2 * d2;
            int c0 = d0 >> 3, jj0 = d0 & 7;
            int p0 = (jj0 & 3) * 2 + (jj0 >> 2);
            int p1 = ((jj0 + 1) & 3) * 2 + ((jj0 + 1) >> 2);
            insp[e * INSPST + c0 * 8 + p0] = cvt_tf32(ctx0);
            insp[e * INSPST + c0 * 8 + p1] = cvt_tf32(ctx1);
        }
        __syncthreads();

        // ---- E+F fused: gate mma + in-register cell ----
        {
            float dd[2][4];
            #pragma unroll
            for (int nt = 0; nt < 2; nt++)
                #pragma unroll
                for (int r = 0; r < 4; r++) dd[nt][r] = 0.0f;
            #pragma unroll
            for (int c = 0; c < 8; c++) {
                uint2 va = *(uint2*)&insp[g * INSPST + c * 8 + 2 * tg];
                uint2 vb = *(uint2*)&insp[(g + 8) * INSPST + c * 8 + 2 * tg];
                unsigned a[4] = {va.x, vb.x, va.y, vb.y};
                mma_tf32(dd[0], a, Bw[(0 * 16 + c) * 2], Bw[(0 * 16 + c) * 2 + 1]);
                mma_tf32(dd[1], a, Bw[(1 * 16 + c) * 2], Bw[(1 * 16 + c) * 2 + 1]);
            }
            #pragma unroll
            for (int c = 0; c < 8; c++) {
                uint2 va = *(uint2*)&scr[g * SCST + c * 8 + 2 * tg];
                uint2 vb = *(uint2*)&scr[(g + 8) * SCST + c * 8 + 2 * tg];
                unsigned a[4] = {va.x, vb.x, va.y, vb.y};
                mma_tf32(dd[0], a, Bw[(0 * 16 + 8 + c) * 2], Bw[(0 * 16 + 8 + c) * 2 + 1]);
                mma_tf32(dd[1], a, Bw[(1 * 16 + 8 + c) * 2], Bw[(1 * 16 + 8 + c) * 2 + 1]);
            }
            float hh[2];
            #pragma unroll
            for (int nt = 0; nt < 2; nt++) {
                dd[nt][0] += bcol[nt][0]; dd[nt][1] += bcol[nt][1];
                dd[nt][2] += bcol[nt][0]; dd[nt][3] += bcol[nt][1];
                float ex0 = __shfl_xor_sync(FULL, dd[nt][0], 1);
                float ex1 = __shfl_xor_sync(FULL, dd[nt][1], 1);
                float ex2 = __shfl_xor_sync(FULL, dd[nt][2], 1);
                float ex3 = __shfl_xor_sync(FULL, dd[nt][3], 1);
                bool odd = (tg & 1);
                float zi = odd ? ex2        : dd[nt][0];
                float zf = odd ? ex3        : dd[nt][1];
                float zg = odd ? dd[nt][2]  : ex0;
                float zo = odd ? dd[nt][3]  : ex1;
                float c = sigapx(zf) * ccr[nt] + sigapx(zi) * tanhapx(zg);
                float h = sigapx(zo) * tanhapx(c);
                ccr[nt] = c;
                hh[nt] = h;
            }
            float r0 = __shfl_xor_sync(FULL, hh[0], 2);
            float r1 = __shfl_xor_sync(FULL, hh[1], 2);
            if (tg < 2) {
                int e = g + 8 * (tg & 1);
                *(float4*)&ss[e * SSST + warp * 4] = make_float4(hh[0], r0, hh[1], r1);
                unsigned* sc = &scw[e * SCST + (warp >> 1) * 8 + (warp & 1)];
                sc[0] = cvt_tf32(hh[0]);
                sc[2] = cvt_tf32(r0);
                sc[4] = cvt_tf32(hh[1]);
                sc[6] = cvt_tf32(r1);
            }
        }
        __syncthreads();

        // ---- OUT: warps 0-7 via tf32 mma ----
        if (warp < 8) {
            float dd[4] = {0.0f, 0.0f, 0.0f, 0.0f};
            #pragma unroll
            for (int c = 0; c < 8; c++) {
                uint2 va = *(uint2*)&scw[g * SCST + c * 8 + 2 * tg];
                uint2 vb = *(uint2*)&scw[(g + 8) * SCST + c * 8 + 2 * tg];
                unsigned a[4] = {va.x, vb.x, va.y, vb.y};
                mma_tf32(dd, a, Bo[c * 2], Bo[c * 2 + 1]);
            }
            *(float2*)(out + ((size_t)(b0 + g) * TY + t) * MV + m0)
                = make_float2(dd[0] + bo0, dd[1] + bo1);
            *(float2*)(out + ((size_t)(b0 + g + 8) * TY + t) * MV + m0)
                = make_float2(dd[2] + bo0, dd[3] + bo1);
        }
    }
}

// ============================================================================
extern "C" void kernel_launch(void* const* d_in, const int* in_sizes, int n_in,
                              void* d_out, int out_size)
{
    const float* X      = (const float*)d_in[0];
    const float* W_ih_f = (const float*)d_in[1];
    const float* W_hh_f = (const float*)d_in[2];
    const float* b_f    = (const float*)d_in[3];
    const float* W_ih_r = (const float*)d_in[4];
    const float* W_hh_r = (const float*)d_in[5];
    const float* b_r    = (const float*)d_in[6];
    const float* W1     = (const float*)d_in[7];
    const float* b1     = (const float*)d_in[8];
    const float* W2     = (const float*)d_in[9];
    const float* b2     = (const float*)d_in[10];
    const float* W_ih_p = (const float*)d_in[11];
    const float* W_hh_p = (const float*)d_in[12];
    const float* b_p    = (const float*)d_in[13];
    const float* Wo     = (const float*)d_in[14];
    const float* bo     = (const float*)d_in[15];
    float* out = (float*)d_out;

    cudaFuncSetAttribute(encoder_fused,  cudaFuncAttributeMaxDynamicSharedMemorySize, ENC_SMEM_BYTES);
    cudaFuncSetAttribute(decoder_kernel, cudaFuncAttributeMaxDynamicSharedMemorySize, DEC_SMEM_BYTES);

    clear_flags_kernel<<<1, 256>>>();

    encoder_fused<<<B_TOT / EBE, ENC_THREADS, ENC_SMEM_BYTES>>>(
        X, W_ih_f, W_hh_f, b_f, W_ih_r, W_hh_r, b_r);

    cudaLaunchConfig_t cfg = {};
    cfg.gridDim = dim3(B_TOT / DBE, 1, 1);
    cfg.blockDim = dim3(DEC_THREADS, 1, 1);
    cfg.dynamicSmemBytes = DEC_SMEM_BYTES;
    cfg.stream = 0;
    cudaLaunchAttribute attr[1];
    attr[0].id = cudaLaunchAttributeProgrammaticStreamSerialization;
    attr[0].val.programmaticStreamSerializationAllowed = 1;
    cfg.attrs = attr;
    cfg.numAttrs = 1;
    cudaLaunchKernelEx(&cfg, decoder_kernel, W1, b1, W2, b2,
                       W_ih_p, W_hh_p, b_p, Wo, bo, out);
}